// round 1
// baseline (speedup 1.0000x reference)
#include <cuda_runtime.h>
#include <math.h>

// ---------------- fixed problem constants (setup_inputs is deterministic) ---
#define BB 2
#define CC 64
#define TT 16
#define HH 36
#define WW 36
#define THW (TT*HH*WW)        // 20736
#define PS 8
#define NT 3
#define NH 6
#define NW 6
#define NPB (NT*NH*NW)        // 108
#define NP (BB*NPB)           // 216
#define TOKN 512
#define NROW (NP*TOKN)        // 110592
#define HEADS 2
#define HID 128
#define NTOK2 (BB*THW)        // 41472

__constant__ int   c_st_t[3] = {0,6,8};
__constant__ int   c_st_h[6] = {0,6,12,18,24,28};
// exact replication of _divisor (NOT coverage count): inverse divisors
__constant__ float c_idt[16] = {1,1,1,1,1,1,0.5f,0.5f,0.5f,0.5f,1,1,1,1,1,1};
__constant__ float c_idh[36] = {1,1,1,1,1,1, 0.5f,0.5f, 1,1,1,1, 0.5f,0.5f,
                                1,1,1,1, 0.5f,0.5f, 1,1,1,1, 0.5f,0.5f,
                                1,1, 0.5f,0.5f, 1,1,1,1,1,1};

// ---------------- scratch (device globals; no runtime allocation) -----------
__device__ float g_tokens[NROW*64];   // extracted patches (residual)
__device__ float g_y[NROW*64];        // LN1 output; later reused as tok2 (post-proj+residual)
__device__ float g_q[NROW*32];
__device__ float g_kbuf[NROW*32];
__device__ float g_v[NROW*64];
__device__ float g_attn[NROW*64];
__device__ float g_xtok[NTOK2*64];    // pre-LN2 token-major (residual for fc2)
__device__ float g_y2[NTOK2*128];     // post fc1+gelu, token-major
__device__ float g_y2cm[BB*HID*THW];  // same, channel-major (conv input)
__device__ float g_dwcm[BB*HID*THW];  // conv+gelu out, channel-major

__device__ __forceinline__ float wred(float v){
  #pragma unroll
  for(int o=16;o;o>>=1) v += __shfl_xor_sync(0xffffffffu, v, o);
  return v;
}
__device__ __forceinline__ float wmaxr(float v){
  #pragma unroll
  for(int o=16;o;o>>=1) v = fmaxf(v, __shfl_xor_sync(0xffffffffu, v, o));
  return v;
}
__device__ __forceinline__ float gelu_exact(float x){
  return 0.5f*x*(1.0f + erff(x*0.70710678118654752f));
}

// ---------------- K1: patch extract + LN1 ----------------------------------
// 4 tokens per 256-thread block; 64 threads (1 channel each) per token.
__global__ void k_extract_ln(const float* __restrict__ x,
                             const float* __restrict__ g1,
                             const float* __restrict__ b1){
  int tid = threadIdx.x, grp = tid>>6, ch = tid&63;
  int row = blockIdx.x*4 + grp;           // [0, NROW)
  int p = row>>9, tok = row&511;
  int bi = p/NPB, r = p%NPB;
  int pt = r/36, ph = (r%36)/6, pw = r%6;
  int tt = tok>>6, hh = (tok>>3)&7, ww = tok&7;
  int ta = c_st_t[pt]+tt, ha = c_st_h[ph]+hh, wa = c_st_h[pw]+ww;
  float v = x[((bi*CC+ch)*TT+ta)*(HH*WW) + ha*WW + wa];

  float s = wred(v), s2 = wred(v*v);
  __shared__ float sm[8][2];
  int wid = tid>>5;
  if((tid&31)==0){ sm[wid][0]=s; sm[wid][1]=s2; }
  __syncthreads();
  float su = sm[grp*2][0]+sm[grp*2+1][0];
  float sq = sm[grp*2][1]+sm[grp*2+1][1];
  float m = su*(1.0f/64.0f);
  float var = sq*(1.0f/64.0f) - m*m;
  float rs = rsqrtf(var + 1e-5f);
  g_tokens[row*64+ch] = v;
  g_y[row*64+ch] = (v-m)*rs*g1[ch] + b1[ch];
}

// ---------------- K2: fused QKV GEMM (M=NROW, K=64, N=128) -----------------
__global__ void k_qkv(const float* __restrict__ wq,
                      const float* __restrict__ wk,
                      const float* __restrict__ wv){
  __shared__ float sy[16*64];
  __shared__ float sw[64*128];
  int tid = threadIdx.x;
  int base = blockIdx.x*16;
  for(int i=tid;i<8192;i+=128){
    int kk = i>>7, j = i&127;
    float wval;
    if(j<32)       wval = wq[kk*32+j];
    else if(j<64)  wval = wk[kk*32+(j-32)];
    else           wval = wv[kk*64+(j-64)];
    sw[i] = wval;
  }
  for(int i=tid;i<1024;i+=128) sy[i] = g_y[base*64 + i];
  __syncthreads();
  int j = tid;
  for(int t=0;t<16;t++){
    float a = 0.f;
    #pragma unroll 16
    for(int kk=0;kk<64;kk++) a += sy[t*64+kk]*sw[kk*128+j];
    int row = base + t;
    if(j<32)       g_q[row*32+j] = a;
    else if(j<64)  g_kbuf[row*32+(j-32)] = a;
    else           g_v[row*64+(j-64)] = a;
  }
}

// ---------------- K3: attention per (patch, head) ---------------------------
// block 256 (8 warps), one warp handles one query at a time (64 queries/warp).
// dyn smem: K[512][17] + V[512][32] + scores[8][512]
#define ATTN_SMEM ((512*17 + 512*32 + 8*512)*4)
extern __shared__ float sm3[];
__global__ void k_attn(){
  int p = blockIdx.x, hd = blockIdx.y;
  float* sK = sm3;                 // 512*17 (pad 17 to kill bank conflicts)
  float* sV = sK + 512*17;         // 512*32
  float* sS = sV + 512*32;         // 8*512
  int tid = threadIdx.x;

  for(int i=tid;i<512*16;i+=256){
    int j = i>>4, d = i&15;
    sK[j*17+d] = g_kbuf[(p*512+j)*32 + hd*16 + d];
  }
  for(int i=tid;i<512*32;i+=256){
    int j = i>>5, d = i&31;
    sV[j*32+d] = g_v[(p*512+j)*64 + hd*32 + d];
  }
  __syncthreads();

  int w = tid>>5, lane = tid&31;
  float* myS = sS + w*512;
  for(int q=w;q<512;q+=8){
    const float* qp = g_q + (p*512+q)*32 + hd*16;
    float qv[16];
    #pragma unroll
    for(int d=0;d<16;d++) qv[d] = qp[d];      // broadcast loads

    float mx = -1e30f; float sl[16];
    #pragma unroll
    for(int i=0;i<16;i++){
      int j = lane + 32*i;
      const float* kr = sK + j*17;
      float s = 0.f;
      #pragma unroll
      for(int d=0;d<16;d++) s += qv[d]*kr[d];
      s *= 0.25f;                 // 1/sqrt(16)
      sl[i] = s; mx = fmaxf(mx, s);
    }
    mx = wmaxr(mx);
    float ss = 0.f;
    #pragma unroll
    for(int i=0;i<16;i++){
      float e = __expf(sl[i]-mx);
      myS[lane+32*i] = e; ss += e;
    }
    ss = wred(ss);
    float inv = 1.0f/ss;
    __syncwarp();
    float o = 0.f;
    #pragma unroll 8
    for(int j=0;j<512;j++) o += myS[j]*sV[j*32+lane];
    g_attn[(p*512+q)*64 + hd*32 + lane] = o*inv;
    __syncwarp();
  }
}

// ---------------- K4: proj + residual --------------------------------------
__global__ void k_proj(const float* __restrict__ wproj){
  __shared__ float sA[256];
  int tid = threadIdx.x, grp = tid>>6, ch = tid&63;
  int row = blockIdx.x*4 + grp;
  sA[tid] = g_attn[blockIdx.x*256 + tid];
  __syncthreads();
  float a = g_tokens[row*64+ch];
  #pragma unroll 16
  for(int kk=0;kk<64;kk++) a += sA[grp*64+kk]*wproj[kk*64+ch];
  g_y[row*64+ch] = a;   // tok2 (reuse g_y)
}

// ---------------- K5: gather-reverse + div + LN2 + fc1 + gelu --------------
__global__ void k_mlp1(const float* __restrict__ g2, const float* __restrict__ b2,
                       const float* __restrict__ fc1w, const float* __restrict__ fc1b){
  int token = blockIdx.x;
  int bi = token/THW, pos = token%THW;
  int t = pos/(HH*WW), h = (pos/WW)%HH, w = pos%WW;
  int tid = threadIdx.x;   // 64

  int ctp[3], ctd[3], nct=0;
  #pragma unroll
  for(int pt=0;pt<NT;pt++){ int d=t-c_st_t[pt]; if(d>=0&&d<PS&&nct<3){ctp[nct]=pt;ctd[nct]=d;nct++;} }
  int chp[3], chd[3], nch=0;
  #pragma unroll
  for(int ph=0;ph<NH;ph++){ int d=h-c_st_h[ph]; if(d>=0&&d<PS&&nch<3){chp[nch]=ph;chd[nch]=d;nch++;} }
  int cwp[3], cwd[3], ncw=0;
  #pragma unroll
  for(int pw=0;pw<NW;pw++){ int d=w-c_st_h[pw]; if(d>=0&&d<PS&&ncw<3){cwp[ncw]=pw;cwd[ncw]=d;ncw++;} }

  float acc = 0.f;
  for(int a=0;a<nct;a++)
    for(int b_=0;b_<nch;b_++)
      for(int c_=0;c_<ncw;c_++){
        int p  = bi*NPB + ctp[a]*36 + chp[b_]*6 + cwp[c_];
        int tk = ctd[a]*64 + chd[b_]*8 + cwd[c_];
        acc += g_y[(p*512+tk)*64 + tid];
      }
  float xv = acc * c_idt[t]*c_idh[h]*c_idh[w];
  g_xtok[token*64+tid] = xv;

  float s = wred(xv), s2 = wred(xv*xv);
  __shared__ float sm[2][2];
  int wid = tid>>5;
  if((tid&31)==0){ sm[wid][0]=s; sm[wid][1]=s2; }
  __syncthreads();
  float su = sm[0][0]+sm[1][0], sq = sm[0][1]+sm[1][1];
  float m = su*(1.0f/64.0f);
  float var = sq*(1.0f/64.0f) - m*m;
  float rs = rsqrtf(var + 1e-5f);
  __shared__ float sY[64];
  sY[tid] = (xv-m)*rs*g2[tid] + b2[tid];
  __syncthreads();

  #pragma unroll
  for(int half=0;half<2;half++){
    int j = tid + half*64;
    float a1 = fc1b[j];
    #pragma unroll 16
    for(int kk=0;kk<64;kk++) a1 += sY[kk]*fc1w[kk*128+j];
    float gv = gelu_exact(a1);
    g_y2[token*128+j] = gv;
    g_y2cm[(bi*HID+j)*THW + pos] = gv;
  }
}

// ---------------- K6: depthwise 5^3 conv + bias + gelu (channel-major) -----
__global__ void k_dwconv(const float* __restrict__ dww, const float* __restrict__ dwb){
  __shared__ float si[20*10*10];
  __shared__ float swt[125];
  int blk = blockIdx.x;
  int tile = blk%36; int cb = blk/36; int ch = cb%HID; int bi = cb/HID;
  int th = tile/6, tw = tile%6;
  int tid = threadIdx.x;
  const float* src = g_y2cm + (bi*HID+ch)*THW;

  for(int i=tid;i<125;i+=128) swt[i] = dww[ch*125+i];
  for(int i=tid;i<2000;i+=128){
    int it = i/100, rm = i%100, ih = rm/10, iw = rm%10;
    int gt = it-2, gh = th*6+ih-2, gw = tw*6+iw-2;
    float v = 0.f;
    if(gt>=0 && gt<TT && gh>=0 && gh<HH && gw>=0 && gw<WW)
      v = src[gt*(HH*WW) + gh*WW + gw];
    si[i] = v;
  }
  __syncthreads();
  float bsv = dwb[ch];
  for(int o=tid;o<576;o+=128){
    int ot = o/36, rm = o%36, oh = rm/6, ow = rm%6;
    float a = 0.f;
    #pragma unroll
    for(int dt=0;dt<5;dt++)
      #pragma unroll
      for(int dh=0;dh<5;dh++)
        #pragma unroll
        for(int dw=0;dw<5;dw++)
          a += si[(ot+dt)*100 + (oh+dh)*10 + (ow+dw)]*swt[dt*25+dh*5+dw];
    a += bsv;
    g_dwcm[(bi*HID+ch)*THW + ot*(HH*WW) + (th*6+oh)*WW + (tw*6+ow)] = gelu_exact(a);
  }
}

// ---------------- K7: fc2 + residual + transposed output -------------------
__global__ void k_mlp2(const float* __restrict__ fc2w, const float* __restrict__ fc2b,
                       float* __restrict__ out){
  int token = blockIdx.x; int bi = token/THW, pos = token%THW;
  __shared__ float yf[128];
  int tid = threadIdx.x;   // 64
  #pragma unroll
  for(int half=0;half<2;half++){
    int j = tid + 64*half;
    yf[j] = g_y2[token*128+j] + g_dwcm[(bi*HID+j)*THW + pos];
  }
  __syncthreads();
  float a = fc2b[tid] + g_xtok[token*64+tid];
  #pragma unroll 16
  for(int j=0;j<128;j++) a += yf[j]*fc2w[j*64+tid];
  out[(bi*CC+tid)*THW + pos] = a;
}

// ---------------- launch ----------------------------------------------------
extern "C" void kernel_launch(void* const* d_in, const int* in_sizes, int n_in,
                              void* d_out, int out_size){
  const float* x    = (const float*)d_in[0];
  const float* ln1g = (const float*)d_in[1];
  const float* ln1b = (const float*)d_in[2];
  const float* wq   = (const float*)d_in[3];
  const float* wk   = (const float*)d_in[4];
  const float* wv   = (const float*)d_in[5];
  const float* wpr  = (const float*)d_in[6];
  const float* ln2g = (const float*)d_in[7];
  const float* ln2b = (const float*)d_in[8];
  const float* fc1w = (const float*)d_in[9];
  const float* fc1b = (const float*)d_in[10];
  const float* dww  = (const float*)d_in[11];
  const float* dwb  = (const float*)d_in[12];
  const float* fc2w = (const float*)d_in[13];
  const float* fc2b = (const float*)d_in[14];
  float* out = (float*)d_out;

  cudaFuncSetAttribute(k_attn, cudaFuncAttributeMaxDynamicSharedMemorySize, ATTN_SMEM);

  k_extract_ln<<<NROW/4, 256>>>(x, ln1g, ln1b);
  k_qkv<<<NROW/16, 128>>>(wq, wk, wv);
  k_attn<<<dim3(NP, HEADS), 256, ATTN_SMEM>>>();
  k_proj<<<NROW/4, 256>>>(wpr);
  k_mlp1<<<NTOK2, 64>>>(ln2g, ln2b, fc1w, fc1b);
  k_dwconv<<<BB*HID*36, 128>>>(dww, dwb);
  k_mlp2<<<NTOK2, 64>>>(fc2w, fc2b, out);
}

// round 2
// speedup vs baseline: 2.1637x; 2.1637x over previous
#include <cuda_runtime.h>
#include <math.h>

// ---------------- fixed problem constants -----------------------------------
#define BB 2
#define CC 64
#define TT 16
#define HH 36
#define WW 36
#define THW (TT*HH*WW)        // 20736
#define PS 8
#define NT 3
#define NH 6
#define NW 6
#define NPB (NT*NH*NW)        // 108
#define NP (BB*NPB)           // 216
#define TOKN 512
#define NROW (NP*TOKN)        // 110592
#define HEADS 2
#define HID 128
#define NTOK2 (BB*THW)        // 41472

__constant__ int   c_st_t[3] = {0,6,8};
__constant__ int   c_st_h[6] = {0,6,12,18,24,28};
// exact replication of _divisor (NOT coverage count): inverse divisors
__constant__ float c_idt[16] = {1,1,1,1,1,1,0.5f,0.5f,0.5f,0.5f,1,1,1,1,1,1};
__constant__ float c_idh[36] = {1,1,1,1,1,1, 0.5f,0.5f, 1,1,1,1, 0.5f,0.5f,
                                1,1,1,1, 0.5f,0.5f, 1,1,1,1, 0.5f,0.5f,
                                1,1, 0.5f,0.5f, 1,1,1,1,1,1};

// ---------------- scratch ---------------------------------------------------
__device__ float g_tokens[NROW*64];
__device__ float g_y[NROW*64];        // LN1 out; later tok2 (post-proj+res)
__device__ float g_q[NROW*32];
__device__ float g_kbuf[NROW*32];
__device__ float g_v[NROW*64];
__device__ float g_attn[NROW*64];
__device__ float g_xtok[NTOK2*64];
__device__ float g_y2[NTOK2*128];     // fc1+gelu token-major
__device__ float g_y2cm[BB*HID*THW];  // channel-major (conv in)
__device__ float g_dwcm[BB*HID*THW];  // conv+gelu channel-major

extern __shared__ float dynsm[];

__device__ __forceinline__ float wred(float v){
  #pragma unroll
  for(int o=16;o;o>>=1) v += __shfl_xor_sync(0xffffffffu, v, o);
  return v;
}
__device__ __forceinline__ float wmaxr(float v){
  #pragma unroll
  for(int o=16;o;o>>=1) v = fmaxf(v, __shfl_xor_sync(0xffffffffu, v, o));
  return v;
}
__device__ __forceinline__ float gelu_exact(float x){
  return 0.5f*x*(1.0f + erff(x*0.70710678118654752f));
}

// ---------------- K1: patch extract + LN1 -----------------------------------
// block per (patch, tt, hh): 8 tokens (ww 0..7); coalesced x reads.
__global__ void k_extract_ln(const float* __restrict__ x,
                             const float* __restrict__ g1,
                             const float* __restrict__ b1){
  int blk = blockIdx.x;               // NP*64
  int p = blk>>6; int rr = blk&63; int tt = rr>>3, hh = rr&7;
  int bi = p/NPB; int r = p%NPB;
  int pt=r/36, ph=(r%36)/6, pw=r%6;
  int ta=c_st_t[pt]+tt, ha=c_st_h[ph]+hh, w0=c_st_h[pw];
  __shared__ float sx[8][65];
  __shared__ float sm[8][2];
  int tid=threadIdx.x;                // 256
  for(int i=tid;i<512;i+=256){
    int ch=i>>3, ww=i&7;
    sx[ww][ch] = x[((bi*CC+ch)*TT+ta)*(HH*WW) + ha*WW + w0+ww];
  }
  __syncthreads();
  int grp=tid>>6, ch=tid&63, wid=tid>>5;
  #pragma unroll
  for(int gq=0;gq<2;gq++){
    int ww = grp + 4*gq;
    float v = sx[ww][ch];
    float s=wred(v), s2=wred(v*v);
    if((tid&31)==0){ sm[wid][0]=s; sm[wid][1]=s2; }
    __syncthreads();
    float su=sm[grp*2][0]+sm[grp*2+1][0];
    float sq=sm[grp*2][1]+sm[grp*2+1][1];
    float m=su*(1.0f/64.0f), var=sq*(1.0f/64.0f)-m*m;
    float rs=rsqrtf(var+1e-5f);
    int row=p*512 + tt*64 + hh*8 + ww;
    g_tokens[row*64+ch]=v;
    g_y[row*64+ch]=(v-m)*rs*g1[ch]+b1[ch];
    __syncthreads();
  }
}

// ---------------- K2: fused QKV GEMM (register-blocked) ---------------------
// 128 threads, 32 tokens/block. Thread j owns one of 128 output cols,
// 64 weights in registers, activations via float4 broadcast LDS.
__global__ void __launch_bounds__(128) k_qkv(const float* __restrict__ wq,
                      const float* __restrict__ wk,
                      const float* __restrict__ wv){
  __shared__ float sy[32*64];
  int tid = threadIdx.x;
  int base = blockIdx.x*32;
  for(int i=tid;i<2048;i+=128) sy[i] = g_y[base*64 + i];
  int j = tid;
  float wreg[64];
  if(j<32){
    #pragma unroll
    for(int kk=0;kk<64;kk++) wreg[kk]=wq[kk*32+j];
  } else if(j<64){
    #pragma unroll
    for(int kk=0;kk<64;kk++) wreg[kk]=wk[kk*32+(j-32)];
  } else {
    #pragma unroll
    for(int kk=0;kk<64;kk++) wreg[kk]=wv[kk*64+(j-64)];
  }
  __syncthreads();
  for(int t=0;t<32;t++){
    float a = 0.f;
    const float4* yp = (const float4*)(sy + t*64);
    #pragma unroll
    for(int k4=0;k4<16;k4++){
      float4 y = yp[k4];
      a += y.x*wreg[k4*4] + y.y*wreg[k4*4+1] + y.z*wreg[k4*4+2] + y.w*wreg[k4*4+3];
    }
    int row = base + t;
    if(j<32)       g_q[row*32+j] = a;
    else if(j<64)  g_kbuf[row*32+(j-32)] = a;
    else           g_v[row*64+(j-64)] = a;
  }
}

// ---------------- K3: attention per (patch, head) ---------------------------
// 256 threads (8 warps). Q/K/V/scores in 200KB dyn smem.
// Warp processes 4 queries at a time: Q in regs, K via LDS.128 (pad 20),
// PV via float4 prob broadcast + scalar V -> FMA-bound.
#define AT_SMEM ((512*16 + 512*20 + 512*32 + 8*4*512)*4)
__global__ void __launch_bounds__(256,1) k_attn(){
  int p = blockIdx.x, hd = blockIdx.y;
  float* sQ = dynsm;            // 512*16
  float* sK = sQ + 512*16;      // 512*20 (padded)
  float* sV = sK + 512*20;      // 512*32
  float* sS = sV + 512*32;      // 8 warps * 4q * 512
  int tid = threadIdx.x;
  const float* qg = g_q   + p*512*32 + hd*16;
  const float* kg = g_kbuf+ p*512*32 + hd*16;
  const float* vg = g_v   + p*512*64 + hd*32;
  for(int i=tid;i<512*16;i+=256){ int j=i>>4, d=i&15; sQ[j*16+d]=qg[j*32+d]; }
  for(int i=tid;i<512*16;i+=256){ int j=i>>4, d=i&15; sK[j*20+d]=kg[j*32+d]; }
  for(int i=tid;i<512*32;i+=256){ int j=i>>5, d=i&31; sV[j*32+d]=vg[j*64+d]; }
  __syncthreads();
  int w = tid>>5, lane = tid&31;
  float* sSw = sS + w*2048;
  for(int r=0;r<16;r++){
    int q0 = r*32 + w*4;
    float qv[4][16];
    #pragma unroll
    for(int qq=0;qq<4;qq++){
      const float4* qp = (const float4*)(sQ + (q0+qq)*16);
      #pragma unroll
      for(int d4=0;d4<4;d4++){
        float4 f = qp[d4];
        qv[qq][d4*4+0]=f.x; qv[qq][d4*4+1]=f.y; qv[qq][d4*4+2]=f.z; qv[qq][d4*4+3]=f.w;
      }
    }
    float mx[4] = {-1e30f,-1e30f,-1e30f,-1e30f};
    #pragma unroll 2
    for(int i=0;i<16;i++){
      int j = lane + 32*i;
      const float4* kp = (const float4*)(sK + j*20);
      float kr[16];
      #pragma unroll
      for(int d4=0;d4<4;d4++){
        float4 f=kp[d4];
        kr[d4*4]=f.x; kr[d4*4+1]=f.y; kr[d4*4+2]=f.z; kr[d4*4+3]=f.w;
      }
      #pragma unroll
      for(int qq=0;qq<4;qq++){
        float s=0.f;
        #pragma unroll
        for(int d=0;d<16;d++) s += qv[qq][d]*kr[d];
        s *= 0.25f;
        sSw[qq*512+j] = s;
        mx[qq] = fmaxf(mx[qq], s);
      }
    }
    #pragma unroll
    for(int qq=0;qq<4;qq++) mx[qq] = wmaxr(mx[qq]);
    float sum[4] = {0.f,0.f,0.f,0.f};
    #pragma unroll 2
    for(int i=0;i<16;i++){
      int j = lane + 32*i;
      #pragma unroll
      for(int qq=0;qq<4;qq++){
        float e = __expf(sSw[qq*512+j] - mx[qq]);
        sSw[qq*512+j] = e;
        sum[qq] += e;
      }
    }
    float inv[4];
    #pragma unroll
    for(int qq=0;qq<4;qq++) inv[qq] = 1.0f/wred(sum[qq]);
    __syncwarp();
    float o[4]={0.f,0.f,0.f,0.f};
    #pragma unroll 2
    for(int j0=0;j0<512;j0+=4){
      float v0 = sV[(j0+0)*32+lane];
      float v1 = sV[(j0+1)*32+lane];
      float v2 = sV[(j0+2)*32+lane];
      float v3 = sV[(j0+3)*32+lane];
      #pragma unroll
      for(int qq=0;qq<4;qq++){
        float4 pr = *(const float4*)(sSw + qq*512 + j0);
        o[qq] += pr.x*v0 + pr.y*v1 + pr.z*v2 + pr.w*v3;
      }
    }
    float* og = g_attn + (p*512+q0)*64 + hd*32 + lane;
    #pragma unroll
    for(int qq=0;qq<4;qq++) og[qq*64] = o[qq]*inv[qq];
    __syncwarp();
  }
}

// ---------------- K4: proj + residual (register-blocked) --------------------
// 128 threads, 16 tokens/block; thread = (ch, tokengroup); weights in regs.
__global__ void __launch_bounds__(128) k_proj(const float* __restrict__ wproj){
  __shared__ float sA[16*64];
  int tid = threadIdx.x;
  int base = blockIdx.x*16;
  int ch = tid&63, tg = tid>>6;
  for(int i=tid;i<1024;i+=128) sA[i] = g_attn[base*64 + i];
  float wreg[64];
  #pragma unroll
  for(int kk=0;kk<64;kk++) wreg[kk] = wproj[kk*64+ch];
  __syncthreads();
  for(int t=tg*8;t<tg*8+8;t++){
    float a = g_tokens[(base+t)*64+ch];
    const float4* ap = (const float4*)(sA + t*64);
    #pragma unroll
    for(int k4=0;k4<16;k4++){
      float4 v = ap[k4];
      a += v.x*wreg[k4*4] + v.y*wreg[k4*4+1] + v.z*wreg[k4*4+2] + v.w*wreg[k4*4+3];
    }
    g_y[(base+t)*64+ch] = a;
  }
}

// ---------------- K5: gather-reverse + div + LN2 + fc1 + gelu ---------------
// 128 threads, 32 tokens/block.
__global__ void __launch_bounds__(128) k_mlp1(const float* __restrict__ g2, const float* __restrict__ b2,
                       const float* __restrict__ fc1w, const float* __restrict__ fc1b){
  __shared__ float sX[32*67];
  __shared__ float sYn[32*68];
  __shared__ float sStat[32][2];
  int base = blockIdx.x*32;
  int bi = base/THW;
  int tid = threadIdx.x;
  int ch = tid&63, half = tid>>6;
  float xvr[16];
  for(int k=0;k<16;k++){
    int t = half + 2*k;
    int token = base + t;
    int pos = token % THW;
    int tt_ = pos/(HH*WW), hh_=(pos/WW)%HH, ww_=pos%WW;
    float acc = 0.f;
    #pragma unroll
    for(int pt=0;pt<3;pt++){
      int dt_ = tt_-c_st_t[pt]; if(dt_<0||dt_>=8) continue;
      #pragma unroll
      for(int ph=0;ph<6;ph++){
        int dh_ = hh_-c_st_h[ph]; if(dh_<0||dh_>=8) continue;
        #pragma unroll
        for(int pw=0;pw<6;pw++){
          int dw_ = ww_-c_st_h[pw]; if(dw_<0||dw_>=8) continue;
          int pp = bi*NPB + pt*36 + ph*6 + pw;
          int tk = dt_*64 + dh_*8 + dw_;
          acc += g_y[(pp*512+tk)*64 + ch];
        }
      }
    }
    float xv = acc * c_idt[tt_]*c_idh[hh_]*c_idh[ww_];
    xvr[k] = xv;
    sX[t*67+ch] = xv;
    g_xtok[token*64+ch] = xv;
  }
  __syncthreads();
  if(tid<32){
    float s=0.f, s2=0.f;
    #pragma unroll 8
    for(int k=0;k<64;k++){ float v=sX[tid*67+k]; s+=v; s2+=v*v; }
    float m=s*(1.0f/64.0f), var=s2*(1.0f/64.0f)-m*m;
    sStat[tid][0]=m; sStat[tid][1]=rsqrtf(var+1e-5f);
  }
  __syncthreads();
  float gg=g2[ch], bb=b2[ch];
  for(int k=0;k<16;k++){
    int t = half + 2*k;
    sYn[t*68+ch] = (xvr[k]-sStat[t][0])*sStat[t][1]*gg + bb;
  }
  __syncthreads();
  int j = tid;
  float wreg[64];
  #pragma unroll
  for(int kk=0;kk<64;kk++) wreg[kk]=fc1w[kk*128+j];
  float bj = fc1b[j];
  for(int t=0;t<32;t++){
    float a = bj;
    const float4* yp = (const float4*)(sYn + t*68);
    #pragma unroll
    for(int k4=0;k4<16;k4++){
      float4 y = yp[k4];
      a += y.x*wreg[k4*4] + y.y*wreg[k4*4+1] + y.z*wreg[k4*4+2] + y.w*wreg[k4*4+3];
    }
    g_y2[(base+t)*128+j] = gelu_exact(a);
  }
}

// ---------------- K5b: transpose token-major -> channel-major ---------------
__global__ void k_tr(){
  __shared__ float tile[32][33];
  int bi = blockIdx.z; int c0 = blockIdx.y*32; int p0 = blockIdx.x*32;
  int tx = threadIdx.x, ty = threadIdx.y;   // 32 x 8
  for(int yy=ty;yy<32;yy+=8)
    tile[yy][tx] = g_y2[(bi*THW + p0+yy)*128 + c0+tx];
  __syncthreads();
  for(int yy=ty;yy<32;yy+=8)
    g_y2cm[(bi*HID + c0+yy)*THW + p0+tx] = tile[tx][yy];
}

// ---------------- K6: depthwise 5^3 conv + bias + gelu ----------------------
// 96 threads; thread = (ot, oh) computes 6 outputs along w.
__global__ void __launch_bounds__(96) k_dwconv(const float* __restrict__ dww, const float* __restrict__ dwb){
  __shared__ float si[20*10*10];
  __shared__ float swt[125];
  int blk = blockIdx.x;
  int tile = blk%36; int cb = blk/36; int ch = cb%HID; int bi = cb/HID;
  int th = tile/6, tw = tile%6;
  int tid = threadIdx.x;
  const float* src = g_y2cm + (bi*HID+ch)*THW;

  for(int i=tid;i<125;i+=96) swt[i] = dww[ch*125+i];
  for(int i=tid;i<2000;i+=96){
    int it = i/100, rm = i%100, ih = rm/10, iw = rm%10;
    int gt = it-2, gh = th*6+ih-2, gw = tw*6+iw-2;
    float v = 0.f;
    if(gt>=0 && gt<TT && gh>=0 && gh<HH && gw>=0 && gw<WW)
      v = src[gt*(HH*WW) + gh*WW + gw];
    si[i] = v;
  }
  __syncthreads();
  int ot = tid/6, oh = tid%6;
  float acc[6] = {0.f,0.f,0.f,0.f,0.f,0.f};
  #pragma unroll
  for(int dt=0;dt<5;dt++){
    #pragma unroll
    for(int dh=0;dh<5;dh++){
      const float* row = si + (ot+dt)*100 + (oh+dh)*10;
      float rr[10];
      #pragma unroll
      for(int i=0;i<10;i++) rr[i]=row[i];
      const float* wp = swt + dt*25 + dh*5;
      float w0=wp[0],w1=wp[1],w2=wp[2],w3=wp[3],w4=wp[4];
      #pragma unroll
      for(int ow=0;ow<6;ow++)
        acc[ow] += rr[ow]*w0 + rr[ow+1]*w1 + rr[ow+2]*w2 + rr[ow+3]*w3 + rr[ow+4]*w4;
    }
  }
  float bsv = dwb[ch];
  float* dst = g_dwcm + (bi*HID+ch)*THW + ot*(HH*WW) + (th*6+oh)*WW + tw*6;
  #pragma unroll
  for(int ow=0;ow<6;ow++) dst[ow] = gelu_exact(acc[ow] + bsv);
}

// ---------------- K7: fc2 + residual + transposed output --------------------
// 128 threads, 32 tokens/block; dyn smem 58KB.
#define MLP2_SMEM ((32*132 + 128*64 + 32*65)*4)
__global__ void __launch_bounds__(128) k_mlp2(const float* __restrict__ fc2w, const float* __restrict__ fc2b,
                       float* __restrict__ out){
  float* sYf  = dynsm;               // 32*132
  float* sW   = sYf + 32*132;        // 128*64
  float* sOut = sW + 128*64;         // 32*65
  int base = blockIdx.x*32;
  int bi = base/THW; int pos0 = base%THW;
  int tid = threadIdx.x;
  for(int i=tid;i<8192;i+=128) sW[i] = fc2w[i];
  for(int i=tid;i<4096;i+=128){ int t=i>>7, j=i&127; sYf[t*132+j] = g_y2[(base+t)*128+j]; }
  __syncthreads();
  for(int i=tid;i<4096;i+=128){ int t=i&31, j=i>>5; sYf[t*132+j] += g_dwcm[(bi*HID+j)*THW + pos0 + t]; }
  __syncthreads();
  int ch = tid&63, tg = tid>>6;
  float b = fc2b[ch];
  #pragma unroll
  for(int tq=0;tq<4;tq++){
    int tt = tg*16 + tq*4;
    float a0 = b + g_xtok[(base+tt+0)*64+ch];
    float a1 = b + g_xtok[(base+tt+1)*64+ch];
    float a2 = b + g_xtok[(base+tt+2)*64+ch];
    float a3 = b + g_xtok[(base+tt+3)*64+ch];
    #pragma unroll 8
    for(int k4=0;k4<32;k4++){
      float4 y0 = *(const float4*)(sYf + (tt+0)*132 + k4*4);
      float4 y1 = *(const float4*)(sYf + (tt+1)*132 + k4*4);
      float4 y2 = *(const float4*)(sYf + (tt+2)*132 + k4*4);
      float4 y3 = *(const float4*)(sYf + (tt+3)*132 + k4*4);
      float w0 = sW[(k4*4+0)*64+ch];
      float w1 = sW[(k4*4+1)*64+ch];
      float w2 = sW[(k4*4+2)*64+ch];
      float w3 = sW[(k4*4+3)*64+ch];
      a0 += y0.x*w0 + y0.y*w1 + y0.z*w2 + y0.w*w3;
      a1 += y1.x*w0 + y1.y*w1 + y1.z*w2 + y1.w*w3;
      a2 += y2.x*w0 + y2.y*w1 + y2.z*w2 + y2.w*w3;
      a3 += y3.x*w0 + y3.y*w1 + y3.z*w2 + y3.w*w3;
    }
    sOut[(tt+0)*65+ch]=a0; sOut[(tt+1)*65+ch]=a1;
    sOut[(tt+2)*65+ch]=a2; sOut[(tt+3)*65+ch]=a3;
  }
  __syncthreads();
  for(int i=tid;i<2048;i+=128){
    int t=i&31, c=i>>5;
    out[(bi*CC+c)*THW + pos0 + t] = sOut[t*65+c];
  }
}

// ---------------- launch ----------------------------------------------------
extern "C" void kernel_launch(void* const* d_in, const int* in_sizes, int n_in,
                              void* d_out, int out_size){
  const float* x    = (const float*)d_in[0];
  const float* ln1g = (const float*)d_in[1];
  const float* ln1b = (const float*)d_in[2];
  const float* wq   = (const float*)d_in[3];
  const float* wk   = (const float*)d_in[4];
  const float* wv   = (const float*)d_in[5];
  const float* wpr  = (const float*)d_in[6];
  const float* ln2g = (const float*)d_in[7];
  const float* ln2b = (const float*)d_in[8];
  const float* fc1w = (const float*)d_in[9];
  const float* fc1b = (const float*)d_in[10];
  const float* dww  = (const float*)d_in[11];
  const float* dwb  = (const float*)d_in[12];
  const float* fc2w = (const float*)d_in[13];
  const float* fc2b = (const float*)d_in[14];
  float* out = (float*)d_out;

  static int inited = 0;
  if(!inited){
    cudaFuncSetAttribute(k_attn, cudaFuncAttributeMaxDynamicSharedMemorySize, AT_SMEM);
    cudaFuncSetAttribute(k_mlp2, cudaFuncAttributeMaxDynamicSharedMemorySize, MLP2_SMEM);
    inited = 1;
  }

  k_extract_ln<<<NP*64, 256>>>(x, ln1g, ln1b);
  k_qkv<<<NROW/32, 128>>>(wq, wk, wv);
  k_attn<<<dim3(NP, HEADS), 256, AT_SMEM>>>();
  k_proj<<<NROW/16, 128>>>(wpr);
  k_mlp1<<<NTOK2/32, 128>>>(ln2g, ln2b, fc1w, fc1b);
  k_tr<<<dim3(THW/32, HID/32, BB), dim3(32,8)>>>();
  k_dwconv<<<BB*HID*36, 96>>>(dww, dwb);
  k_mlp2<<<NTOK2/32, 128, MLP2_SMEM>>>(fc2w, fc2b, out);
}

// round 4
// speedup vs baseline: 2.2385x; 1.0346x over previous
#include <cuda_runtime.h>
#include <math.h>

// ---------------- fixed problem constants -----------------------------------
#define BB 2
#define CC 64
#define TT 16
#define HH 36
#define WW 36
#define THW (TT*HH*WW)        // 20736
#define PS 8
#define NT 3
#define NH 6
#define NW 6
#define NPB (NT*NH*NW)        // 108
#define NP (BB*NPB)           // 216
#define TOKN 512
#define NROW (NP*TOKN)        // 110592
#define HEADS 2
#define HID 128
#define NTOK2 (BB*THW)        // 41472

__constant__ int   c_st_t[3] = {0,6,8};
__constant__ int   c_st_h[6] = {0,6,12,18,24,28};
// exact replication of _divisor (NOT coverage count): inverse divisors
__constant__ float c_idt[16] = {1,1,1,1,1,1,0.5f,0.5f,0.5f,0.5f,1,1,1,1,1,1};
__constant__ float c_idh[36] = {1,1,1,1,1,1, 0.5f,0.5f, 1,1,1,1, 0.5f,0.5f,
                                1,1,1,1, 0.5f,0.5f, 1,1,1,1, 0.5f,0.5f,
                                1,1, 0.5f,0.5f, 1,1,1,1,1,1};

// ---------------- scratch ---------------------------------------------------
__device__ float g_xt[NTOK2*64];      // x, token-major grid
__device__ float g_yt[NTOK2*64];      // LN1(x), token-major grid
__device__ float g_q[NROW*32];
__device__ float g_kbuf[NROW*32];
__device__ float g_v[NROW*64];
__device__ float g_attn[NROW*64];
__device__ float g_tok2[NROW*64];     // proj out + residual (per patch-token)
__device__ float g_xtok[NTOK2*64];    // pre-LN2 grid (residual for fc2)
__device__ float g_y2[NTOK2*128];     // fc1+gelu token-major
__device__ float g_y2cm[BB*HID*THW];  // channel-major (conv in)
__device__ float g_dwcm[BB*HID*THW];  // conv+gelu channel-major

extern __shared__ float dynsm[];

__device__ __forceinline__ float wred(float v){
  #pragma unroll
  for(int o=16;o;o>>=1) v += __shfl_xor_sync(0xffffffffu, v, o);
  return v;
}
__device__ __forceinline__ float wmaxr(float v){
  #pragma unroll
  for(int o=16;o;o>>=1) v = fmaxf(v, __shfl_xor_sync(0xffffffffu, v, o));
  return v;
}
__device__ __forceinline__ float gelu_exact(float x){
  return 0.5f*x*(1.0f + erff(x*0.70710678118654752f));
}
// token index (0..511) + patch coords -> spatial pos
__device__ __forceinline__ int tok2pos(int tok, int pt, int ph, int pw){
  int tt = tok>>6, hh = (tok>>3)&7, ww = tok&7;
  return (c_st_t[pt]+tt)*(HH*WW) + (c_st_h[ph]+hh)*WW + (c_st_h[pw]+ww);
}

// ---------------- K0: grid LN1 (stats are per-position, patch-independent) --
__global__ void __launch_bounds__(256) k_ln1(const float* __restrict__ x,
                    const float* __restrict__ g1, const float* __restrict__ b1){
  __shared__ float s[32][65];
  __shared__ float st[32][2];
  int bi = blockIdx.y; int pos0 = blockIdx.x*32;
  int tid = threadIdx.x;
  for(int i=tid;i<2048;i+=256){
    int ch=i>>5, pp=i&31;
    s[pp][ch] = x[(bi*64+ch)*THW + pos0+pp];
  }
  __syncthreads();
  int w = tid>>5, lane = tid&31;
  #pragma unroll
  for(int q=0;q<4;q++){
    int pp = w*4+q;
    float a = s[pp][lane], b = s[pp][lane+32];
    float su = wred(a+b);
    float sq = wred(a*a+b*b);
    if(lane==0){
      float m = su*(1.0f/64.0f);
      float var = sq*(1.0f/64.0f) - m*m;
      st[pp][0]=m; st[pp][1]=rsqrtf(var+1e-5f);
    }
  }
  __syncthreads();
  for(int i=tid;i<2048;i+=256){
    int pp=i>>6, ch=i&63;
    float v = s[pp][ch];
    int idx = (bi*THW + pos0+pp)*64 + ch;
    g_xt[idx] = v;
    g_yt[idx] = (v-st[pp][0])*st[pp][1]*g1[ch] + b1[ch];
  }
}

// ---------------- K1: fused QKV GEMM (gather + ILP-8) -----------------------
__global__ void __launch_bounds__(128) k_qkv(const float* __restrict__ wq,
                      const float* __restrict__ wk,
                      const float* __restrict__ wv){
  __shared__ float sy[32*64];
  int tid = threadIdx.x;
  int base = blockIdx.x*32;
  int p = base>>9, tok0 = base&511;
  int bi = p/NPB; int r = p%NPB;
  int pt=r/36, ph=(r%36)/6, pw=r%6;
  for(int i=tid;i<2048;i+=128){
    int t=i>>6, ch=i&63;
    int pos = tok2pos(tok0+t, pt, ph, pw);
    sy[t*64+ch] = g_yt[(bi*THW+pos)*64+ch];
  }
  int j = tid;
  float wreg[64];
  if(j<32){
    #pragma unroll
    for(int kk=0;kk<64;kk++) wreg[kk]=wq[kk*32+j];
  } else if(j<64){
    #pragma unroll
    for(int kk=0;kk<64;kk++) wreg[kk]=wk[kk*32+(j-32)];
  } else {
    #pragma unroll
    for(int kk=0;kk<64;kk++) wreg[kk]=wv[kk*64+(j-64)];
  }
  __syncthreads();
  for(int tb=0;tb<4;tb++){
    float acc[8] = {0,0,0,0,0,0,0,0};
    #pragma unroll
    for(int k4=0;k4<16;k4++){
      float w0=wreg[k4*4], w1=wreg[k4*4+1], w2=wreg[k4*4+2], w3=wreg[k4*4+3];
      #pragma unroll
      for(int t=0;t<8;t++){
        float4 y = *(const float4*)(sy + (tb*8+t)*64 + k4*4);
        acc[t] += y.x*w0 + y.y*w1 + y.z*w2 + y.w*w3;
      }
    }
    #pragma unroll
    for(int t=0;t<8;t++){
      int row = base + tb*8 + t;
      if(j<32)       g_q[row*32+j] = acc[t];
      else if(j<64)  g_kbuf[row*32+(j-32)] = acc[t];
      else           g_v[row*64+(j-64)] = acc[t];
    }
  }
}

// ---------------- K2: attention per (patch, head) ---------------------------
// 256 threads (8 warps), 4 queries per warp-pass, V transposed in smem.
#define AT_SMEM ((512*16 + 512*20 + 32*516 + 8*4*512)*4)
__global__ void __launch_bounds__(256,1) k_attn(){
  int p = blockIdx.x, hd = blockIdx.y;
  float* sQ  = dynsm;               // 512*16
  float* sK  = sQ + 512*16;         // 512*20 (padded)
  float* sVT = sK + 512*20;         // 32 rows * 516 (padded): VT[d][j]
  float* sS  = sVT + 32*516;        // 8 warps * 4q * 512
  int tid = threadIdx.x;
  const float* qg = g_q   + p*512*32 + hd*16;
  const float* kg = g_kbuf+ p*512*32 + hd*16;
  const float* vg = g_v   + p*512*64 + hd*32;
  for(int i=tid;i<512*16;i+=256){ int j=i>>4, d=i&15; sQ[j*16+d]=qg[j*32+d]; }
  for(int i=tid;i<512*16;i+=256){ int j=i>>4, d=i&15; sK[j*20+d]=kg[j*32+d]; }
  for(int i=tid;i<512*32;i+=256){ int j=i>>5, d=i&31; sVT[d*516+j]=vg[j*64+d]; }
  __syncthreads();
  int w = tid>>5, lane = tid&31;
  float* sSw = sS + w*2048;
  for(int it=0;it<16;it++){
    int q0 = it*32 + w*4;
    float qv[4][16];
    #pragma unroll
    for(int qq=0;qq<4;qq++){
      const float4* qp = (const float4*)(sQ + (q0+qq)*16);
      #pragma unroll
      for(int d4=0;d4<4;d4++){
        float4 f = qp[d4];
        qv[qq][d4*4+0]=f.x; qv[qq][d4*4+1]=f.y; qv[qq][d4*4+2]=f.z; qv[qq][d4*4+3]=f.w;
      }
    }
    float mx[4] = {-1e30f,-1e30f,-1e30f,-1e30f};
    #pragma unroll 2
    for(int i=0;i<16;i++){
      int j = lane + 32*i;
      const float4* kp = (const float4*)(sK + j*20);
      float kr[16];
      #pragma unroll
      for(int d4=0;d4<4;d4++){
        float4 f=kp[d4];
        kr[d4*4]=f.x; kr[d4*4+1]=f.y; kr[d4*4+2]=f.z; kr[d4*4+3]=f.w;
      }
      #pragma unroll
      for(int qq=0;qq<4;qq++){
        float s=0.f;
        #pragma unroll
        for(int d=0;d<16;d++) s += qv[qq][d]*kr[d];
        s *= 0.25f;
        sSw[qq*512+j] = s;
        mx[qq] = fmaxf(mx[qq], s);
      }
    }
    #pragma unroll
    for(int qq=0;qq<4;qq++) mx[qq] = wmaxr(mx[qq]);
    float sum[4] = {0.f,0.f,0.f,0.f};
    #pragma unroll 2
    for(int i=0;i<16;i++){
      int j = lane + 32*i;
      #pragma unroll
      for(int qq=0;qq<4;qq++){
        float e = __expf(sSw[qq*512+j] - mx[qq]);
        sSw[qq*512+j] = e;
        sum[qq] += e;
      }
    }
    float inv[4];
    #pragma unroll
    for(int qq=0;qq<4;qq++) inv[qq] = 1.0f/wred(sum[qq]);
    __syncwarp();
    float o[4]={0.f,0.f,0.f,0.f};
    #pragma unroll 4
    for(int j0=0;j0<512;j0+=4){
      float4 vv = *(const float4*)(sVT + lane*516 + j0);
      #pragma unroll
      for(int qq=0;qq<4;qq++){
        float4 pr = *(const float4*)(sSw + qq*512 + j0);
        o[qq] += pr.x*vv.x + pr.y*vv.y + pr.z*vv.z + pr.w*vv.w;
      }
    }
    float* og = g_attn + (p*512+q0)*64 + hd*32 + lane;
    #pragma unroll
    for(int qq=0;qq<4;qq++) og[qq*64] = o[qq]*inv[qq];
    __syncwarp();
  }
}

// ---------------- K3: proj + residual (ILP-8) -------------------------------
__global__ void __launch_bounds__(128) k_proj(const float* __restrict__ wproj){
  __shared__ float sA[32*64];
  int tid = threadIdx.x;
  int base = blockIdx.x*32;
  int p = base>>9, tok0 = base&511;
  int bi = p/NPB; int r = p%NPB;
  int pt=r/36, ph=(r%36)/6, pw=r%6;
  int ch = tid&63, tg = tid>>6;
  for(int i=tid;i<2048;i+=128) sA[i] = g_attn[base*64 + i];
  float wreg[64];
  #pragma unroll
  for(int kk=0;kk<64;kk++) wreg[kk] = wproj[kk*64+ch];
  __syncthreads();
  for(int tb=0;tb<2;tb++){
    int t0 = tg*16 + tb*8;
    float acc[8];
    #pragma unroll
    for(int t=0;t<8;t++){
      int pos = tok2pos(tok0+t0+t, pt, ph, pw);
      acc[t] = g_xt[(bi*THW+pos)*64+ch];
    }
    #pragma unroll
    for(int k4=0;k4<16;k4++){
      float w0=wreg[k4*4], w1=wreg[k4*4+1], w2=wreg[k4*4+2], w3=wreg[k4*4+3];
      #pragma unroll
      for(int t=0;t<8;t++){
        float4 a4 = *(const float4*)(sA + (t0+t)*64 + k4*4);
        acc[t] += a4.x*w0 + a4.y*w1 + a4.z*w2 + a4.w*w3;
      }
    }
    #pragma unroll
    for(int t=0;t<8;t++) g_tok2[(base+t0+t)*64+ch] = acc[t];
  }
}

// ---------------- K4: gather-reverse + div + LN2 + fc1 + gelu (ILP-8) -------
__global__ void __launch_bounds__(128) k_mlp1(const float* __restrict__ g2, const float* __restrict__ b2,
                       const float* __restrict__ fc1w, const float* __restrict__ fc1b){
  __shared__ float sX[32*67];
  __shared__ float sYn[32*68];
  __shared__ float sStat[32][2];
  int base = blockIdx.x*32;
  int bi = base/THW;
  int tid = threadIdx.x;
  int ch = tid&63, half = tid>>6;
  float xvr[16];
  for(int k=0;k<16;k++){
    int t = half + 2*k;
    int token = base + t;
    int pos = token % THW;
    int tt_ = pos/(HH*WW), hh_=(pos/WW)%HH, ww_=pos%WW;
    float acc = 0.f;
    #pragma unroll
    for(int pt=0;pt<3;pt++){
      int dt_ = tt_-c_st_t[pt]; if(dt_<0||dt_>=8) continue;
      #pragma unroll
      for(int ph=0;ph<6;ph++){
        int dh_ = hh_-c_st_h[ph]; if(dh_<0||dh_>=8) continue;
        #pragma unroll
        for(int pw=0;pw<6;pw++){
          int dw_ = ww_-c_st_h[pw]; if(dw_<0||dw_>=8) continue;
          int pp = bi*NPB + pt*36 + ph*6 + pw;
          int tk = dt_*64 + dh_*8 + dw_;
          acc += g_tok2[(pp*512+tk)*64 + ch];
        }
      }
    }
    float xv = acc * c_idt[tt_]*c_idh[hh_]*c_idh[ww_];
    xvr[k] = xv;
    sX[t*67+ch] = xv;
    g_xtok[token*64+ch] = xv;
  }
  __syncthreads();
  if(tid<32){
    float s=0.f, s2=0.f;
    #pragma unroll 8
    for(int k=0;k<64;k++){ float v=sX[tid*67+k]; s+=v; s2+=v*v; }
    float m=s*(1.0f/64.0f), var=s2*(1.0f/64.0f)-m*m;
    sStat[tid][0]=m; sStat[tid][1]=rsqrtf(var+1e-5f);
  }
  __syncthreads();
  float gg=g2[ch], bb=b2[ch];
  for(int k=0;k<16;k++){
    int t = half + 2*k;
    sYn[t*68+ch] = (xvr[k]-sStat[t][0])*sStat[t][1]*gg + bb;
  }
  __syncthreads();
  int j = tid;
  float wreg[64];
  #pragma unroll
  for(int kk=0;kk<64;kk++) wreg[kk]=fc1w[kk*128+j];
  float bj = fc1b[j];
  for(int tb=0;tb<4;tb++){
    float acc[8];
    #pragma unroll
    for(int t=0;t<8;t++) acc[t]=bj;
    #pragma unroll
    for(int k4=0;k4<16;k4++){
      float w0=wreg[k4*4], w1=wreg[k4*4+1], w2=wreg[k4*4+2], w3=wreg[k4*4+3];
      #pragma unroll
      for(int t=0;t<8;t++){
        float4 y = *(const float4*)(sYn + (tb*8+t)*68 + k4*4);
        acc[t] += y.x*w0 + y.y*w1 + y.z*w2 + y.w*w3;
      }
    }
    #pragma unroll
    for(int t=0;t<8;t++) g_y2[(base+tb*8+t)*128+j] = gelu_exact(acc[t]);
  }
}

// ---------------- K5: transpose token-major -> channel-major ----------------
__global__ void k_tr(){
  __shared__ float tile[32][33];
  int bi = blockIdx.z; int c0 = blockIdx.y*32; int p0 = blockIdx.x*32;
  int tx = threadIdx.x, ty = threadIdx.y;   // 32 x 8
  for(int yy=ty;yy<32;yy+=8)
    tile[yy][tx] = g_y2[(bi*THW + p0+yy)*128 + c0+tx];
  __syncthreads();
  for(int yy=ty;yy<32;yy+=8)
    g_y2cm[(bi*HID + c0+yy)*THW + p0+tx] = tile[tx][yy];
}

// ---------------- K6: depthwise 5^3 conv + bias + gelu ----------------------
__global__ void __launch_bounds__(96) k_dwconv(const float* __restrict__ dww, const float* __restrict__ dwb){
  __shared__ float si[20*10*10];
  __shared__ float swt[125];
  int blk = blockIdx.x;
  int tile = blk%36; int cb = blk/36; int ch = cb%HID; int bi = cb/HID;
  int th = tile/6, tw = tile%6;
  int tid = threadIdx.x;
  const float* src = g_y2cm + (bi*HID+ch)*THW;

  for(int i=tid;i<125;i+=96) swt[i] = dww[ch*125+i];
  for(int i=tid;i<2000;i+=96){
    int it = i/100, rm = i%100, ih = rm/10, iw = rm%10;
    int gt = it-2, gh = th*6+ih-2, gw = tw*6+iw-2;
    float v = 0.f;
    if(gt>=0 && gt<TT && gh>=0 && gh<HH && gw>=0 && gw<WW)
      v = src[gt*(HH*WW) + gh*WW + gw];
    si[i] = v;
  }
  __syncthreads();
  int ot = tid/6, oh = tid%6;
  float acc[6] = {0.f,0.f,0.f,0.f,0.f,0.f};
  #pragma unroll
  for(int dt=0;dt<5;dt++){
    #pragma unroll
    for(int dh=0;dh<5;dh++){
      const float* row = si + (ot+dt)*100 + (oh+dh)*10;
      float rr[10];
      #pragma unroll
      for(int i=0;i<10;i++) rr[i]=row[i];
      const float* wp = swt + dt*25 + dh*5;
      float w0=wp[0],w1=wp[1],w2=wp[2],w3=wp[3],w4=wp[4];
      #pragma unroll
      for(int ow=0;ow<6;ow++)
        acc[ow] += rr[ow]*w0 + rr[ow+1]*w1 + rr[ow+2]*w2 + rr[ow+3]*w3 + rr[ow+4]*w4;
    }
  }
  float bsv = dwb[ch];
  float* dst = g_dwcm + (bi*HID+ch)*THW + ot*(HH*WW) + (th*6+oh)*WW + tw*6;
  #pragma unroll
  for(int ow=0;ow<6;ow++) dst[ow] = gelu_exact(acc[ow] + bsv);
}

// ---------------- K7: fc2 + residual + transposed output (ILP-8) ------------
#define MLP2_SMEM ((32*132 + 128*64 + 32*65)*4)
__global__ void __launch_bounds__(128) k_mlp2(const float* __restrict__ fc2w, const float* __restrict__ fc2b,
                       float* __restrict__ out){
  float* sYf  = dynsm;               // 32*132
  float* sW   = sYf + 32*132;        // 128*64
  float* sOut = sW + 128*64;         // 32*65
  int base = blockIdx.x*32;
  int bi = base/THW; int pos0 = base%THW;
  int tid = threadIdx.x;
  for(int i=tid;i<8192;i+=128) sW[i] = fc2w[i];
  for(int i=tid;i<4096;i+=128){ int t=i>>7, j=i&127; sYf[t*132+j] = g_y2[(base+t)*128+j]; }
  __syncthreads();
  for(int i=tid;i<4096;i+=128){ int t=i&31, j=i>>5; sYf[t*132+j] += g_dwcm[(bi*HID+j)*THW + pos0 + t]; }
  __syncthreads();
  int ch = tid&63, tg = tid>>6;
  float b = fc2b[ch];
  #pragma unroll
  for(int tb=0;tb<2;tb++){
    int t0 = tg*16 + tb*8;
    float acc[8];
    #pragma unroll
    for(int t=0;t<8;t++) acc[t] = b + g_xtok[(base+t0+t)*64+ch];
    #pragma unroll 8
    for(int k4=0;k4<32;k4++){
      float w0 = sW[(k4*4+0)*64+ch];
      float w1 = sW[(k4*4+1)*64+ch];
      float w2 = sW[(k4*4+2)*64+ch];
      float w3 = sW[(k4*4+3)*64+ch];
      #pragma unroll
      for(int t=0;t<8;t++){
        float4 y = *(const float4*)(sYf + (t0+t)*132 + k4*4);
        acc[t] += y.x*w0 + y.y*w1 + y.z*w2 + y.w*w3;
      }
    }
    #pragma unroll
    for(int t=0;t<8;t++) sOut[(t0+t)*65+ch] = acc[t];
  }
  __syncthreads();
  for(int i=tid;i<2048;i+=128){
    int t=i&31, c=i>>5;
    out[(bi*CC+c)*THW + pos0 + t] = sOut[t*65+c];
  }
}

// ---------------- launch ----------------------------------------------------
extern "C" void kernel_launch(void* const* d_in, const int* in_sizes, int n_in,
                              void* d_out, int out_size){
  const float* x    = (const float*)d_in[0];
  const float* ln1g = (const float*)d_in[1];
  const float* ln1b = (const float*)d_in[2];
  const float* wq   = (const float*)d_in[3];
  const float* wk   = (const float*)d_in[4];
  const float* wv   = (const float*)d_in[5];
  const float* wpr  = (const float*)d_in[6];
  const float* ln2g = (const float*)d_in[7];
  const float* ln2b = (const float*)d_in[8];
  const float* fc1w = (const float*)d_in[9];
  const float* fc1b = (const float*)d_in[10];
  const float* dww  = (const float*)d_in[11];
  const float* dwb  = (const float*)d_in[12];
  const float* fc2w = (const float*)d_in[13];
  const float* fc2b = (const float*)d_in[14];
  float* out = (float*)d_out;

  cudaFuncSetAttribute(k_attn, cudaFuncAttributeMaxDynamicSharedMemorySize, AT_SMEM);
  cudaFuncSetAttribute(k_mlp2, cudaFuncAttributeMaxDynamicSharedMemorySize, MLP2_SMEM);

  k_ln1<<<dim3(THW/32, BB), 256>>>(x, ln1g, ln1b);
  k_qkv<<<NROW/32, 128>>>(wq, wk, wv);
  k_attn<<<dim3(NP, HEADS), 256, AT_SMEM>>>();
  k_proj<<<NROW/32, 128>>>(wpr);
  k_mlp1<<<NTOK2/32, 128>>>(ln2g, ln2b, fc1w, fc1b);
  k_tr<<<dim3(THW/32, HID/32, BB), dim3(32,8)>>>();
  k_dwconv<<<BB*HID*36, 96>>>(dww, dwb);
  k_mlp2<<<NTOK2/32, 128, MLP2_SMEM>>>(fc2w, fc2b, out);
}

// round 5
// speedup vs baseline: 2.4237x; 1.0827x over previous
#include <cuda_runtime.h>
#include <math.h>
#include <stdint.h>

// ---------------- fixed problem constants -----------------------------------
#define BB 2
#define CC 64
#define TT 16
#define HH 36
#define WW 36
#define THW (TT*HH*WW)        // 20736
#define PS 8
#define NT 3
#define NH 6
#define NW 6
#define NPB (NT*NH*NW)        // 108
#define NP (BB*NPB)           // 216
#define TOKN 512
#define NROW (NP*TOKN)        // 110592
#define HEADS 2
#define HID 128
#define NTOK2 (BB*THW)        // 41472

__constant__ int   c_st_t[3] = {0,6,8};
__constant__ int   c_st_h[6] = {0,6,12,18,24,28};
// exact replication of _divisor (NOT coverage count): inverse divisors
__constant__ float c_idt[16] = {1,1,1,1,1,1,0.5f,0.5f,0.5f,0.5f,1,1,1,1,1,1};
__constant__ float c_idh[36] = {1,1,1,1,1,1, 0.5f,0.5f, 1,1,1,1, 0.5f,0.5f,
                                1,1,1,1, 0.5f,0.5f, 1,1,1,1, 0.5f,0.5f,
                                1,1, 0.5f,0.5f, 1,1,1,1,1,1};

// ---------------- scratch ---------------------------------------------------
__device__ float g_xt[NTOK2*64];      // x, token-major grid
__device__ float g_yt[NTOK2*64];      // LN1(x), token-major grid
__device__ float g_q[NROW*32];
__device__ float g_kbuf[NROW*32];
__device__ float g_v[NROW*64];
__device__ float g_attn[NROW*64];
__device__ float g_tok2[NROW*64];     // proj out + residual (per patch-token)
__device__ float g_xtok[NTOK2*64];    // pre-LN2 grid (residual for fc2)
__device__ float g_y2[NTOK2*128];     // fc1+gelu token-major
__device__ float g_y2cm[BB*HID*THW];  // channel-major (conv in)
__device__ float g_dwcm[BB*HID*THW];  // conv+gelu channel-major

extern __shared__ float dynsm[];

typedef unsigned long long u64t;

// ---- packed f32x2 helpers (Blackwell FFMA2 path; PTX-only) ------------------
__device__ __forceinline__ u64t pk2(float lo, float hi){
  u64t r; asm("mov.b64 %0,{%1,%2};" : "=l"(r) : "f"(lo), "f"(hi)); return r;
}
__device__ __forceinline__ void fma2(u64t& d, u64t a, u64t b){
  asm("fma.rn.f32x2 %0,%1,%2,%3;" : "=l"(d) : "l"(a), "l"(b), "l"(d));
}
__device__ __forceinline__ float lohiadd(u64t v){
  float lo, hi; asm("mov.b64 {%0,%1},%2;" : "=f"(lo), "=f"(hi) : "l"(v)); return lo+hi;
}
__device__ __forceinline__ uint32_t sptr(const void* p){
  return (uint32_t)__cvta_generic_to_shared(p);
}
// 16B shared load -> two packed f32x2 operands
__device__ __forceinline__ void lds128_2(u64t& a, u64t& b, uint32_t addr){
  asm("ld.shared.v2.u64 {%0,%1},[%2];" : "=l"(a), "=l"(b) : "r"(addr));
}
__device__ __forceinline__ u64t lds64(uint32_t addr){
  u64t r; asm("ld.shared.b64 %0,[%1];" : "=l"(r) : "r"(addr)); return r;
}

__device__ __forceinline__ float wred(float v){
  #pragma unroll
  for(int o=16;o;o>>=1) v += __shfl_xor_sync(0xffffffffu, v, o);
  return v;
}
__device__ __forceinline__ float wmaxr(float v){
  #pragma unroll
  for(int o=16;o;o>>=1) v = fmaxf(v, __shfl_xor_sync(0xffffffffu, v, o));
  return v;
}
__device__ __forceinline__ float gelu_exact(float x){
  return 0.5f*x*(1.0f + erff(x*0.70710678118654752f));
}
// token index (0..511) + patch coords -> spatial pos
__device__ __forceinline__ int tok2pos(int tok, int pt, int ph, int pw){
  int tt = tok>>6, hh = (tok>>3)&7, ww = tok&7;
  return (c_st_t[pt]+tt)*(HH*WW) + (c_st_h[ph]+hh)*WW + (c_st_h[pw]+ww);
}

// ---------------- K0: grid LN1 (stats are per-position, patch-independent) --
__global__ void __launch_bounds__(256) k_ln1(const float* __restrict__ x,
                    const float* __restrict__ g1, const float* __restrict__ b1){
  __shared__ float s[32][65];
  __shared__ float st[32][2];
  int bi = blockIdx.y; int pos0 = blockIdx.x*32;
  int tid = threadIdx.x;
  for(int i=tid;i<2048;i+=256){
    int ch=i>>5, pp=i&31;
    s[pp][ch] = x[(bi*64+ch)*THW + pos0+pp];
  }
  __syncthreads();
  int w = tid>>5, lane = tid&31;
  #pragma unroll
  for(int q=0;q<4;q++){
    int pp = w*4+q;
    float a = s[pp][lane], b = s[pp][lane+32];
    float su = wred(a+b);
    float sq = wred(a*a+b*b);
    if(lane==0){
      float m = su*(1.0f/64.0f);
      float var = sq*(1.0f/64.0f) - m*m;
      st[pp][0]=m; st[pp][1]=rsqrtf(var+1e-5f);
    }
  }
  __syncthreads();
  for(int i=tid;i<2048;i+=256){
    int pp=i>>6, ch=i&63;
    float v = s[pp][ch];
    int idx = (bi*THW + pos0+pp)*64 + ch;
    g_xt[idx] = v;
    g_yt[idx] = (v-st[pp][0])*st[pp][1]*g1[ch] + b1[ch];
  }
}

// ---------------- K1: fused QKV GEMM (gather + f32x2) -----------------------
__global__ void __launch_bounds__(128) k_qkv(const float* __restrict__ wq,
                      const float* __restrict__ wk,
                      const float* __restrict__ wv){
  __shared__ float sy[32*64];
  int tid = threadIdx.x;
  int base = blockIdx.x*32;
  int p = base>>9, tok0 = base&511;
  int bi = p/NPB; int r = p%NPB;
  int pt=r/36, ph=(r%36)/6, pw=r%6;
  for(int i=tid;i<2048;i+=128){
    int t=i>>6, ch=i&63;
    int pos = tok2pos(tok0+t, pt, ph, pw);
    sy[t*64+ch] = g_yt[(bi*THW+pos)*64+ch];
  }
  int j = tid;
  u64t wp[32];
  if(j<32){
    #pragma unroll
    for(int k2=0;k2<32;k2++) wp[k2]=pk2(wq[(2*k2)*32+j], wq[(2*k2+1)*32+j]);
  } else if(j<64){
    #pragma unroll
    for(int k2=0;k2<32;k2++) wp[k2]=pk2(wk[(2*k2)*32+(j-32)], wk[(2*k2+1)*32+(j-32)]);
  } else {
    #pragma unroll
    for(int k2=0;k2<32;k2++) wp[k2]=pk2(wv[(2*k2)*64+(j-64)], wv[(2*k2+1)*64+(j-64)]);
  }
  __syncthreads();
  uint32_t syb = sptr(sy);
  for(int tb=0;tb<4;tb++){
    u64t acc[8];
    #pragma unroll
    for(int t=0;t<8;t++) acc[t]=0ull;
    #pragma unroll
    for(int k4=0;k4<16;k4++){
      u64t w0=wp[2*k4], w1=wp[2*k4+1];
      #pragma unroll
      for(int t=0;t<8;t++){
        u64t ya, yb;
        lds128_2(ya, yb, syb + ((tb*8+t)*64 + k4*4)*4);
        fma2(acc[t], ya, w0);
        fma2(acc[t], yb, w1);
      }
    }
    #pragma unroll
    for(int t=0;t<8;t++){
      float a = lohiadd(acc[t]);
      int row = base + tb*8 + t;
      if(j<32)       g_q[row*32+j] = a;
      else if(j<64)  g_kbuf[row*32+(j-32)] = a;
      else           g_v[row*64+(j-64)] = a;
    }
  }
}

// ---------------- K2: attention per (patch, head), f32x2 --------------------
// 256 threads (8 warps), 4 queries per warp-pass, V transposed in smem.
#define AT_SMEM ((512*16 + 512*20 + 32*516 + 8*4*512)*4)
__global__ void __launch_bounds__(256,1) k_attn(){
  int p = blockIdx.x, hd = blockIdx.y;
  float* sQ  = dynsm;               // 512*16
  float* sK  = sQ + 512*16;         // 512*20 (padded)
  float* sVT = sK + 512*20;         // 32 rows * 516 (padded): VT[d][j]
  float* sS  = sVT + 32*516;        // 8 warps * 4q * 512
  int tid = threadIdx.x;
  const float* qg = g_q   + p*512*32 + hd*16;
  const float* kg = g_kbuf+ p*512*32 + hd*16;
  const float* vg = g_v   + p*512*64 + hd*32;
  for(int i=tid;i<512*16;i+=256){ int j=i>>4, d=i&15; sQ[j*16+d]=qg[j*32+d]; }
  for(int i=tid;i<512*16;i+=256){ int j=i>>4, d=i&15; sK[j*20+d]=kg[j*32+d]; }
  for(int i=tid;i<512*32;i+=256){ int j=i>>5, d=i&31; sVT[d*516+j]=vg[j*64+d]; }
  __syncthreads();
  int w = tid>>5, lane = tid&31;
  float* sSw = sS + w*2048;
  uint32_t sKb = sptr(sK), sSb = sptr(sSw), sVb = sptr(sVT + lane*516);
  for(int it=0;it<16;it++){
    int q0 = it*32 + w*4;
    u64t qp[4][8];
    #pragma unroll
    for(int qq=0;qq<4;qq++){
      uint32_t qa = sptr(sQ + (q0+qq)*16);
      lds128_2(qp[qq][0], qp[qq][1], qa);
      lds128_2(qp[qq][2], qp[qq][3], qa+16);
      lds128_2(qp[qq][4], qp[qq][5], qa+32);
      lds128_2(qp[qq][6], qp[qq][7], qa+48);
    }
    float mx[4] = {-1e30f,-1e30f,-1e30f,-1e30f};
    #pragma unroll 2
    for(int i=0;i<16;i++){
      int j = lane + 32*i;
      u64t kr[8];
      uint32_t ka = sKb + j*80;
      lds128_2(kr[0], kr[1], ka);
      lds128_2(kr[2], kr[3], ka+16);
      lds128_2(kr[4], kr[5], ka+32);
      lds128_2(kr[6], kr[7], ka+48);
      #pragma unroll
      for(int qq=0;qq<4;qq++){
        u64t a2 = 0ull, b2 = 0ull;
        #pragma unroll
        for(int d2=0;d2<4;d2++){
          fma2(a2, qp[qq][2*d2],   kr[2*d2]);
          fma2(b2, qp[qq][2*d2+1], kr[2*d2+1]);
        }
        float s = (lohiadd(a2) + lohiadd(b2)) * 0.25f;
        sSw[qq*512+j] = s;
        mx[qq] = fmaxf(mx[qq], s);
      }
    }
    #pragma unroll
    for(int qq=0;qq<4;qq++) mx[qq] = wmaxr(mx[qq]);
    float sum[4] = {0.f,0.f,0.f,0.f};
    #pragma unroll 2
    for(int i=0;i<16;i++){
      int j = lane + 32*i;
      #pragma unroll
      for(int qq=0;qq<4;qq++){
        float e = __expf(sSw[qq*512+j] - mx[qq]);
        sSw[qq*512+j] = e;
        sum[qq] += e;
      }
    }
    float inv[4];
    #pragma unroll
    for(int qq=0;qq<4;qq++) inv[qq] = 1.0f/wred(sum[qq]);
    __syncwarp();
    u64t oa[4] = {0,0,0,0}, ob[4] = {0,0,0,0};
    #pragma unroll 4
    for(int j0=0;j0<512;j0+=4){
      u64t va, vb;
      lds128_2(va, vb, sVb + j0*4);
      #pragma unroll
      for(int qq=0;qq<4;qq++){
        u64t pa, pb;
        lds128_2(pa, pb, sSb + (qq*512+j0)*4);
        fma2(oa[qq], pa, va);
        fma2(ob[qq], pb, vb);
      }
    }
    float* og = g_attn + (p*512+q0)*64 + hd*32 + lane;
    #pragma unroll
    for(int qq=0;qq<4;qq++) og[qq*64] = (lohiadd(oa[qq]) + lohiadd(ob[qq]))*inv[qq];
    __syncwarp();
  }
}

// ---------------- K3: proj + residual (f32x2) -------------------------------
__global__ void __launch_bounds__(128) k_proj(const float* __restrict__ wproj){
  __shared__ float sA[32*64];
  int tid = threadIdx.x;
  int base = blockIdx.x*32;
  int p = base>>9, tok0 = base&511;
  int bi = p/NPB; int r = p%NPB;
  int pt=r/36, ph=(r%36)/6, pw=r%6;
  int ch = tid&63, tg = tid>>6;
  for(int i=tid;i<2048;i+=128) sA[i] = g_attn[base*64 + i];
  u64t wp[32];
  #pragma unroll
  for(int k2=0;k2<32;k2++) wp[k2] = pk2(wproj[(2*k2)*64+ch], wproj[(2*k2+1)*64+ch]);
  __syncthreads();
  uint32_t sAb = sptr(sA);
  for(int tb=0;tb<2;tb++){
    int t0 = tg*16 + tb*8;
    u64t acc[8];
    #pragma unroll
    for(int t=0;t<8;t++){
      int pos = tok2pos(tok0+t0+t, pt, ph, pw);
      acc[t] = pk2(g_xt[(bi*THW+pos)*64+ch], 0.f);
    }
    #pragma unroll
    for(int k4=0;k4<16;k4++){
      u64t w0=wp[2*k4], w1=wp[2*k4+1];
      #pragma unroll
      for(int t=0;t<8;t++){
        u64t ya, yb;
        lds128_2(ya, yb, sAb + ((t0+t)*64 + k4*4)*4);
        fma2(acc[t], ya, w0);
        fma2(acc[t], yb, w1);
      }
    }
    #pragma unroll
    for(int t=0;t<8;t++) g_tok2[(base+t0+t)*64+ch] = lohiadd(acc[t]);
  }
}

// ---------------- K4: gather-reverse + div + LN2 + fc1 + gelu (f32x2) -------
__global__ void __launch_bounds__(128) k_mlp1(const float* __restrict__ g2, const float* __restrict__ b2,
                       const float* __restrict__ fc1w, const float* __restrict__ fc1b){
  __shared__ float sX[32*67];
  __shared__ float sYn[32*68];
  __shared__ float sStat[32][2];
  int base = blockIdx.x*32;
  int bi = base/THW;
  int tid = threadIdx.x;
  int ch = tid&63, half = tid>>6;
  float xvr[16];
  for(int k=0;k<16;k++){
    int t = half + 2*k;
    int token = base + t;
    int pos = token % THW;
    int tt_ = pos/(HH*WW), hh_=(pos/WW)%HH, ww_=pos%WW;
    float acc = 0.f;
    #pragma unroll
    for(int pt=0;pt<3;pt++){
      int dt_ = tt_-c_st_t[pt]; if(dt_<0||dt_>=8) continue;
      #pragma unroll
      for(int ph=0;ph<6;ph++){
        int dh_ = hh_-c_st_h[ph]; if(dh_<0||dh_>=8) continue;
        #pragma unroll
        for(int pw=0;pw<6;pw++){
          int dw_ = ww_-c_st_h[pw]; if(dw_<0||dw_>=8) continue;
          int pp = bi*NPB + pt*36 + ph*6 + pw;
          int tk = dt_*64 + dh_*8 + dw_;
          acc += g_tok2[(pp*512+tk)*64 + ch];
        }
      }
    }
    float xv = acc * c_idt[tt_]*c_idh[hh_]*c_idh[ww_];
    xvr[k] = xv;
    sX[t*67+ch] = xv;
    g_xtok[token*64+ch] = xv;
  }
  __syncthreads();
  if(tid<32){
    float s=0.f, s2=0.f;
    #pragma unroll 8
    for(int k=0;k<64;k++){ float v=sX[tid*67+k]; s+=v; s2+=v*v; }
    float m=s*(1.0f/64.0f), var=s2*(1.0f/64.0f)-m*m;
    sStat[tid][0]=m; sStat[tid][1]=rsqrtf(var+1e-5f);
  }
  __syncthreads();
  float gg=g2[ch], bb=b2[ch];
  for(int k=0;k<16;k++){
    int t = half + 2*k;
    sYn[t*68+ch] = (xvr[k]-sStat[t][0])*sStat[t][1]*gg + bb;
  }
  __syncthreads();
  int j = tid;
  u64t wp[32];
  #pragma unroll
  for(int k2=0;k2<32;k2++) wp[k2] = pk2(fc1w[(2*k2)*128+j], fc1w[(2*k2+1)*128+j]);
  float bj = fc1b[j];
  uint32_t sYb = sptr(sYn);
  for(int tb=0;tb<4;tb++){
    u64t acc[8];
    #pragma unroll
    for(int t=0;t<8;t++) acc[t] = pk2(bj, 0.f);
    #pragma unroll
    for(int k4=0;k4<16;k4++){
      u64t w0=wp[2*k4], w1=wp[2*k4+1];
      #pragma unroll
      for(int t=0;t<8;t++){
        u64t ya, yb;
        lds128_2(ya, yb, sYb + ((tb*8+t)*68 + k4*4)*4);
        fma2(acc[t], ya, w0);
        fma2(acc[t], yb, w1);
      }
    }
    #pragma unroll
    for(int t=0;t<8;t++) g_y2[(base+tb*8+t)*128+j] = gelu_exact(lohiadd(acc[t]));
  }
}

// ---------------- K5: transpose token-major -> channel-major ----------------
__global__ void k_tr(){
  __shared__ float tile[32][33];
  int bi = blockIdx.z; int c0 = blockIdx.y*32; int p0 = blockIdx.x*32;
  int tx = threadIdx.x, ty = threadIdx.y;   // 32 x 8
  for(int yy=ty;yy<32;yy+=8)
    tile[yy][tx] = g_y2[(bi*THW + p0+yy)*128 + c0+tx];
  __syncthreads();
  for(int yy=ty;yy<32;yy+=8)
    g_y2cm[(bi*HID + c0+yy)*THW + p0+tx] = tile[tx][yy];
}

// ---------------- K6: depthwise 5^3 conv + bias + gelu ----------------------
__global__ void __launch_bounds__(96) k_dwconv(const float* __restrict__ dww, const float* __restrict__ dwb){
  __shared__ float si[20*10*10];
  __shared__ float swt[125];
  int blk = blockIdx.x;
  int tile = blk%36; int cb = blk/36; int ch = cb%HID; int bi = cb/HID;
  int th = tile/6, tw = tile%6;
  int tid = threadIdx.x;
  const float* src = g_y2cm + (bi*HID+ch)*THW;

  for(int i=tid;i<125;i+=96) swt[i] = dww[ch*125+i];
  for(int i=tid;i<2000;i+=96){
    int it = i/100, rm = i%100, ih = rm/10, iw = rm%10;
    int gt = it-2, gh = th*6+ih-2, gw = tw*6+iw-2;
    float v = 0.f;
    if(gt>=0 && gt<TT && gh>=0 && gh<HH && gw>=0 && gw<WW)
      v = src[gt*(HH*WW) + gh*WW + gw];
    si[i] = v;
  }
  __syncthreads();
  int ot = tid/6, oh = tid%6;
  float acc[6] = {0.f,0.f,0.f,0.f,0.f,0.f};
  #pragma unroll
  for(int dt=0;dt<5;dt++){
    #pragma unroll
    for(int dh=0;dh<5;dh++){
      const float* row = si + (ot+dt)*100 + (oh+dh)*10;
      float rr[10];
      #pragma unroll
      for(int i=0;i<10;i++) rr[i]=row[i];
      const float* wp = swt + dt*25 + dh*5;
      float w0=wp[0],w1=wp[1],w2=wp[2],w3=wp[3],w4=wp[4];
      #pragma unroll
      for(int ow=0;ow<6;ow++)
        acc[ow] += rr[ow]*w0 + rr[ow+1]*w1 + rr[ow+2]*w2 + rr[ow+3]*w3 + rr[ow+4]*w4;
    }
  }
  float bsv = dwb[ch];
  float* dst = g_dwcm + (bi*HID+ch)*THW + ot*(HH*WW) + (th*6+oh)*WW + tw*6;
  #pragma unroll
  for(int ow=0;ow<6;ow++) dst[ow] = gelu_exact(acc[ow] + bsv);
}

// ---------------- K7: fc2 + residual + transposed output (f32x2) ------------
// sW2: pair-interleaved weights: sW2[k2*128 + ch*2 + {0,1}] = w[2k2][ch], w[2k2+1][ch]
#define MLP2_SMEM ((32*132 + 128*64 + 32*65)*4)
__global__ void __launch_bounds__(128) k_mlp2(const float* __restrict__ fc2w, const float* __restrict__ fc2b,
                       float* __restrict__ out){
  float* sYf  = dynsm;               // 32*132
  float* sW2  = sYf + 32*132;        // 128*64 (pair-interleaved)
  float* sOut = sW2 + 128*64;        // 32*65
  int base = blockIdx.x*32;
  int bi = base/THW; int pos0 = base%THW;
  int tid = threadIdx.x;
  for(int i=tid;i<8192;i+=128){
    int k=i>>6, c=i&63;
    sW2[(k>>1)*128 + c*2 + (k&1)] = fc2w[i];
  }
  for(int i=tid;i<4096;i+=128){ int t=i>>7, j=i&127; sYf[t*132+j] = g_y2[(base+t)*128+j]; }
  __syncthreads();
  for(int i=tid;i<4096;i+=128){ int t=i&31, j=i>>5; sYf[t*132+j] += g_dwcm[(bi*HID+j)*THW + pos0 + t]; }
  __syncthreads();
  int ch = tid&63, tg = tid>>6;
  float b = fc2b[ch];
  uint32_t sYb = sptr(sYf);
  uint32_t sWb = sptr(sW2) + ch*8;
  #pragma unroll
  for(int tb=0;tb<2;tb++){
    int t0 = tg*16 + tb*8;
    u64t acc[8];
    #pragma unroll
    for(int t=0;t<8;t++) acc[t] = pk2(b + g_xtok[(base+t0+t)*64+ch], 0.f);
    #pragma unroll 8
    for(int k4=0;k4<32;k4++){
      u64t w0 = lds64(sWb + (2*k4)*512);
      u64t w1 = lds64(sWb + (2*k4+1)*512);
      #pragma unroll
      for(int t=0;t<8;t++){
        u64t ya, yb;
        lds128_2(ya, yb, sYb + ((t0+t)*132 + k4*4)*4);
        fma2(acc[t], ya, w0);
        fma2(acc[t], yb, w1);
      }
    }
    #pragma unroll
    for(int t=0;t<8;t++) sOut[(t0+t)*65+ch] = lohiadd(acc[t]);
  }
  __syncthreads();
  for(int i=tid;i<2048;i+=128){
    int t=i&31, c=i>>5;
    out[(bi*CC+c)*THW + pos0 + t] = sOut[t*65+c];
  }
}

// ---------------- launch ----------------------------------------------------
extern "C" void kernel_launch(void* const* d_in, const int* in_sizes, int n_in,
                              void* d_out, int out_size){
  const float* x    = (const float*)d_in[0];
  const float* ln1g = (const float*)d_in[1];
  const float* ln1b = (const float*)d_in[2];
  const float* wq   = (const float*)d_in[3];
  const float* wk   = (const float*)d_in[4];
  const float* wv   = (const float*)d_in[5];
  const float* wpr  = (const float*)d_in[6];
  const float* ln2g = (const float*)d_in[7];
  const float* ln2b = (const float*)d_in[8];
  const float* fc1w = (const float*)d_in[9];
  const float* fc1b = (const float*)d_in[10];
  const float* dww  = (const float*)d_in[11];
  const float* dwb  = (const float*)d_in[12];
  const float* fc2w = (const float*)d_in[13];
  const float* fc2b = (const float*)d_in[14];
  float* out = (float*)d_out;

  cudaFuncSetAttribute(k_attn, cudaFuncAttributeMaxDynamicSharedMemorySize, AT_SMEM);
  cudaFuncSetAttribute(k_mlp2, cudaFuncAttributeMaxDynamicSharedMemorySize, MLP2_SMEM);

  k_ln1<<<dim3(THW/32, BB), 256>>>(x, ln1g, ln1b);
  k_qkv<<<NROW/32, 128>>>(wq, wk, wv);
  k_attn<<<dim3(NP, HEADS), 256, AT_SMEM>>>();
  k_proj<<<NROW/32, 128>>>(wpr);
  k_mlp1<<<NTOK2/32, 128>>>(ln2g, ln2b, fc1w, fc1b);
  k_tr<<<dim3(THW/32, HID/32, BB), dim3(32,8)>>>();
  k_dwconv<<<BB*HID*36, 96>>>(dww, dwb);
  k_mlp2<<<NTOK2/32, 128, MLP2_SMEM>>>(fc2w, fc2b, out);
}

// round 6
// speedup vs baseline: 3.0475x; 1.2574x over previous
#include <cuda_runtime.h>
#include <cuda_bf16.h>
#include <math.h>
#include <stdint.h>

// ---------------- fixed problem constants -----------------------------------
#define BB 2
#define CC 64
#define TT 16
#define HH 36
#define WW 36
#define THW (TT*HH*WW)        // 20736
#define PS 8
#define NT 3
#define NH 6
#define NW 6
#define NPB (NT*NH*NW)        // 108
#define NP (BB*NPB)           // 216
#define TOKN 512
#define NROW (NP*TOKN)        // 110592
#define HEADS 2
#define HID 128
#define NTOK2 (BB*THW)        // 41472

__constant__ int   c_st_t[3] = {0,6,8};
__constant__ int   c_st_h[6] = {0,6,12,18,24,28};
// exact replication of _divisor (NOT coverage count): inverse divisors
__constant__ float c_idt[16] = {1,1,1,1,1,1,0.5f,0.5f,0.5f,0.5f,1,1,1,1,1,1};
__constant__ float c_idh[36] = {1,1,1,1,1,1, 0.5f,0.5f, 1,1,1,1, 0.5f,0.5f,
                                1,1,1,1, 0.5f,0.5f, 1,1,1,1, 0.5f,0.5f,
                                1,1, 0.5f,0.5f, 1,1,1,1,1,1};

// ---------------- scratch ---------------------------------------------------
__device__ float g_xt[NTOK2*64];      // x, token-major grid
__device__ float g_yt[NTOK2*64];      // LN1(x), token-major grid
__device__ __nv_bfloat16 g_qh[NROW*32];
__device__ __nv_bfloat16 g_kh[NROW*32];
__device__ __nv_bfloat16 g_vh[NROW*64];
__device__ float g_attn[NROW*64];
__device__ float g_tok2[NROW*64];     // proj out + residual (per patch-token)
__device__ float g_xtok[NTOK2*64];    // pre-LN2 grid (residual for fc2)
__device__ float g_y2[NTOK2*128];     // fc1+gelu token-major
__device__ float g_y2cm[BB*HID*THW];  // channel-major (conv in)
__device__ float g_dwcm[BB*HID*THW];  // conv+gelu channel-major

extern __shared__ float dynsm[];

typedef unsigned long long u64t;

// ---- packed f32x2 helpers ---------------------------------------------------
__device__ __forceinline__ u64t pk2(float lo, float hi){
  u64t r; asm("mov.b64 %0,{%1,%2};" : "=l"(r) : "f"(lo), "f"(hi)); return r;
}
__device__ __forceinline__ void fma2(u64t& d, u64t a, u64t b){
  asm("fma.rn.f32x2 %0,%1,%2,%3;" : "=l"(d) : "l"(a), "l"(b), "l"(d));
}
__device__ __forceinline__ float lohiadd(u64t v){
  float lo, hi; asm("mov.b64 {%0,%1},%2;" : "=f"(lo), "=f"(hi) : "l"(v)); return lo+hi;
}
__device__ __forceinline__ uint32_t sptr(const void* p){
  return (uint32_t)__cvta_generic_to_shared(p);
}
__device__ __forceinline__ void lds128_2(u64t& a, u64t& b, uint32_t addr){
  asm("ld.shared.v2.u64 {%0,%1},[%2];" : "=l"(a), "=l"(b) : "r"(addr));
}
__device__ __forceinline__ u64t lds64(uint32_t addr){
  u64t r; asm("ld.shared.b64 %0,[%1];" : "=l"(r) : "r"(addr)); return r;
}

// ---- mma helpers ------------------------------------------------------------
__device__ __forceinline__ void ldm_x4(uint32_t& r0, uint32_t& r1, uint32_t& r2, uint32_t& r3, uint32_t addr){
  asm volatile("ldmatrix.sync.aligned.m8n8.x4.shared.b16 {%0,%1,%2,%3},[%4];"
    : "=r"(r0),"=r"(r1),"=r"(r2),"=r"(r3) : "r"(addr));
}
__device__ __forceinline__ void ldm_x2t(uint32_t& r0, uint32_t& r1, uint32_t addr){
  asm volatile("ldmatrix.sync.aligned.m8n8.x2.trans.shared.b16 {%0,%1},[%2];"
    : "=r"(r0),"=r"(r1) : "r"(addr));
}
__device__ __forceinline__ void mma_bf16(float& c0, float& c1, float& c2, float& c3,
    uint32_t a0, uint32_t a1, uint32_t a2, uint32_t a3, uint32_t b0, uint32_t b1){
  asm volatile("mma.sync.aligned.m16n8k16.row.col.f32.bf16.bf16.f32 "
    "{%0,%1,%2,%3},{%4,%5,%6,%7},{%8,%9},{%0,%1,%2,%3};"
    : "+f"(c0),"+f"(c1),"+f"(c2),"+f"(c3)
    : "r"(a0),"r"(a1),"r"(a2),"r"(a3),"r"(b0),"r"(b1));
}

__device__ __forceinline__ float wred(float v){
  #pragma unroll
  for(int o=16;o;o>>=1) v += __shfl_xor_sync(0xffffffffu, v, o);
  return v;
}
__device__ __forceinline__ float wmaxr(float v){
  #pragma unroll
  for(int o=16;o;o>>=1) v = fmaxf(v, __shfl_xor_sync(0xffffffffu, v, o));
  return v;
}
__device__ __forceinline__ float gelu_exact(float x){
  return 0.5f*x*(1.0f + erff(x*0.70710678118654752f));
}
__device__ __forceinline__ int tok2pos(int tok, int pt, int ph, int pw){
  int tt = tok>>6, hh = (tok>>3)&7, ww = tok&7;
  return (c_st_t[pt]+tt)*(HH*WW) + (c_st_h[ph]+hh)*WW + (c_st_h[pw]+ww);
}

// ---------------- K0: grid LN1 ----------------------------------------------
__global__ void __launch_bounds__(256) k_ln1(const float* __restrict__ x,
                    const float* __restrict__ g1, const float* __restrict__ b1){
  __shared__ float s[32][65];
  __shared__ float st[32][2];
  int bi = blockIdx.y; int pos0 = blockIdx.x*32;
  int tid = threadIdx.x;
  for(int i=tid;i<2048;i+=256){
    int ch=i>>5, pp=i&31;
    s[pp][ch] = x[(bi*64+ch)*THW + pos0+pp];
  }
  __syncthreads();
  int w = tid>>5, lane = tid&31;
  #pragma unroll
  for(int q=0;q<4;q++){
    int pp = w*4+q;
    float a = s[pp][lane], b = s[pp][lane+32];
    float su = wred(a+b);
    float sq = wred(a*a+b*b);
    if(lane==0){
      float m = su*(1.0f/64.0f);
      float var = sq*(1.0f/64.0f) - m*m;
      st[pp][0]=m; st[pp][1]=rsqrtf(var+1e-5f);
    }
  }
  __syncthreads();
  for(int i=tid;i<2048;i+=256){
    int pp=i>>6, ch=i&63;
    float v = s[pp][ch];
    int idx = (bi*THW + pos0+pp)*64 + ch;
    g_xt[idx] = v;
    g_yt[idx] = (v-st[pp][0])*st[pp][1]*g1[ch] + b1[ch];
  }
}

// ---------------- K1: fused QKV GEMM -> bf16 outputs ------------------------
__global__ void __launch_bounds__(128) k_qkv(const float* __restrict__ wq,
                      const float* __restrict__ wk,
                      const float* __restrict__ wv){
  __shared__ float sy[32*64];
  int tid = threadIdx.x;
  int base = blockIdx.x*32;
  int p = base>>9, tok0 = base&511;
  int bi = p/NPB; int r = p%NPB;
  int pt=r/36, ph=(r%36)/6, pw=r%6;
  for(int i=tid;i<2048;i+=128){
    int t=i>>6, ch=i&63;
    int pos = tok2pos(tok0+t, pt, ph, pw);
    sy[t*64+ch] = g_yt[(bi*THW+pos)*64+ch];
  }
  int j = tid;
  u64t wp[32];
  if(j<32){
    #pragma unroll
    for(int k2=0;k2<32;k2++) wp[k2]=pk2(wq[(2*k2)*32+j], wq[(2*k2+1)*32+j]);
  } else if(j<64){
    #pragma unroll
    for(int k2=0;k2<32;k2++) wp[k2]=pk2(wk[(2*k2)*32+(j-32)], wk[(2*k2+1)*32+(j-32)]);
  } else {
    #pragma unroll
    for(int k2=0;k2<32;k2++) wp[k2]=pk2(wv[(2*k2)*64+(j-64)], wv[(2*k2+1)*64+(j-64)]);
  }
  __syncthreads();
  uint32_t syb = sptr(sy);
  for(int tb=0;tb<4;tb++){
    u64t acc[8];
    #pragma unroll
    for(int t=0;t<8;t++) acc[t]=0ull;
    #pragma unroll
    for(int k4=0;k4<16;k4++){
      u64t w0=wp[2*k4], w1=wp[2*k4+1];
      #pragma unroll
      for(int t=0;t<8;t++){
        u64t ya, yb;
        lds128_2(ya, yb, syb + ((tb*8+t)*64 + k4*4)*4);
        fma2(acc[t], ya, w0);
        fma2(acc[t], yb, w1);
      }
    }
    #pragma unroll
    for(int t=0;t<8;t++){
      float a = lohiadd(acc[t]);
      int row = base + tb*8 + t;
      if(j<32)       g_qh[row*32+j] = __float2bfloat16(a);
      else if(j<64)  g_kh[row*32+(j-32)] = __float2bfloat16(a);
      else           g_vh[row*64+(j-64)] = __float2bfloat16(a);
    }
  }
}

// ---------------- K2: attention via mma.sync bf16 ---------------------------
// grid (NP, HEADS, 8): 64 queries/block, 256 threads (8 warps).
// smem: S fp32 [64][524] (reused as P bf16 rows), K bf16 [512] pitch48B,
//       V bf16 [512] pitch80B, Q bf16 [64] pitch48B, inv[64].
#define S_PITCH_W 524
#define S_PITCH_B 2096
#define SK_OFF 134144
#define SV_OFF 158720
#define SQ_OFF 199680
#define SINV_OFF 202752
#define AT_SMEM 203008
__global__ void __launch_bounds__(256,1) k_attn(){
  char* sm = (char*)dynsm;
  int p = blockIdx.x, hd = blockIdx.y;
  int q0 = blockIdx.z*64;
  int tid = threadIdx.x;
  float* sS = (float*)sm;
  float* sInv = (float*)(sm + SINV_OFF);

  // loads (uint32 = bf16 pair granularity)
  {
    const uint32_t* qsrc = (const uint32_t*)g_qh + (size_t)(p*512+q0)*16 + hd*8;
    uint32_t* dq = (uint32_t*)(sm + SQ_OFF);
    for(int i=tid;i<64*8;i+=256){ int r=i>>3, dp=i&7; dq[r*12+dp] = qsrc[r*16+dp]; }
    const uint32_t* ksrc = (const uint32_t*)g_kh + (size_t)p*512*16 + hd*8;
    uint32_t* dk = (uint32_t*)(sm + SK_OFF);
    for(int i=tid;i<512*8;i+=256){ int r=i>>3, dp=i&7; dk[r*12+dp] = ksrc[r*16+dp]; }
    const uint32_t* vsrc = (const uint32_t*)g_vh + (size_t)p*512*32 + hd*16;
    uint32_t* dv = (uint32_t*)(sm + SV_OFF);
    for(int i=tid;i<512*16;i+=256){ int r=i>>4, dp=i&15; dv[r*20+dp] = vsrc[r*32+dp]; }
  }
  __syncthreads();

  int w = tid>>5, lane = tid&31;

  // ---- phase 1: S = Q @ K^T (raw scores, scale folded into softmax) ----
  {
    uint32_t sQb = sptr(sm + SQ_OFF);
    uint32_t aQ[4][4];
    #pragma unroll
    for(int qt=0;qt<4;qt++){
      int row = qt*16 + (lane&7) + ((lane&8)?8:0);
      uint32_t addr = sQb + row*48 + ((lane&16)?16:0);
      ldm_x4(aQ[qt][0],aQ[qt][1],aQ[qt][2],aQ[qt][3], addr);
    }
    uint32_t sKb = sptr(sm + SK_OFF);
    for(int kt=0;kt<8;kt++){
      int j0 = w*64 + kt*8;
      uint32_t baddr = sKb + (j0 + (lane&7))*48 + ((lane&8)?16:0);
      uint32_t b0,b1; ldm_x2t(b0,b1, baddr);
      #pragma unroll
      for(int qt=0;qt<4;qt++){
        float c0=0.f,c1=0.f,c2=0.f,c3=0.f;
        mma_bf16(c0,c1,c2,c3, aQ[qt][0],aQ[qt][1],aQ[qt][2],aQ[qt][3], b0,b1);
        int r = qt*16 + (lane>>2);
        int c = j0 + (lane&3)*2;
        *(float2*)(sS + r*S_PITCH_W + c) = make_float2(c0,c1);
        *(float2*)(sS + (r+8)*S_PITCH_W + c) = make_float2(c2,c3);
      }
    }
  }
  __syncthreads();

  // ---- phase 2: softmax; write unnormalized P (bf16) in place ----
  for(int rr=0;rr<8;rr++){
    int r = w*8 + rr;
    float* Srow = sS + r*S_PITCH_W;
    float m = -1e30f;
    #pragma unroll
    for(int jj=0;jj<16;jj++) m = fmaxf(m, Srow[lane + 32*jj]);
    m = wmaxr(m);
    float ev[16]; float sum = 0.f;
    #pragma unroll
    for(int jj=0;jj<16;jj++){
      ev[jj] = __expf(0.25f*(Srow[lane + 32*jj] - m));
      sum += ev[jj];
    }
    __syncwarp();   // all reads of this row done before bf16 overwrite
    __nv_bfloat16* Prow = (__nv_bfloat16*)(sm + r*S_PITCH_B);
    #pragma unroll
    for(int jj=0;jj<16;jj++) Prow[lane + 32*jj] = __float2bfloat16(ev[jj]);
    sum = wred(sum);
    if(lane==0) sInv[r] = 1.0f/sum;
  }
  __syncthreads();

  // ---- phase 3: O = P @ V ----
  {
    uint32_t sVb = sptr(sm + SV_OFF);
    uint32_t sPb = sptr(sm);
    #pragma unroll
    for(int t2=0;t2<2;t2++){
      int tt = w + t2*8;
      int qt = tt>>2, nt = tt&3;
      float c0=0.f,c1=0.f,c2=0.f,c3=0.f;
      int arow = qt*16 + (lane&7) + ((lane&8)?8:0);
      uint32_t aBase = sPb + arow*S_PITCH_B + ((lane&16)?16:0);
      uint32_t bBase = sVb + ((lane&7) + ((lane&8)?8:0))*80 + nt*16;
      #pragma unroll 4
      for(int ks=0;ks<32;ks++){
        uint32_t a0,a1,a2,a3; ldm_x4(a0,a1,a2,a3, aBase + ks*32);
        uint32_t b0,b1; ldm_x2t(b0,b1, bBase + ks*16*80);
        mma_bf16(c0,c1,c2,c3, a0,a1,a2,a3, b0,b1);
      }
      int r = qt*16 + (lane>>2);
      int c = nt*8 + (lane&3)*2;
      float i0 = sInv[r], i1 = sInv[r+8];
      float* og = g_attn + (size_t)(p*512 + q0 + r)*64 + hd*32 + c;
      og[0] = c0*i0; og[1] = c1*i0;
      og[8*64+0] = c2*i1; og[8*64+1] = c3*i1;
    }
  }
}

// ---------------- K3: proj + residual (f32x2) -------------------------------
__global__ void __launch_bounds__(128) k_proj(const float* __restrict__ wproj){
  __shared__ float sA[32*64];
  int tid = threadIdx.x;
  int base = blockIdx.x*32;
  int p = base>>9, tok0 = base&511;
  int bi = p/NPB; int r = p%NPB;
  int pt=r/36, ph=(r%36)/6, pw=r%6;
  int ch = tid&63, tg = tid>>6;
  for(int i=tid;i<2048;i+=128) sA[i] = g_attn[base*64 + i];
  u64t wp[32];
  #pragma unroll
  for(int k2=0;k2<32;k2++) wp[k2] = pk2(wproj[(2*k2)*64+ch], wproj[(2*k2+1)*64+ch]);
  __syncthreads();
  uint32_t sAb = sptr(sA);
  for(int tb=0;tb<2;tb++){
    int t0 = tg*16 + tb*8;
    u64t acc[8];
    #pragma unroll
    for(int t=0;t<8;t++){
      int pos = tok2pos(tok0+t0+t, pt, ph, pw);
      acc[t] = pk2(g_xt[(bi*THW+pos)*64+ch], 0.f);
    }
    #pragma unroll
    for(int k4=0;k4<16;k4++){
      u64t w0=wp[2*k4], w1=wp[2*k4+1];
      #pragma unroll
      for(int t=0;t<8;t++){
        u64t ya, yb;
        lds128_2(ya, yb, sAb + ((t0+t)*64 + k4*4)*4);
        fma2(acc[t], ya, w0);
        fma2(acc[t], yb, w1);
      }
    }
    #pragma unroll
    for(int t=0;t<8;t++) g_tok2[(base+t0+t)*64+ch] = lohiadd(acc[t]);
  }
}

// ---------------- K4: gather-reverse + div + LN2 + fc1 + gelu (f32x2) -------
__global__ void __launch_bounds__(128) k_mlp1(const float* __restrict__ g2, const float* __restrict__ b2,
                       const float* __restrict__ fc1w, const float* __restrict__ fc1b){
  __shared__ float sX[32*67];
  __shared__ float sYn[32*68];
  __shared__ float sStat[32][2];
  int base = blockIdx.x*32;
  int bi = base/THW;
  int tid = threadIdx.x;
  int ch = tid&63, half = tid>>6;
  float xvr[16];
  for(int k=0;k<16;k++){
    int t = half + 2*k;
    int token = base + t;
    int pos = token % THW;
    int tt_ = pos/(HH*WW), hh_=(pos/WW)%HH, ww_=pos%WW;
    float acc = 0.f;
    #pragma unroll
    for(int pt=0;pt<3;pt++){
      int dt_ = tt_-c_st_t[pt]; if(dt_<0||dt_>=8) continue;
      #pragma unroll
      for(int ph=0;ph<6;ph++){
        int dh_ = hh_-c_st_h[ph]; if(dh_<0||dh_>=8) continue;
        #pragma unroll
        for(int pw=0;pw<6;pw++){
          int dw_ = ww_-c_st_h[pw]; if(dw_<0||dw_>=8) continue;
          int pp = bi*NPB + pt*36 + ph*6 + pw;
          int tk = dt_*64 + dh_*8 + dw_;
          acc += g_tok2[(pp*512+tk)*64 + ch];
        }
      }
    }
    float xv = acc * c_idt[tt_]*c_idh[hh_]*c_idh[ww_];
    xvr[k] = xv;
    sX[t*67+ch] = xv;
    g_xtok[token*64+ch] = xv;
  }
  __syncthreads();
  if(tid<32){
    float s=0.f, s2=0.f;
    #pragma unroll 8
    for(int k=0;k<64;k++){ float v=sX[tid*67+k]; s+=v; s2+=v*v; }
    float m=s*(1.0f/64.0f), var=s2*(1.0f/64.0f)-m*m;
    sStat[tid][0]=m; sStat[tid][1]=rsqrtf(var+1e-5f);
  }
  __syncthreads();
  float gg=g2[ch], bb=b2[ch];
  for(int k=0;k<16;k++){
    int t = half + 2*k;
    sYn[t*68+ch] = (xvr[k]-sStat[t][0])*sStat[t][1]*gg + bb;
  }
  __syncthreads();
  int j = tid;
  u64t wp[32];
  #pragma unroll
  for(int k2=0;k2<32;k2++) wp[k2] = pk2(fc1w[(2*k2)*128+j], fc1w[(2*k2+1)*128+j]);
  float bj = fc1b[j];
  uint32_t sYb = sptr(sYn);
  for(int tb=0;tb<4;tb++){
    u64t acc[8];
    #pragma unroll
    for(int t=0;t<8;t++) acc[t] = pk2(bj, 0.f);
    #pragma unroll
    for(int k4=0;k4<16;k4++){
      u64t w0=wp[2*k4], w1=wp[2*k4+1];
      #pragma unroll
      for(int t=0;t<8;t++){
        u64t ya, yb;
        lds128_2(ya, yb, sYb + ((tb*8+t)*68 + k4*4)*4);
        fma2(acc[t], ya, w0);
        fma2(acc[t], yb, w1);
      }
    }
    #pragma unroll
    for(int t=0;t<8;t++) g_y2[(base+tb*8+t)*128+j] = gelu_exact(lohiadd(acc[t]));
  }
}

// ---------------- K5: transpose token-major -> channel-major ----------------
__global__ void k_tr(){
  __shared__ float tile[32][33];
  int bi = blockIdx.z; int c0 = blockIdx.y*32; int p0 = blockIdx.x*32;
  int tx = threadIdx.x, ty = threadIdx.y;   // 32 x 8
  for(int yy=ty;yy<32;yy+=8)
    tile[yy][tx] = g_y2[(bi*THW + p0+yy)*128 + c0+tx];
  __syncthreads();
  for(int yy=ty;yy<32;yy+=8)
    g_y2cm[(bi*HID + c0+yy)*THW + p0+tx] = tile[tx][yy];
}

// ---------------- K6: depthwise 5^3 conv + bias + gelu ----------------------
__global__ void __launch_bounds__(96) k_dwconv(const float* __restrict__ dww, const float* __restrict__ dwb){
  __shared__ float si[20*10*10];
  __shared__ float swt[125];
  int blk = blockIdx.x;
  int tile = blk%36; int cb = blk/36; int ch = cb%HID; int bi = cb/HID;
  int th = tile/6, tw = tile%6;
  int tid = threadIdx.x;
  const float* src = g_y2cm + (bi*HID+ch)*THW;

  for(int i=tid;i<125;i+=96) swt[i] = dww[ch*125+i];
  for(int i=tid;i<2000;i+=96){
    int it = i/100, rm = i%100, ih = rm/10, iw = rm%10;
    int gt = it-2, gh = th*6+ih-2, gw = tw*6+iw-2;
    float v = 0.f;
    if(gt>=0 && gt<TT && gh>=0 && gh<HH && gw>=0 && gw<WW)
      v = src[gt*(HH*WW) + gh*WW + gw];
    si[i] = v;
  }
  __syncthreads();
  int ot = tid/6, oh = tid%6;
  float acc[6] = {0.f,0.f,0.f,0.f,0.f,0.f};
  #pragma unroll
  for(int dt=0;dt<5;dt++){
    #pragma unroll
    for(int dh=0;dh<5;dh++){
      const float* row = si + (ot+dt)*100 + (oh+dh)*10;
      float rr[10];
      #pragma unroll
      for(int i=0;i<10;i++) rr[i]=row[i];
      const float* wp = swt + dt*25 + dh*5;
      float w0=wp[0],w1=wp[1],w2=wp[2],w3=wp[3],w4=wp[4];
      #pragma unroll
      for(int ow=0;ow<6;ow++)
        acc[ow] += rr[ow]*w0 + rr[ow+1]*w1 + rr[ow+2]*w2 + rr[ow+3]*w3 + rr[ow+4]*w4;
    }
  }
  float bsv = dwb[ch];
  float* dst = g_dwcm + (bi*HID+ch)*THW + ot*(HH*WW) + (th*6+oh)*WW + tw*6;
  #pragma unroll
  for(int ow=0;ow<6;ow++) dst[ow] = gelu_exact(acc[ow] + bsv);
}

// ---------------- K7: fc2 + residual + transposed output (f32x2) ------------
#define MLP2_SMEM ((32*132 + 128*64 + 32*65)*4)
__global__ void __launch_bounds__(128) k_mlp2(const float* __restrict__ fc2w, const float* __restrict__ fc2b,
                       float* __restrict__ out){
  float* sYf  = dynsm;               // 32*132
  float* sW2  = sYf + 32*132;        // 128*64 (pair-interleaved)
  float* sOut = sW2 + 128*64;        // 32*65
  int base = blockIdx.x*32;
  int bi = base/THW; int pos0 = base%THW;
  int tid = threadIdx.x;
  for(int i=tid;i<8192;i+=128){
    int k=i>>6, c=i&63;
    sW2[(k>>1)*128 + c*2 + (k&1)] = fc2w[i];
  }
  for(int i=tid;i<4096;i+=128){ int t=i>>7, j=i&127; sYf[t*132+j] = g_y2[(base+t)*128+j]; }
  __syncthreads();
  for(int i=tid;i<4096;i+=128){ int t=i&31, j=i>>5; sYf[t*132+j] += g_dwcm[(bi*HID+j)*THW + pos0 + t]; }
  __syncthreads();
  int ch = tid&63, tg = tid>>6;
  float b = fc2b[ch];
  uint32_t sYb = sptr(sYf);
  uint32_t sWb = sptr(sW2) + ch*8;
  #pragma unroll
  for(int tb=0;tb<2;tb++){
    int t0 = tg*16 + tb*8;
    u64t acc[8];
    #pragma unroll
    for(int t=0;t<8;t++) acc[t] = pk2(b + g_xtok[(base+t0+t)*64+ch], 0.f);
    #pragma unroll 8
    for(int k4=0;k4<32;k4++){
      u64t w0 = lds64(sWb + (2*k4)*512);
      u64t w1 = lds64(sWb + (2*k4+1)*512);
      #pragma unroll
      for(int t=0;t<8;t++){
        u64t ya, yb;
        lds128_2(ya, yb, sYb + ((t0+t)*132 + k4*4)*4);
        fma2(acc[t], ya, w0);
        fma2(acc[t], yb, w1);
      }
    }
    #pragma unroll
    for(int t=0;t<8;t++) sOut[(t0+t)*65+ch] = lohiadd(acc[t]);
  }
  __syncthreads();
  for(int i=tid;i<2048;i+=128){
    int t=i&31, c=i>>5;
    out[(bi*CC+c)*THW + pos0 + t] = sOut[t*65+c];
  }
}

// ---------------- launch ----------------------------------------------------
extern "C" void kernel_launch(void* const* d_in, const int* in_sizes, int n_in,
                              void* d_out, int out_size){
  const float* x    = (const float*)d_in[0];
  const float* ln1g = (const float*)d_in[1];
  const float* ln1b = (const float*)d_in[2];
  const float* wq   = (const float*)d_in[3];
  const float* wk   = (const float*)d_in[4];
  const float* wv   = (const float*)d_in[5];
  const float* wpr  = (const float*)d_in[6];
  const float* ln2g = (const float*)d_in[7];
  const float* ln2b = (const float*)d_in[8];
  const float* fc1w = (const float*)d_in[9];
  const float* fc1b = (const float*)d_in[10];
  const float* dww  = (const float*)d_in[11];
  const float* dwb  = (const float*)d_in[12];
  const float* fc2w = (const float*)d_in[13];
  const float* fc2b = (const float*)d_in[14];
  float* out = (float*)d_out;

  cudaFuncSetAttribute(k_attn, cudaFuncAttributeMaxDynamicSharedMemorySize, AT_SMEM);
  cudaFuncSetAttribute(k_mlp2, cudaFuncAttributeMaxDynamicSharedMemorySize, MLP2_SMEM);

  k_ln1<<<dim3(THW/32, BB), 256>>>(x, ln1g, ln1b);
  k_qkv<<<NROW/32, 128>>>(wq, wk, wv);
  k_attn<<<dim3(NP, HEADS, 8), 256, AT_SMEM>>>();
  k_proj<<<NROW/32, 128>>>(wpr);
  k_mlp1<<<NTOK2/32, 128>>>(ln2g, ln2b, fc1w, fc1b);
  k_tr<<<dim3(THW/32, HID/32, BB), dim3(32,8)>>>();
  k_dwconv<<<BB*HID*36, 96>>>(dww, dwb);
  k_mlp2<<<NTOK2/32, 128, MLP2_SMEM>>>(fc2w, fc2b, out);
}

// round 9
// speedup vs baseline: 3.1235x; 1.0249x over previous
#include <cuda_runtime.h>
#include <cuda_bf16.h>
#include <math.h>
#include <stdint.h>

#define BB 2
#define CC 64
#define TT 16
#define HH 36
#define WW 36
#define THW (TT*HH*WW)
#define PS 8
#define NT 3
#define NH 6
#define NW 6
#define NPB (NT*NH*NW)
#define NP (BB*NPB)
#define TOKN 512
#define NROW (NP*TOKN)
#define HEADS 2
#define HID 128
#define NTOK2 (BB*THW)

__constant__ int   c_st_t[3] = {0,6,8};
__constant__ int   c_st_h[6] = {0,6,12,18,24,28};
__constant__ float c_idt[16] = {1,1,1,1,1,1,0.5f,0.5f,0.5f,0.5f,1,1,1,1,1,1};
__constant__ float c_idh[36] = {1,1,1,1,1,1, 0.5f,0.5f, 1,1,1,1, 0.5f,0.5f,
                                1,1,1,1, 0.5f,0.5f, 1,1,1,1, 0.5f,0.5f,
                                1,1, 0.5f,0.5f, 1,1,1,1,1,1};

__device__ float g_xt[NTOK2*64];
__device__ float g_yt[NTOK2*64];
__device__ __nv_bfloat16 g_qh[NROW*32];
__device__ __nv_bfloat16 g_kh[NROW*32];
__device__ __nv_bfloat16 g_vh[NROW*64];
__device__ float g_attn[NROW*64];
__device__ float g_tok2[NROW*64];
__device__ float g_xtok[NTOK2*64];
__device__ float g_y2[NTOK2*128];
__device__ float g_y2cm[BB*HID*THW];
__device__ float g_dwcm[BB*HID*THW];

extern __shared__ float dynsm[];

__device__ __forceinline__ uint32_t sptr(const void* p){
  return (uint32_t)__cvta_generic_to_shared(p);
}
__device__ __forceinline__ void ldm_x4(uint32_t& r0, uint32_t& r1, uint32_t& r2, uint32_t& r3, uint32_t addr){
  asm volatile("ldmatrix.sync.aligned.m8n8.x4.shared.b16 {%0,%1,%2,%3},[%4];"
    : "=r"(r0),"=r"(r1),"=r"(r2),"=r"(r3) : "r"(addr));
}
__device__ __forceinline__ void ldm_x2(uint32_t& r0, uint32_t& r1, uint32_t addr){
  asm volatile("ldmatrix.sync.aligned.m8n8.x2.shared.b16 {%0,%1},[%2];"
    : "=r"(r0),"=r"(r1) : "r"(addr));
}
__device__ __forceinline__ void ldm_x2t(uint32_t& r0, uint32_t& r1, uint32_t addr){
  asm volatile("ldmatrix.sync.aligned.m8n8.x2.trans.shared.b16 {%0,%1},[%2];"
    : "=r"(r0),"=r"(r1) : "r"(addr));
}
__device__ __forceinline__ void mma_bf16(float& c0, float& c1, float& c2, float& c3,
    uint32_t a0, uint32_t a1, uint32_t a2, uint32_t a3, uint32_t b0, uint32_t b1){
  asm volatile("mma.sync.aligned.m16n8k16.row.col.f32.bf16.bf16.f32 "
    "{%0,%1,%2,%3},{%4,%5,%6,%7},{%8,%9},{%0,%1,%2,%3};"
    : "+f"(c0),"+f"(c1),"+f"(c2),"+f"(c3)
    : "r"(a0),"r"(a1),"r"(a2),"r"(a3),"r"(b0),"r"(b1));
}
__device__ __forceinline__ float wred(float v){
  #pragma unroll
  for(int o=16;o;o>>=1) v += __shfl_xor_sync(0xffffffffu, v, o);
  return v;
}
__device__ __forceinline__ float wmaxr(float v){
  #pragma unroll
  for(int o=16;o;o>>=1) v = fmaxf(v, __shfl_xor_sync(0xffffffffu, v, o));
  return v;
}
__device__ __forceinline__ float gelu_exact(float x){
  return 0.5f*x*(1.0f + erff(x*0.70710678118654752f));
}
__device__ __forceinline__ int tok2pos(int tok, int pt, int ph, int pw){
  int tt = tok>>6, hh = (tok>>3)&7, ww = tok&7;
  return (c_st_t[pt]+tt)*(HH*WW) + (c_st_h[ph]+hh)*WW + (c_st_h[pw]+ww);
}
__device__ __forceinline__ __nv_bfloat162 bf2(float a, float b){
  return __floats2bfloat162_rn(a, b);
}

// ---------------- K0: grid LN1 ----------------------------------------------
__global__ void __launch_bounds__(256) k_ln1(const float* __restrict__ x,
                    const float* __restrict__ g1, const float* __restrict__ b1){
  __shared__ float s[32][65];
  __shared__ float st[32][2];
  int bi = blockIdx.y; int pos0 = blockIdx.x*32;
  int tid = threadIdx.x;
  for(int i=tid;i<2048;i+=256){
    int ch=i>>5, pp=i&31;
    s[pp][ch] = x[(bi*64+ch)*THW + pos0+pp];
  }
  __syncthreads();
  int w = tid>>5, lane = tid&31;
  #pragma unroll
  for(int q=0;q<4;q++){
    int pp = w*4+q;
    float a = s[pp][lane], b = s[pp][lane+32];
    float su = wred(a+b);
    float sq = wred(a*a+b*b);
    if(lane==0){
      float m = su*(1.0f/64.0f);
      float var = sq*(1.0f/64.0f) - m*m;
      st[pp][0]=m; st[pp][1]=rsqrtf(var+1e-5f);
    }
  }
  __syncthreads();
  for(int i=tid;i<2048;i+=256){
    int pp=i>>6, ch=i&63;
    float v = s[pp][ch];
    int idx = (bi*THW + pos0+pp)*64 + ch;
    g_xt[idx] = v;
    g_yt[idx] = (v-st[pp][0])*st[pp][1]*g1[ch] + b1[ch];
  }
}

// ---------------- K1: fused QKV GEMM via mma (M128 K64 N128) ----------------
__global__ void __launch_bounds__(256) k_qkv(const float* __restrict__ wq,
                      const float* __restrict__ wk,
                      const float* __restrict__ wv){
  __shared__ __nv_bfloat16 sA[128*72];
  __shared__ __nv_bfloat16 sB[128*72];
  int tid = threadIdx.x;
  int base = blockIdx.x*128;
  int p = base>>9, tok0 = base&511;
  int bi = p/NPB; int r0 = p%NPB;
  int pt=r0/36, ph=(r0%36)/6, pw=r0%6;
  for(int i=tid;i<4096;i+=256){
    int t=i>>5, cp=i&31;
    int pos = tok2pos(tok0+t, pt, ph, pw);
    float2 v = *(const float2*)&g_yt[((size_t)(bi*THW+pos))*64 + cp*2];
    *(__nv_bfloat162*)&sA[t*72+cp*2] = bf2(v.x, v.y);
  }
  for(int i=tid;i<8192;i+=256){
    int n=i>>6, k=i&63;
    float wval;
    if(n<32)       wval = wq[k*32+n];
    else if(n<64)  wval = wk[k*32+(n-32)];
    else           wval = wv[k*64+(n-64)];
    sB[n*72+k] = __float2bfloat16(wval);
  }
  __syncthreads();
  int w = tid>>5, lane = tid&31;
  int wr = w>>1, wc = w&1;
  float acc[2][8][4];
  #pragma unroll
  for(int mt=0;mt<2;mt++)
    #pragma unroll
    for(int nt=0;nt<8;nt++)
      #pragma unroll
      for(int q=0;q<4;q++) acc[mt][nt][q]=0.f;
  uint32_t sAb = sptr(sA), sBb = sptr(sB);
  #pragma unroll
  for(int ks=0;ks<4;ks++){
    uint32_t a[2][4];
    #pragma unroll
    for(int mt=0;mt<2;mt++){
      int row = wr*32 + mt*16 + (lane&7) + ((lane&8)?8:0);
      ldm_x4(a[mt][0],a[mt][1],a[mt][2],a[mt][3],
             sAb + row*144 + ks*32 + ((lane&16)?16:0));
    }
    #pragma unroll
    for(int nt=0;nt<8;nt++){
      int n0 = wc*64 + nt*8;
      uint32_t b0,b1;
      ldm_x2(b0,b1, sBb + (n0+(lane&7))*144 + ks*32 + ((lane&8)?16:0));
      #pragma unroll
      for(int mt=0;mt<2;mt++)
        mma_bf16(acc[mt][nt][0],acc[mt][nt][1],acc[mt][nt][2],acc[mt][nt][3],
                 a[mt][0],a[mt][1],a[mt][2],a[mt][3], b0,b1);
    }
  }
  #pragma unroll
  for(int mt=0;mt<2;mt++){
    #pragma unroll
    for(int nt=0;nt<8;nt++){
      int r = wr*32 + mt*16 + (lane>>2);
      int c = wc*64 + nt*8 + (lane&3)*2;
      #pragma unroll
      for(int hrow=0;hrow<2;hrow++){
        int rg = base + r + hrow*8;
        float v0 = acc[mt][nt][hrow*2], v1 = acc[mt][nt][hrow*2+1];
        if(c<32)       *(__nv_bfloat162*)&g_qh[(size_t)rg*32 + c]      = bf2(v0,v1);
        else if(c<64)  *(__nv_bfloat162*)&g_kh[(size_t)rg*32 + (c-32)] = bf2(v0,v1);
        else           *(__nv_bfloat162*)&g_vh[(size_t)rg*64 + (c-64)] = bf2(v0,v1);
      }
    }
  }
}

// ---------------- K2: attention via mma.sync bf16 ---------------------------
#define S_PITCH_W 524
#define S_PITCH_B 2096
#define SK_OFF 134144
#define SV_OFF 158720
#define SQ_OFF 199680
#define SINV_OFF 202752
#define AT_SMEM 203008
__global__ void __launch_bounds__(256,1) k_attn(){
  char* sm = (char*)dynsm;
  int p = blockIdx.x, hd = blockIdx.y;
  int q0 = blockIdx.z*64;
  int tid = threadIdx.x;
  float* sS = (float*)sm;
  float* sInv = (float*)(sm + SINV_OFF);
  {
    const uint32_t* qsrc = (const uint32_t*)g_qh + (size_t)(p*512+q0)*16 + hd*8;
    uint32_t* dq = (uint32_t*)(sm + SQ_OFF);
    for(int i=tid;i<64*8;i+=256){ int r=i>>3, dp=i&7; dq[r*12+dp] = qsrc[r*16+dp]; }
    const uint32_t* ksrc = (const uint32_t*)g_kh + (size_t)p*512*16 + hd*8;
    uint32_t* dk = (uint32_t*)(sm + SK_OFF);
    for(int i=tid;i<512*8;i+=256){ int r=i>>3, dp=i&7; dk[r*12+dp] = ksrc[r*16+dp]; }
    const uint32_t* vsrc = (const uint32_t*)g_vh + (size_t)p*512*32 + hd*16;
    uint32_t* dv = (uint32_t*)(sm + SV_OFF);
    for(int i=tid;i<512*16;i+=256){ int r=i>>4, dp=i&15; dv[r*20+dp] = vsrc[r*32+dp]; }
  }
  __syncthreads();
  int w = tid>>5, lane = tid&31;
  {
    uint32_t sQb = sptr(sm + SQ_OFF);
    uint32_t aQ[4][4];
    #pragma unroll
    for(int qt=0;qt<4;qt++){
      int row = qt*16 + (lane&7) + ((lane&8)?8:0);
      ldm_x4(aQ[qt][0],aQ[qt][1],aQ[qt][2],aQ[qt][3],
             sQb + row*48 + ((lane&16)?16:0));
    }
    uint32_t sKb = sptr(sm + SK_OFF);
    for(int kt=0;kt<8;kt++){
      int j0 = w*64 + kt*8;
      uint32_t b0,b1;
      ldm_x2(b0,b1, sKb + (j0 + (lane&7))*48 + ((lane&8)?16:0));  // non-trans (n-major rows)
      #pragma unroll
      for(int qt=0;qt<4;qt++){
        float c0=0.f,c1=0.f,c2=0.f,c3=0.f;
        mma_bf16(c0,c1,c2,c3, aQ[qt][0],aQ[qt][1],aQ[qt][2],aQ[qt][3], b0,b1);
        int r = qt*16 + (lane>>2);
        int c = j0 + (lane&3)*2;
        *(float2*)(sS + r*S_PITCH_W + c) = make_float2(c0,c1);
        *(float2*)(sS + (r+8)*S_PITCH_W + c) = make_float2(c2,c3);
      }
    }
  }
  __syncthreads();
  for(int rr=0;rr<8;rr++){
    int r = w*8 + rr;
    float* Srow = sS + r*S_PITCH_W;
    float m = -1e30f;
    #pragma unroll
    for(int jj=0;jj<16;jj++) m = fmaxf(m, Srow[lane + 32*jj]);
    m = wmaxr(m);
    float ev[16]; float sum = 0.f;
    #pragma unroll
    for(int jj=0;jj<16;jj++){
      ev[jj] = __expf(0.25f*(Srow[lane + 32*jj] - m));
      sum += ev[jj];
    }
    __syncwarp();
    __nv_bfloat16* Prow = (__nv_bfloat16*)(sm + r*S_PITCH_B);
    #pragma unroll
    for(int jj=0;jj<16;jj++) Prow[lane + 32*jj] = __float2bfloat16(ev[jj]);
    sum = wred(sum);
    if(lane==0) sInv[r] = 1.0f/sum;
  }
  __syncthreads();
  {
    uint32_t sVb = sptr(sm + SV_OFF);
    uint32_t sPb = sptr(sm);
    #pragma unroll
    for(int t2=0;t2<2;t2++){
      int tt = w + t2*8;
      int qt = tt>>2, nt = tt&3;
      float c0=0.f,c1=0.f,c2=0.f,c3=0.f;
      int arow = qt*16 + (lane&7) + ((lane&8)?8:0);
      uint32_t aBase = sPb + arow*S_PITCH_B + ((lane&16)?16:0);
      uint32_t bBase = sVb + ((lane&7) + ((lane&8)?8:0))*80 + nt*16;
      #pragma unroll 4
      for(int ks=0;ks<32;ks++){
        uint32_t a0,a1,a2,a3; ldm_x4(a0,a1,a2,a3, aBase + ks*32);
        uint32_t b0,b1; ldm_x2t(b0,b1, bBase + ks*16*80);   // k-major rows: trans correct
        mma_bf16(c0,c1,c2,c3, a0,a1,a2,a3, b0,b1);
      }
      int r = qt*16 + (lane>>2);
      int c = nt*8 + (lane&3)*2;
      float i0 = sInv[r], i1 = sInv[r+8];
      float* og = g_attn + (size_t)(p*512 + q0 + r)*64 + hd*32 + c;
      og[0] = c0*i0; og[1] = c1*i0;
      og[8*64+0] = c2*i1; og[8*64+1] = c3*i1;
    }
  }
}

// ---------------- K3: proj + residual via mma (M128 K64 N64) ----------------
__global__ void __launch_bounds__(256) k_proj(const float* __restrict__ wproj){
  __shared__ __nv_bfloat16 sA[128*72];
  __shared__ __nv_bfloat16 sB[64*72];
  int tid = threadIdx.x;
  int base = blockIdx.x*128;
  int p = base>>9, tok0 = base&511;
  int bi = p/NPB; int r0 = p%NPB;
  int pt=r0/36, ph=(r0%36)/6, pw=r0%6;
  for(int i=tid;i<4096;i+=256){
    int t=i>>5, cp=i&31;
    float2 v = *(const float2*)&g_attn[((size_t)(base+t))*64 + cp*2];
    *(__nv_bfloat162*)&sA[t*72+cp*2] = bf2(v.x, v.y);
  }
  for(int i=tid;i<4096;i+=256){
    int n=i>>6, k=i&63;
    sB[n*72+k] = __float2bfloat16(wproj[k*64+n]);
  }
  __syncthreads();
  int w = tid>>5, lane = tid&31;
  int wr = w>>1, wc = w&1;
  float acc[2][4][4];
  #pragma unroll
  for(int mt=0;mt<2;mt++)
    #pragma unroll
    for(int nt=0;nt<4;nt++)
      #pragma unroll
      for(int q=0;q<4;q++) acc[mt][nt][q]=0.f;
  uint32_t sAb = sptr(sA), sBb = sptr(sB);
  #pragma unroll
  for(int ks=0;ks<4;ks++){
    uint32_t a[2][4];
    #pragma unroll
    for(int mt=0;mt<2;mt++){
      int row = wr*32 + mt*16 + (lane&7) + ((lane&8)?8:0);
      ldm_x4(a[mt][0],a[mt][1],a[mt][2],a[mt][3],
             sAb + row*144 + ks*32 + ((lane&16)?16:0));
    }
    #pragma unroll
    for(int nt=0;nt<4;nt++){
      int n0 = wc*32 + nt*8;
      uint32_t b0,b1;
      ldm_x2(b0,b1, sBb + (n0+(lane&7))*144 + ks*32 + ((lane&8)?16:0));
      #pragma unroll
      for(int mt=0;mt<2;mt++)
        mma_bf16(acc[mt][nt][0],acc[mt][nt][1],acc[mt][nt][2],acc[mt][nt][3],
                 a[mt][0],a[mt][1],a[mt][2],a[mt][3], b0,b1);
    }
  }
  #pragma unroll
  for(int mt=0;mt<2;mt++){
    #pragma unroll
    for(int nt=0;nt<4;nt++){
      int r = wr*32 + mt*16 + (lane>>2);
      int c = wc*32 + nt*8 + (lane&3)*2;
      #pragma unroll
      for(int hrow=0;hrow<2;hrow++){
        int tok = r + hrow*8;
        int pos = tok2pos(tok0+tok, pt, ph, pw);
        float2 res = *(const float2*)&g_xt[((size_t)(bi*THW+pos))*64 + c];
        float v0 = acc[mt][nt][hrow*2]   + res.x;
        float v1 = acc[mt][nt][hrow*2+1] + res.y;
        *(float2*)&g_tok2[((size_t)(base+tok))*64 + c] = make_float2(v0,v1);
      }
    }
  }
}

// ---------------- K4: gather + LN2 + fc1(mma) + gelu ------------------------
#define MLP1_SMEM (34816 + 18432 + 18432)
__global__ void __launch_bounds__(256) k_mlp1(const float* __restrict__ g2, const float* __restrict__ b2,
                       const float* __restrict__ fc1w, const float* __restrict__ fc1b){
  float* sX = dynsm;                         // 128*66
  float* sM = dynsm + 8448;
  float* sR = sM + 128;
  __nv_bfloat16* sYn = (__nv_bfloat16*)((char*)dynsm + 34816);  // 128*72
  __nv_bfloat16* sB  = (__nv_bfloat16*)((char*)dynsm + 34816 + 18432);
  int base = blockIdx.x*128;
  int bi = base/THW;
  int tid = threadIdx.x;
  int ch = tid&63, tg = tid>>6;
  for(int k=0;k<32;k++){
    int t = tg + 4*k;
    int token = base + t;
    int pos = token % THW;
    int tt_ = pos/(HH*WW), hh_=(pos/WW)%HH, ww_=pos%WW;
    float acc = 0.f;
    #pragma unroll
    for(int pt=0;pt<3;pt++){
      int dt_ = tt_-c_st_t[pt]; if(dt_<0||dt_>=8) continue;
      #pragma unroll
      for(int ph=0;ph<6;ph++){
        int dh_ = hh_-c_st_h[ph]; if(dh_<0||dh_>=8) continue;
        #pragma unroll
        for(int pw=0;pw<6;pw++){
          int dw_ = ww_-c_st_h[pw]; if(dw_<0||dw_>=8) continue;
          int pp = bi*NPB + pt*36 + ph*6 + pw;
          int tk = dt_*64 + dh_*8 + dw_;
          acc += g_tok2[((size_t)(pp*512+tk))*64 + ch];
        }
      }
    }
    float xv = acc * c_idt[tt_]*c_idh[hh_]*c_idh[ww_];
    sX[t*66+ch] = xv;
    g_xtok[(size_t)token*64+ch] = xv;
  }
  for(int i=tid;i<8192;i+=256){
    int n=i>>6, k=i&63;
    sB[n*72+k] = __float2bfloat16(fc1w[k*128+n]);
  }
  __syncthreads();
  {
    int row = tid>>1, hf = tid&1;
    float s=0.f, s2=0.f;
    #pragma unroll 8
    for(int j=hf*32;j<hf*32+32;j++){ float v=sX[row*66+j]; s+=v; s2+=v*v; }
    s  += __shfl_xor_sync(0xffffffffu, s, 1);
    s2 += __shfl_xor_sync(0xffffffffu, s2, 1);
    if(hf==0){
      float m=s*(1.0f/64.0f), var=s2*(1.0f/64.0f)-m*m;
      sM[row]=m; sR[row]=rsqrtf(var+1e-5f);
    }
  }
  __syncthreads();
  for(int i=tid;i<8192;i+=256){
    int t=i>>6, cc=i&63;
    float v = sX[t*66+cc];
    sYn[t*72+cc] = __float2bfloat16((v-sM[t])*sR[t]*g2[cc]+b2[cc]);
  }
  __syncthreads();
  int w = tid>>5, lane = tid&31;
  int wr = w>>1, wc = w&1;
  float acc[2][8][4];
  #pragma unroll
  for(int mt=0;mt<2;mt++)
    #pragma unroll
    for(int nt=0;nt<8;nt++)
      #pragma unroll
      for(int q=0;q<4;q++) acc[mt][nt][q]=0.f;
  uint32_t sAb = sptr(sYn), sBb = sptr(sB);
  #pragma unroll
  for(int ks=0;ks<4;ks++){
    uint32_t a[2][4];
    #pragma unroll
    for(int mt=0;mt<2;mt++){
      int row = wr*32 + mt*16 + (lane&7) + ((lane&8)?8:0);
      ldm_x4(a[mt][0],a[mt][1],a[mt][2],a[mt][3],
             sAb + row*144 + ks*32 + ((lane&16)?16:0));
    }
    #pragma unroll
    for(int nt=0;nt<8;nt++){
      int n0 = wc*64 + nt*8;
      uint32_t b0,b1;
      ldm_x2(b0,b1, sBb + (n0+(lane&7))*144 + ks*32 + ((lane&8)?16:0));
      #pragma unroll
      for(int mt=0;mt<2;mt++)
        mma_bf16(acc[mt][nt][0],acc[mt][nt][1],acc[mt][nt][2],acc[mt][nt][3],
                 a[mt][0],a[mt][1],a[mt][2],a[mt][3], b0,b1);
    }
  }
  #pragma unroll
  for(int mt=0;mt<2;mt++){
    #pragma unroll
    for(int nt=0;nt<8;nt++){
      int r = wr*32 + mt*16 + (lane>>2);
      int c = wc*64 + nt*8 + (lane&3)*2;
      float bj0 = fc1b[c], bj1 = fc1b[c+1];
      #pragma unroll
      for(int hrow=0;hrow<2;hrow++){
        int tok = base + r + hrow*8;
        float v0 = gelu_exact(acc[mt][nt][hrow*2]   + bj0);
        float v1 = gelu_exact(acc[mt][nt][hrow*2+1] + bj1);
        *(float2*)&g_y2[(size_t)tok*128 + c] = make_float2(v0,v1);
      }
    }
  }
}

// ---------------- K5: transpose token-major -> channel-major ----------------
__global__ void k_tr(){
  __shared__ float tile[32][33];
  int bi = blockIdx.z; int c0 = blockIdx.y*32; int p0 = blockIdx.x*32;
  int tx = threadIdx.x, ty = threadIdx.y;
  for(int yy=ty;yy<32;yy+=8)
    tile[yy][tx] = g_y2[((size_t)(bi*THW + p0+yy))*128 + c0+tx];
  __syncthreads();
  for(int yy=ty;yy<32;yy+=8)
    g_y2cm[((size_t)(bi*HID + c0+yy))*THW + p0+tx] = tile[tx][yy];
}

// ---------------- K6: depthwise 5^3 conv + bias + gelu ----------------------
__global__ void __launch_bounds__(96) k_dwconv(const float* __restrict__ dww, const float* __restrict__ dwb){
  __shared__ float si[20*10*10];
  __shared__ float swt[125];
  int blk = blockIdx.x;
  int tile = blk%36; int cb = blk/36; int ch = cb%HID; int bi = cb/HID;
  int th = tile/6, tw = tile%6;
  int tid = threadIdx.x;
  const float* src = g_y2cm + ((size_t)(bi*HID+ch))*THW;

  for(int i=tid;i<125;i+=96) swt[i] = dww[ch*125+i];
  for(int i=tid;i<2000;i+=96){
    int it = i/100, rm = i%100, ih = rm/10, iw = rm%10;
    int gt = it-2, gh = th*6+ih-2, gw = tw*6+iw-2;
    float v = 0.f;
    if(gt>=0 && gt<TT && gh>=0 && gh<HH && gw>=0 && gw<WW)
      v = src[gt*(HH*WW) + gh*WW + gw];
    si[i] = v;
  }
  __syncthreads();
  int ot = tid/6, oh = tid%6;
  float acc[6] = {0.f,0.f,0.f,0.f,0.f,0.f};
  #pragma unroll
  for(int dt=0;dt<5;dt++){
    #pragma unroll
    for(int dh=0;dh<5;dh++){
      const float* row = si + (ot+dt)*100 + (oh+dh)*10;
      float rr[10];
      #pragma unroll
      for(int i=0;i<10;i++) rr[i]=row[i];
      const float* wp = swt + dt*25 + dh*5;
      float w0=wp[0],w1=wp[1],w2=wp[2],w3=wp[3],w4=wp[4];
      #pragma unroll
      for(int ow=0;ow<6;ow++)
        acc[ow] += rr[ow]*w0 + rr[ow+1]*w1 + rr[ow+2]*w2 + rr[ow+3]*w3 + rr[ow+4]*w4;
    }
  }
  float bsv = dwb[ch];
  float* dst = g_dwcm + ((size_t)(bi*HID+ch))*THW + ot*(HH*WW) + (th*6+oh)*WW + tw*6;
  #pragma unroll
  for(int ow=0;ow<6;ow++) dst[ow] = gelu_exact(acc[ow] + bsv);
}

// ---------------- K7: fc2(mma) + residual + transposed store ----------------
#define MLP2_SMEM (68608 + 16640)
__global__ void __launch_bounds__(256) k_mlp2(const float* __restrict__ fc2w, const float* __restrict__ fc2b,
                       float* __restrict__ out){
  float* sYf = dynsm;                                          // 64*132 f32
  __nv_bfloat16* sA = (__nv_bfloat16*)((char*)dynsm + 33792);  // 64*136
  __nv_bfloat16* sB = (__nv_bfloat16*)((char*)dynsm + 51200);  // 64*136
  float* sOut = (float*)((char*)dynsm + 68608);                // 64*65
  int base = blockIdx.x*64;
  int bi = base/THW; int pos0 = base%THW;
  int tid = threadIdx.x;
  for(int i=tid;i<8192;i+=256){ int t=i>>7, j=i&127; sYf[t*132+j] = g_y2[((size_t)(base+t))*128+j]; }
  for(int i=tid;i<8192;i+=256){
    int n=i>>7, k=i&127;
    sB[n*136+k] = __float2bfloat16(fc2w[k*64+n]);
  }
  __syncthreads();
  for(int i=tid;i<8192;i+=256){ int t=i&63, j=i>>6; sYf[t*132+j] += g_dwcm[((size_t)(bi*HID+j))*THW + pos0 + t]; }
  __syncthreads();
  for(int i=tid;i<4096;i+=256){
    int t=i>>6, jp=i&63;
    float2 v = *(const float2*)&sYf[t*132 + jp*2];
    *(__nv_bfloat162*)&sA[t*136+jp*2] = bf2(v.x, v.y);
  }
  __syncthreads();
  int w = tid>>5, lane = tid&31;
  int wr = w>>1, wc = w&1;
  float acc[4][4];
  #pragma unroll
  for(int nt=0;nt<4;nt++)
    #pragma unroll
    for(int q=0;q<4;q++) acc[nt][q]=0.f;
  uint32_t sAb = sptr(sA), sBb = sptr(sB);
  #pragma unroll
  for(int ks=0;ks<8;ks++){
    uint32_t a0,a1,a2,a3;
    {
      int row = wr*16 + (lane&7) + ((lane&8)?8:0);
      ldm_x4(a0,a1,a2,a3, sAb + row*272 + ks*32 + ((lane&16)?16:0));
    }
    #pragma unroll
    for(int nt=0;nt<4;nt++){
      int n0 = wc*32 + nt*8;
      uint32_t b0,b1;
      ldm_x2(b0,b1, sBb + (n0+(lane&7))*272 + ks*32 + ((lane&8)?16:0));
      mma_bf16(acc[nt][0],acc[nt][1],acc[nt][2],acc[nt][3], a0,a1,a2,a3, b0,b1);
    }
  }
  #pragma unroll
  for(int nt=0;nt<4;nt++){
    int r = wr*16 + (lane>>2);
    int c = wc*32 + nt*8 + (lane&3)*2;
    float b0 = fc2b[c], b1 = fc2b[c+1];
    #pragma unroll
    for(int hrow=0;hrow<2;hrow++){
      int t = r + hrow*8;
      float2 res = *(const float2*)&g_xtok[((size_t)(base+t))*64 + c];
      sOut[t*65+c]   = acc[nt][hrow*2]   + b0 + res.x;
      sOut[t*65+c+1] = acc[nt][hrow*2+1] + b1 + res.y;
    }
  }
  __syncthreads();
  for(int i=tid;i<4096;i+=256){
    int t=i&63, c=i>>6;
    out[((size_t)(bi*CC+c))*THW + pos0 + t] = sOut[t*65+c];
  }
}

// ---------------- launch ----------------------------------------------------
extern "C" void kernel_launch(void* const* d_in, const int* in_sizes, int n_in,
                              void* d_out, int out_size){
  const float* x    = (const float*)d_in[0];
  const float* ln1g = (const float*)d_in[1];
  const float* ln1b = (const float*)d_in[2];
  const float* wq   = (const float*)d_in[3];
  const float* wk   = (const float*)d_in[4];
  const float* wv   = (const float*)d_in[5];
  const float* wpr  = (const float*)d_in[6];
  const float* ln2g = (const float*)d_in[7];
  const float* ln2b = (const float*)d_in[8];
  const float* fc1w = (const float*)d_in[9];
  const float* fc1b = (const float*)d_in[10];
  const float* dww  = (const float*)d_in[11];
  const float* dwb  = (const float*)d_in[12];
  const float* fc2w = (const float*)d_in[13];
  const float* fc2b = (const float*)d_in[14];
  float* out = (float*)d_out;

  cudaFuncSetAttribute(k_attn, cudaFuncAttributeMaxDynamicSharedMemorySize, AT_SMEM);
  cudaFuncSetAttribute(k_mlp1, cudaFuncAttributeMaxDynamicSharedMemorySize, MLP1_SMEM);
  cudaFuncSetAttribute(k_mlp2, cudaFuncAttributeMaxDynamicSharedMemorySize, MLP2_SMEM);

  k_ln1<<<dim3(THW/32, BB), 256>>>(x, ln1g, ln1b);
  k_qkv<<<NROW/128, 256>>>(wq, wk, wv);
  k_attn<<<dim3(NP, HEADS, 8), 256, AT_SMEM>>>();
  k_proj<<<NROW/128, 256>>>(wpr);
  k_mlp1<<<NTOK2/128, 256, MLP1_SMEM>>>(ln2g, ln2b, fc1w, fc1b);
  k_tr<<<dim3(THW/32, HID/32, BB), dim3(32,8)>>>();
  k_dwconv<<<BB*HID*36, 96>>>(dww, dwb);
  k_mlp2<<<NTOK2/64, 256, MLP2_SMEM>>>(fc2w, fc2b, out);
}

// round 12
// speedup vs baseline: 3.3315x; 1.0666x over previous
#include <cuda_runtime.h>
#include <cuda_bf16.h>
#include <math.h>
#include <stdint.h>

#define BB 2
#define CC 64
#define TT 16
#define HH 36
#define WW 36
#define THW (TT*HH*WW)
#define PS 8
#define NT 3
#define NH 6
#define NW 6
#define NPB (NT*NH*NW)
#define NP (BB*NPB)
#define TOKN 512
#define NROW (NP*TOKN)
#define HEADS 2
#define HID 128
#define NTOK2 (BB*THW)

__constant__ int   c_st_t[3] = {0,6,8};
__constant__ int   c_st_h[6] = {0,6,12,18,24,28};
__constant__ float c_idt[16] = {1,1,1,1,1,1,0.5f,0.5f,0.5f,0.5f,1,1,1,1,1,1};
__constant__ float c_idh[36] = {1,1,1,1,1,1, 0.5f,0.5f, 1,1,1,1, 0.5f,0.5f,
                                1,1,1,1, 0.5f,0.5f, 1,1,1,1, 0.5f,0.5f,
                                1,1, 0.5f,0.5f, 1,1,1,1,1,1};
// coverage tables: bit0=n-1, bits1-3=p0, bits4-6=d0, bits7-9=p1, bits10-12=d1
__constant__ uint32_t c_cov_t[16] = {0,16,32,48,64,80,225,1265,291,1331,2371,3411,4451,5491,100,116};
__constant__ uint32_t c_cov_h[36] = {0,16,32,48,64,80,225,1265,34,50,66,82,355,1395,36,52,68,84,
                                     485,1525,38,54,70,86,615,1655,40,56,713,1753,2793,3833,74,90,106,122};

__device__ float g_xt[NTOK2*64];
__device__ float g_yt[NTOK2*64];
__device__ __nv_bfloat16 g_qh[NROW*32];
__device__ __nv_bfloat16 g_kh[NROW*32];
__device__ __nv_bfloat16 g_vh[NROW*64];
__device__ float g_attn[NROW*64];
__device__ float g_tok2[NROW*64];
__device__ float g_xtok[NTOK2*64];
__device__ float g_y2[NTOK2*128];
__device__ float g_y2cm[BB*HID*THW];
__device__ float g_dwcm[BB*HID*THW];

extern __shared__ float dynsm[];

__device__ __forceinline__ uint32_t sptr(const void* p){
  return (uint32_t)__cvta_generic_to_shared(p);
}
__device__ __forceinline__ void ldm_x4(uint32_t& r0, uint32_t& r1, uint32_t& r2, uint32_t& r3, uint32_t addr){
  asm volatile("ldmatrix.sync.aligned.m8n8.x4.shared.b16 {%0,%1,%2,%3},[%4];"
    : "=r"(r0),"=r"(r1),"=r"(r2),"=r"(r3) : "r"(addr));
}
__device__ __forceinline__ void ldm_x2(uint32_t& r0, uint32_t& r1, uint32_t addr){
  asm volatile("ldmatrix.sync.aligned.m8n8.x2.shared.b16 {%0,%1},[%2];"
    : "=r"(r0),"=r"(r1) : "r"(addr));
}
__device__ __forceinline__ void ldm_x2t(uint32_t& r0, uint32_t& r1, uint32_t addr){
  asm volatile("ldmatrix.sync.aligned.m8n8.x2.trans.shared.b16 {%0,%1},[%2];"
    : "=r"(r0),"=r"(r1) : "r"(addr));
}
__device__ __forceinline__ void mma_bf16(float& c0, float& c1, float& c2, float& c3,
    uint32_t a0, uint32_t a1, uint32_t a2, uint32_t a3, uint32_t b0, uint32_t b1){
  asm volatile("mma.sync.aligned.m16n8k16.row.col.f32.bf16.bf16.f32 "
    "{%0,%1,%2,%3},{%4,%5,%6,%7},{%8,%9},{%0,%1,%2,%3};"
    : "+f"(c0),"+f"(c1),"+f"(c2),"+f"(c3)
    : "r"(a0),"r"(a1),"r"(a2),"r"(a3),"r"(b0),"r"(b1));
}
__device__ __forceinline__ float wred(float v){
  #pragma unroll
  for(int o=16;o;o>>=1) v += __shfl_xor_sync(0xffffffffu, v, o);
  return v;
}
__device__ __forceinline__ float wmaxr(float v){
  #pragma unroll
  for(int o=16;o;o>>=1) v = fmaxf(v, __shfl_xor_sync(0xffffffffu, v, o));
  return v;
}
__device__ __forceinline__ float gelu_exact(float x){
  return 0.5f*x*(1.0f + erff(x*0.70710678118654752f));
}
__device__ __forceinline__ int tok2pos(int tok, int pt, int ph, int pw){
  int tt = tok>>6, hh = (tok>>3)&7, ww = tok&7;
  return (c_st_t[pt]+tt)*(HH*WW) + (c_st_h[ph]+hh)*WW + (c_st_h[pw]+ww);
}
__device__ __forceinline__ __nv_bfloat162 bf2(float a, float b){
  return __floats2bfloat162_rn(a, b);
}

// ---------------- K0: grid LN1 ----------------------------------------------
__global__ void __launch_bounds__(256) k_ln1(const float* __restrict__ x,
                    const float* __restrict__ g1, const float* __restrict__ b1){
  __shared__ float s[32][65];
  __shared__ float st[32][2];
  int bi = blockIdx.y; int pos0 = blockIdx.x*32;
  int tid = threadIdx.x;
  for(int i=tid;i<2048;i+=256){
    int ch=i>>5, pp=i&31;
    s[pp][ch] = x[(bi*64+ch)*THW + pos0+pp];
  }
  __syncthreads();
  int w = tid>>5, lane = tid&31;
  #pragma unroll
  for(int q=0;q<4;q++){
    int pp = w*4+q;
    float a = s[pp][lane], b = s[pp][lane+32];
    float su = wred(a+b);
    float sq = wred(a*a+b*b);
    if(lane==0){
      float m = su*(1.0f/64.0f);
      float var = sq*(1.0f/64.0f) - m*m;
      st[pp][0]=m; st[pp][1]=rsqrtf(var+1e-5f);
    }
  }
  __syncthreads();
  for(int i=tid;i<2048;i+=256){
    int pp=i>>6, ch=i&63;
    float v = s[pp][ch];
    int idx = (bi*THW + pos0+pp)*64 + ch;
    g_xt[idx] = v;
    g_yt[idx] = (v-st[pp][0])*st[pp][1]*g1[ch] + b1[ch];
  }
}

// ---------------- K1: fused QKV GEMM via mma (M128 K64 N128) ----------------
__global__ void __launch_bounds__(256) k_qkv(const float* __restrict__ wq,
                      const float* __restrict__ wk,
                      const float* __restrict__ wv){
  __shared__ __nv_bfloat16 sA[128*72];
  __shared__ __nv_bfloat16 sB[128*72];
  int tid = threadIdx.x;
  int base = blockIdx.x*128;
  int p = base>>9, tok0 = base&511;
  int bi = p/NPB; int r0 = p%NPB;
  int pt=r0/36, ph=(r0%36)/6, pw=r0%6;
  for(int i=tid;i<4096;i+=256){
    int t=i>>5, cp=i&31;
    int pos = tok2pos(tok0+t, pt, ph, pw);
    float2 v = *(const float2*)&g_yt[((size_t)(bi*THW+pos))*64 + cp*2];
    *(__nv_bfloat162*)&sA[t*72+cp*2] = bf2(v.x, v.y);
  }
  for(int i=tid;i<8192;i+=256){
    int n=i>>6, k=i&63;
    float wval;
    if(n<32)       wval = wq[k*32+n];
    else if(n<64)  wval = wk[k*32+(n-32)];
    else           wval = wv[k*64+(n-64)];
    sB[n*72+k] = __float2bfloat16(wval);
  }
  __syncthreads();
  int w = tid>>5, lane = tid&31;
  int wr = w>>1, wc = w&1;
  float acc[2][8][4];
  #pragma unroll
  for(int mt=0;mt<2;mt++)
    #pragma unroll
    for(int nt=0;nt<8;nt++)
      #pragma unroll
      for(int q=0;q<4;q++) acc[mt][nt][q]=0.f;
  uint32_t sAb = sptr(sA), sBb = sptr(sB);
  #pragma unroll
  for(int ks=0;ks<4;ks++){
    uint32_t a[2][4];
    #pragma unroll
    for(int mt=0;mt<2;mt++){
      int row = wr*32 + mt*16 + (lane&7) + ((lane&8)?8:0);
      ldm_x4(a[mt][0],a[mt][1],a[mt][2],a[mt][3],
             sAb + row*144 + ks*32 + ((lane&16)?16:0));
    }
    #pragma unroll
    for(int nt=0;nt<8;nt++){
      int n0 = wc*64 + nt*8;
      uint32_t b0,b1;
      ldm_x2(b0,b1, sBb + (n0+(lane&7))*144 + ks*32 + ((lane&8)?16:0));
      #pragma unroll
      for(int mt=0;mt<2;mt++)
        mma_bf16(acc[mt][nt][0],acc[mt][nt][1],acc[mt][nt][2],acc[mt][nt][3],
                 a[mt][0],a[mt][1],a[mt][2],a[mt][3], b0,b1);
    }
  }
  #pragma unroll
  for(int mt=0;mt<2;mt++){
    #pragma unroll
    for(int nt=0;nt<8;nt++){
      int r = wr*32 + mt*16 + (lane>>2);
      int c = wc*64 + nt*8 + (lane&3)*2;
      #pragma unroll
      for(int hrow=0;hrow<2;hrow++){
        int rg = base + r + hrow*8;
        float v0 = acc[mt][nt][hrow*2], v1 = acc[mt][nt][hrow*2+1];
        if(c<32)       *(__nv_bfloat162*)&g_qh[(size_t)rg*32 + c]      = bf2(v0,v1);
        else if(c<64)  *(__nv_bfloat162*)&g_kh[(size_t)rg*32 + (c-32)] = bf2(v0,v1);
        else           *(__nv_bfloat162*)&g_vh[(size_t)rg*64 + (c-64)] = bf2(v0,v1);
      }
    }
  }
}

// ---------------- K2: attention via mma.sync bf16 (R9-proven version) -------
#define S_PITCH_W 524
#define S_PITCH_B 2096
#define SK_OFF 134144
#define SV_OFF 158720
#define SQ_OFF 199680
#define SINV_OFF 202752
#define AT_SMEM 203008
__global__ void __launch_bounds__(256,1) k_attn(){
  char* sm = (char*)dynsm;
  int p = blockIdx.x, hd = blockIdx.y;
  int q0 = blockIdx.z*64;
  int tid = threadIdx.x;
  float* sS = (float*)sm;
  float* sInv = (float*)(sm + SINV_OFF);
  {
    const uint32_t* qsrc = (const uint32_t*)g_qh + (size_t)(p*512+q0)*16 + hd*8;
    uint32_t* dq = (uint32_t*)(sm + SQ_OFF);
    for(int i=tid;i<64*8;i+=256){ int r=i>>3, dp=i&7; dq[r*12+dp] = qsrc[r*16+dp]; }
    const uint32_t* ksrc = (const uint32_t*)g_kh + (size_t)p*512*16 + hd*8;
    uint32_t* dk = (uint32_t*)(sm + SK_OFF);
    for(int i=tid;i<512*8;i+=256){ int r=i>>3, dp=i&7; dk[r*12+dp] = ksrc[r*16+dp]; }
    const uint32_t* vsrc = (const uint32_t*)g_vh + (size_t)p*512*32 + hd*16;
    uint32_t* dv = (uint32_t*)(sm + SV_OFF);
    for(int i=tid;i<512*16;i+=256){ int r=i>>4, dp=i&15; dv[r*20+dp] = vsrc[r*32+dp]; }
  }
  __syncthreads();
  int w = tid>>5, lane = tid&31;
  {
    uint32_t sQb = sptr(sm + SQ_OFF);
    uint32_t aQ[4][4];
    #pragma unroll
    for(int qt=0;qt<4;qt++){
      int row = qt*16 + (lane&7) + ((lane&8)?8:0);
      ldm_x4(aQ[qt][0],aQ[qt][1],aQ[qt][2],aQ[qt][3],
             sQb + row*48 + ((lane&16)?16:0));
    }
    uint32_t sKb = sptr(sm + SK_OFF);
    for(int kt=0;kt<8;kt++){
      int j0 = w*64 + kt*8;
      uint32_t b0,b1;
      ldm_x2(b0,b1, sKb + (j0 + (lane&7))*48 + ((lane&8)?16:0));
      #pragma unroll
      for(int qt=0;qt<4;qt++){
        float c0=0.f,c1=0.f,c2=0.f,c3=0.f;
        mma_bf16(c0,c1,c2,c3, aQ[qt][0],aQ[qt][1],aQ[qt][2],aQ[qt][3], b0,b1);
        int r = qt*16 + (lane>>2);
        int c = j0 + (lane&3)*2;
        *(float2*)(sS + r*S_PITCH_W + c) = make_float2(c0,c1);
        *(float2*)(sS + (r+8)*S_PITCH_W + c) = make_float2(c2,c3);
      }
    }
  }
  __syncthreads();
  for(int rr=0;rr<8;rr++){
    int r = w*8 + rr;
    float* Srow = sS + r*S_PITCH_W;
    float m = -1e30f;
    #pragma unroll
    for(int jj=0;jj<16;jj++) m = fmaxf(m, Srow[lane + 32*jj]);
    m = wmaxr(m);
    float ev[16]; float sum = 0.f;
    #pragma unroll
    for(int jj=0;jj<16;jj++){
      ev[jj] = __expf(0.25f*(Srow[lane + 32*jj] - m));
      sum += ev[jj];
    }
    __syncwarp();
    __nv_bfloat16* Prow = (__nv_bfloat16*)(sm + r*S_PITCH_B);
    #pragma unroll
    for(int jj=0;jj<16;jj++) Prow[lane + 32*jj] = __float2bfloat16(ev[jj]);
    sum = wred(sum);
    if(lane==0) sInv[r] = 1.0f/sum;
  }
  __syncthreads();
  {
    uint32_t sVb = sptr(sm + SV_OFF);
    uint32_t sPb = sptr(sm);
    #pragma unroll
    for(int t2=0;t2<2;t2++){
      int tt = w + t2*8;
      int qt = tt>>2, nt = tt&3;
      float c0=0.f,c1=0.f,c2=0.f,c3=0.f;
      int arow = qt*16 + (lane&7) + ((lane&8)?8:0);
      uint32_t aBase = sPb + arow*S_PITCH_B + ((lane&16)?16:0);
      uint32_t bBase = sVb + ((lane&7) + ((lane&8)?8:0))*80 + nt*16;
      #pragma unroll 4
      for(int ks=0;ks<32;ks++){
        uint32_t a0,a1,a2,a3; ldm_x4(a0,a1,a2,a3, aBase + ks*32);
        uint32_t b0,b1; ldm_x2t(b0,b1, bBase + ks*16*80);
        mma_bf16(c0,c1,c2,c3, a0,a1,a2,a3, b0,b1);
      }
      int r = qt*16 + (lane>>2);
      int c = nt*8 + (lane&3)*2;
      float i0 = sInv[r], i1 = sInv[r+8];
      float* og = g_attn + (size_t)(p*512 + q0 + r)*64 + hd*32 + c;
      og[0] = c0*i0; og[1] = c1*i0;
      og[8*64+0] = c2*i1; og[8*64+1] = c3*i1;
    }
  }
}

// ---------------- K3: proj + residual via mma (M128 K64 N64) ----------------
__global__ void __launch_bounds__(256) k_proj(const float* __restrict__ wproj){
  __shared__ __nv_bfloat16 sA[128*72];
  __shared__ __nv_bfloat16 sB[64*72];
  int tid = threadIdx.x;
  int base = blockIdx.x*128;
  int p = base>>9, tok0 = base&511;
  int bi = p/NPB; int r0 = p%NPB;
  int pt=r0/36, ph=(r0%36)/6, pw=r0%6;
  for(int i=tid;i<4096;i+=256){
    int t=i>>5, cp=i&31;
    float2 v = *(const float2*)&g_attn[((size_t)(base+t))*64 + cp*2];
    *(__nv_bfloat162*)&sA[t*72+cp*2] = bf2(v.x, v.y);
  }
  for(int i=tid;i<4096;i+=256){
    int n=i>>6, k=i&63;
    sB[n*72+k] = __float2bfloat16(wproj[k*64+n]);
  }
  __syncthreads();
  int w = tid>>5, lane = tid&31;
  int wr = w>>1, wc = w&1;
  float acc[2][4][4];
  #pragma unroll
  for(int mt=0;mt<2;mt++)
    #pragma unroll
    for(int nt=0;nt<4;nt++)
      #pragma unroll
      for(int q=0;q<4;q++) acc[mt][nt][q]=0.f;
  uint32_t sAb = sptr(sA), sBb = sptr(sB);
  #pragma unroll
  for(int ks=0;ks<4;ks++){
    uint32_t a[2][4];
    #pragma unroll
    for(int mt=0;mt<2;mt++){
      int row = wr*32 + mt*16 + (lane&7) + ((lane&8)?8:0);
      ldm_x4(a[mt][0],a[mt][1],a[mt][2],a[mt][3],
             sAb + row*144 + ks*32 + ((lane&16)?16:0));
    }
    #pragma unroll
    for(int nt=0;nt<4;nt++){
      int n0 = wc*32 + nt*8;
      uint32_t b0,b1;
      ldm_x2(b0,b1, sBb + (n0+(lane&7))*144 + ks*32 + ((lane&8)?16:0));
      #pragma unroll
      for(int mt=0;mt<2;mt++)
        mma_bf16(acc[mt][nt][0],acc[mt][nt][1],acc[mt][nt][2],acc[mt][nt][3],
                 a[mt][0],a[mt][1],a[mt][2],a[mt][3], b0,b1);
    }
  }
  #pragma unroll
  for(int mt=0;mt<2;mt++){
    #pragma unroll
    for(int nt=0;nt<4;nt++){
      int r = wr*32 + mt*16 + (lane>>2);
      int c = wc*32 + nt*8 + (lane&3)*2;
      #pragma unroll
      for(int hrow=0;hrow<2;hrow++){
        int tok = r + hrow*8;
        int pos = tok2pos(tok0+tok, pt, ph, pw);
        float2 res = *(const float2*)&g_xt[((size_t)(bi*THW+pos))*64 + c];
        float v0 = acc[mt][nt][hrow*2]   + res.x;
        float v1 = acc[mt][nt][hrow*2+1] + res.y;
        *(float2*)&g_tok2[((size_t)(base+tok))*64 + c] = make_float2(v0,v1);
      }
    }
  }
}

// ---------------- K4: gather(tables) + LN2 + fc1(mma) + gelu + fused tr -----
#define MLP1_SMEM (34816 + 18432 + 18432)
__global__ void __launch_bounds__(256) k_mlp1(const float* __restrict__ g2, const float* __restrict__ b2,
                       const float* __restrict__ fc1w, const float* __restrict__ fc1b){
  float* sX = dynsm;                         // 128*66
  float* sM = dynsm + 8448;
  float* sR = sM + 128;
  __nv_bfloat16* sYn = (__nv_bfloat16*)((char*)dynsm + 34816);  // 128*72
  __nv_bfloat16* sB  = (__nv_bfloat16*)((char*)dynsm + 34816 + 18432);
  float* cmb = dynsm;                        // reused after GEMM: 128*132 f32
  int base = blockIdx.x*128;
  int bi = base/THW; int pos0 = base%THW;
  int tid = threadIdx.x;
  int ch = tid&63, tg = tid>>6;
  for(int k=0;k<32;k++){
    int t = tg + 4*k;
    int token = base + t;
    int pos = pos0 + t;
    int tt_ = pos/(HH*WW), hh_=(pos/WW)%HH, ww_=pos%WW;
    uint32_t et = c_cov_t[tt_], eh = c_cov_h[hh_], ew = c_cov_h[ww_];
    int na=1+(et&1), nb=1+(eh&1), nc=1+(ew&1);
    int tp0=(et>>1)&7, td0=(et>>4)&7, tp1=(et>>7)&7, td1=(et>>10)&7;
    int hp0=(eh>>1)&7, hd0=(eh>>4)&7, hp1=(eh>>7)&7, hd1=(eh>>10)&7;
    int wp0=(ew>>1)&7, wd0=(ew>>4)&7, wp1=(ew>>7)&7, wd1=(ew>>10)&7;
    float acc = 0.f;
    #pragma unroll
    for(int a=0;a<2;a++){
      if(a>=na) break;
      int pa = (a? tp1:tp0)*36, da = (a? td1:td0)*64;
      #pragma unroll
      for(int b=0;b<2;b++){
        if(b>=nb) break;
        int pb = pa + (b? hp1:hp0)*6, db = da + (b? hd1:hd0)*8;
        #pragma unroll
        for(int cI=0;cI<2;cI++){
          if(cI>=nc) break;
          int pp = bi*NPB + pb + (cI? wp1:wp0);
          int tk = db + (cI? wd1:wd0);
          acc += g_tok2[((size_t)(pp*512+tk))*64 + ch];
        }
      }
    }
    float xv = acc * c_idt[tt_]*c_idh[hh_]*c_idh[ww_];
    sX[t*66+ch] = xv;
    g_xtok[(size_t)token*64+ch] = xv;
  }
  for(int i=tid;i<8192;i+=256){
    int n=i>>6, k=i&63;
    sB[n*72+k] = __float2bfloat16(fc1w[k*128+n]);
  }
  __syncthreads();
  {
    int row = tid>>1, hf = tid&1;
    float s=0.f, s2=0.f;
    #pragma unroll 8
    for(int j=hf*32;j<hf*32+32;j++){ float v=sX[row*66+j]; s+=v; s2+=v*v; }
    s  += __shfl_xor_sync(0xffffffffu, s, 1);
    s2 += __shfl_xor_sync(0xffffffffu, s2, 1);
    if(hf==0){
      float m=s*(1.0f/64.0f), var=s2*(1.0f/64.0f)-m*m;
      sM[row]=m; sR[row]=rsqrtf(var+1e-5f);
    }
  }
  __syncthreads();
  for(int i=tid;i<8192;i+=256){
    int t=i>>6, cc=i&63;
    float v = sX[t*66+cc];
    sYn[t*72+cc] = __float2bfloat16((v-sM[t])*sR[t]*g2[cc]+b2[cc]);
  }
  __syncthreads();
  int w = tid>>5, lane = tid&31;
  int wr = w>>1, wc = w&1;
  float acc[2][8][4];
  #pragma unroll
  for(int mt=0;mt<2;mt++)
    #pragma unroll
    for(int nt=0;nt<8;nt++)
      #pragma unroll
      for(int q=0;q<4;q++) acc[mt][nt][q]=0.f;
  uint32_t sAb = sptr(sYn), sBb = sptr(sB);
  #pragma unroll
  for(int ks=0;ks<4;ks++){
    uint32_t a[2][4];
    #pragma unroll
    for(int mt=0;mt<2;mt++){
      int row = wr*32 + mt*16 + (lane&7) + ((lane&8)?8:0);
      ldm_x4(a[mt][0],a[mt][1],a[mt][2],a[mt][3],
             sAb + row*144 + ks*32 + ((lane&16)?16:0));
    }
    #pragma unroll
    for(int nt=0;nt<8;nt++){
      int n0 = wc*64 + nt*8;
      uint32_t b0,b1;
      ldm_x2(b0,b1, sBb + (n0+(lane&7))*144 + ks*32 + ((lane&8)?16:0));
      #pragma unroll
      for(int mt=0;mt<2;mt++)
        mma_bf16(acc[mt][nt][0],acc[mt][nt][1],acc[mt][nt][2],acc[mt][nt][3],
                 a[mt][0],a[mt][1],a[mt][2],a[mt][3], b0,b1);
    }
  }
  __syncthreads();   // all mma smem reads done; safe to reuse smem as cm buffer
  #pragma unroll
  for(int mt=0;mt<2;mt++){
    #pragma unroll
    for(int nt=0;nt<8;nt++){
      int r = wr*32 + mt*16 + (lane>>2);
      int c = wc*64 + nt*8 + (lane&3)*2;
      float bj0 = fc1b[c], bj1 = fc1b[c+1];
      #pragma unroll
      for(int hrow=0;hrow<2;hrow++){
        int tl = r + hrow*8;
        float v0 = gelu_exact(acc[mt][nt][hrow*2]   + bj0);
        float v1 = gelu_exact(acc[mt][nt][hrow*2+1] + bj1);
        *(float2*)&g_y2[(size_t)(base+tl)*128 + c] = make_float2(v0,v1);
        cmb[c*132 + tl] = v0;
        cmb[(c+1)*132 + tl] = v1;
      }
    }
  }
  __syncthreads();
  for(int i=tid;i<16384;i+=256){
    int c=i>>7, t=i&127;
    g_y2cm[((size_t)(bi*HID+c))*THW + pos0 + t] = cmb[c*132+t];
  }
}

// ---------------- K6: depthwise 5^3 conv + bias + gelu ----------------------
__global__ void __launch_bounds__(96) k_dwconv(const float* __restrict__ dww, const float* __restrict__ dwb){
  __shared__ float si[20*10*10];
  __shared__ float swt[125];
  int blk = blockIdx.x;
  int tile = blk%36; int cb = blk/36; int ch = cb%HID; int bi = cb/HID;
  int th = tile/6, tw = tile%6;
  int tid = threadIdx.x;
  const float* src = g_y2cm + ((size_t)(bi*HID+ch))*THW;

  for(int i=tid;i<125;i+=96) swt[i] = dww[ch*125+i];
  for(int i=tid;i<2000;i+=96){
    int it = i/100, rm = i%100, ih = rm/10, iw = rm%10;
    int gt = it-2, gh = th*6+ih-2, gw = tw*6+iw-2;
    float v = 0.f;
    if(gt>=0 && gt<TT && gh>=0 && gh<HH && gw>=0 && gw<WW)
      v = src[gt*(HH*WW) + gh*WW + gw];
    si[i] = v;
  }
  __syncthreads();
  int ot = tid/6, oh = tid%6;
  float acc[6] = {0.f,0.f,0.f,0.f,0.f,0.f};
  #pragma unroll
  for(int dt=0;dt<5;dt++){
    #pragma unroll
    for(int dh=0;dh<5;dh++){
      const float* row = si + (ot+dt)*100 + (oh+dh)*10;
      float rr[10];
      #pragma unroll
      for(int i=0;i<10;i++) rr[i]=row[i];
      const float* wp = swt + dt*25 + dh*5;
      float w0=wp[0],w1=wp[1],w2=wp[2],w3=wp[3],w4=wp[4];
      #pragma unroll
      for(int ow=0;ow<6;ow++)
        acc[ow] += rr[ow]*w0 + rr[ow+1]*w1 + rr[ow+2]*w2 + rr[ow+3]*w3 + rr[ow+4]*w4;
    }
  }
  float bsv = dwb[ch];
  float* dst = g_dwcm + ((size_t)(bi*HID+ch))*THW + ot*(HH*WW) + (th*6+oh)*WW + tw*6;
  #pragma unroll
  for(int ow=0;ow<6;ow++) dst[ow] = gelu_exact(acc[ow] + bsv);
}

// ---------------- K7: fc2(mma) + residual + transposed store ----------------
#define MLP2_SMEM (68608 + 16640)
__global__ void __launch_bounds__(256) k_mlp2(const float* __restrict__ fc2w, const float* __restrict__ fc2b,
                       float* __restrict__ out){
  float* sYf = dynsm;                                          // 64*132 f32
  __nv_bfloat16* sA = (__nv_bfloat16*)((char*)dynsm + 33792);  // 64*136
  __nv_bfloat16* sB = (__nv_bfloat16*)((char*)dynsm + 51200);  // 64*136
  float* sOut = (float*)((char*)dynsm + 68608);                // 64*65
  int base = blockIdx.x*64;
  int bi = base/THW; int pos0 = base%THW;
  int tid = threadIdx.x;
  for(int i=tid;i<8192;i+=256){ int t=i>>7, j=i&127; sYf[t*132+j] = g_y2[((size_t)(base+t))*128+j]; }
  for(int i=tid;i<8192;i+=256){
    int n=i>>7, k=i&127;
    sB[n*136+k] = __float2bfloat16(fc2w[k*64+n]);
  }
  __syncthreads();
  for(int i=tid;i<8192;i+=256){ int t=i&63, j=i>>6; sYf[t*132+j] += g_dwcm[((size_t)(bi*HID+j))*THW + pos0 + t]; }
  __syncthreads();
  for(int i=tid;i<4096;i+=256){
    int t=i>>6, jp=i&63;
    float2 v = *(const float2*)&sYf[t*132 + jp*2];
    *(__nv_bfloat162*)&sA[t*136+jp*2] = bf2(v.x, v.y);
  }
  __syncthreads();
  int w = tid>>5, lane = tid&31;
  int wr = w>>1, wc = w&1;
  float acc[4][4];
  #pragma unroll
  for(int nt=0;nt<4;nt++)
    #pragma unroll
    for(int q=0;q<4;q++) acc[nt][q]=0.f;
  uint32_t sAb = sptr(sA), sBb = sptr(sB);
  #pragma unroll
  for(int ks=0;ks<8;ks++){
    uint32_t a0,a1,a2,a3;
    {
      int row = wr*16 + (lane&7) + ((lane&8)?8:0);
      ldm_x4(a0,a1,a2,a3, sAb + row*272 + ks*32 + ((lane&16)?16:0));
    }
    #pragma unroll
    for(int nt=0;nt<4;nt++){
      int n0 = wc*32 + nt*8;
      uint32_t b0,b1;
      ldm_x2(b0,b1, sBb + (n0+(lane&7))*272 + ks*32 + ((lane&8)?16:0));
      mma_bf16(acc[nt][0],acc[nt][1],acc[nt][2],acc[nt][3], a0,a1,a2,a3, b0,b1);
    }
  }
  #pragma unroll
  for(int nt=0;nt<4;nt++){
    int r = wr*16 + (lane>>2);
    int c = wc*32 + nt*8 + (lane&3)*2;
    float b0 = fc2b[c], b1 = fc2b[c+1];
    #pragma unroll
    for(int hrow=0;hrow<2;hrow++){
      int t = r + hrow*8;
      float2 res = *(const float2*)&g_xtok[((size_t)(base+t))*64 + c];
      sOut[t*65+c]   = acc[nt][hrow*2]   + b0 + res.x;
      sOut[t*65+c+1] = acc[nt][hrow*2+1] + b1 + res.y;
    }
  }
  __syncthreads();
  for(int i=tid;i<4096;i+=256){
    int t=i&63, c=i>>6;
    out[((size_t)(bi*CC+c))*THW + pos0 + t] = sOut[t*65+c];
  }
}

// ---------------- launch ----------------------------------------------------
extern "C" void kernel_launch(void* const* d_in, const int* in_sizes, int n_in,
                              void* d_out, int out_size){
  const float* x    = (const float*)d_in[0];
  const float* ln1g = (const float*)d_in[1];
  const float* ln1b = (const float*)d_in[2];
  const float* wq   = (const float*)d_in[3];
  const float* wk   = (const float*)d_in[4];
  const float* wv   = (const float*)d_in[5];
  const float* wpr  = (const float*)d_in[6];
  const float* ln2g = (const float*)d_in[7];
  const float* ln2b = (const float*)d_in[8];
  const float* fc1w = (const float*)d_in[9];
  const float* fc1b = (const float*)d_in[10];
  const float* dww  = (const float*)d_in[11];
  const float* dwb  = (const float*)d_in[12];
  const float* fc2w = (const float*)d_in[13];
  const float* fc2b = (const float*)d_in[14];
  float* out = (float*)d_out;

  cudaFuncSetAttribute(k_attn, cudaFuncAttributeMaxDynamicSharedMemorySize, AT_SMEM);
  cudaFuncSetAttribute(k_mlp1, cudaFuncAttributeMaxDynamicSharedMemorySize, MLP1_SMEM);
  cudaFuncSetAttribute(k_mlp2, cudaFuncAttributeMaxDynamicSharedMemorySize, MLP2_SMEM);

  k_ln1<<<dim3(THW/32, BB), 256>>>(x, ln1g, ln1b);
  k_qkv<<<NROW/128, 256>>>(wq, wk, wv);
  k_attn<<<dim3(NP, HEADS, 8), 256, AT_SMEM>>>();
  k_proj<<<NROW/128, 256>>>(wpr);
  k_mlp1<<<NTOK2/128, 256, MLP1_SMEM>>>(ln2g, ln2b, fc1w, fc1b);
  k_dwconv<<<BB*HID*36, 96>>>(dww, dwb);
  k_mlp2<<<NTOK2/64, 256, MLP2_SMEM>>>(fc2w, fc2b, out);
}

// round 13
// speedup vs baseline: 3.4717x; 1.0421x over previous
#include <cuda_runtime.h>
#include <cuda_bf16.h>
#include <math.h>
#include <stdint.h>

#define BB 2
#define CC 64
#define TT 16
#define HH 36
#define WW 36
#define THW (TT*HH*WW)
#define PS 8
#define NT 3
#define NH 6
#define NW 6
#define NPB (NT*NH*NW)
#define NP (BB*NPB)
#define TOKN 512
#define NROW (NP*TOKN)
#define HEADS 2
#define HID 128
#define NTOK2 (BB*THW)

__constant__ int   c_st_t[3] = {0,6,8};
__constant__ int   c_st_h[6] = {0,6,12,18,24,28};
__constant__ float c_idt[16] = {1,1,1,1,1,1,0.5f,0.5f,0.5f,0.5f,1,1,1,1,1,1};
__constant__ float c_idh[36] = {1,1,1,1,1,1, 0.5f,0.5f, 1,1,1,1, 0.5f,0.5f,
                                1,1,1,1, 0.5f,0.5f, 1,1,1,1, 0.5f,0.5f,
                                1,1, 0.5f,0.5f, 1,1,1,1,1,1};
// coverage tables: bit0=n-1, bits1-3=p0, bits4-6=d0, bits7-9=p1, bits10-12=d1
__constant__ uint32_t c_cov_t[16] = {0,16,32,48,64,80,225,1265,291,1331,2371,3411,4451,5491,100,116};
__constant__ uint32_t c_cov_h[36] = {0,16,32,48,64,80,225,1265,34,50,66,82,355,1395,36,52,68,84,
                                     485,1525,38,54,70,86,615,1655,40,56,713,1753,2793,3833,74,90,106,122};

__device__ float g_xt[NTOK2*64];               // x token-major grid
__device__ __nv_bfloat16 g_qh[NTOK2*32];       // grid q (both heads)
__device__ __nv_bfloat16 g_kh[NTOK2*32];       // grid k
__device__ __nv_bfloat16 g_vh[NTOK2*64];       // grid v
__device__ __nv_bfloat16 g_attnh[NROW*64];     // attention out (bf16)
__device__ float g_tok2[NROW*64];
__device__ float g_xtok[NTOK2*64];
__device__ float g_y2[NTOK2*128];
__device__ float g_y2cm[BB*HID*THW];
__device__ float g_dwcm[BB*HID*THW];

extern __shared__ float dynsm[];

__device__ __forceinline__ uint32_t sptr(const void* p){
  return (uint32_t)__cvta_generic_to_shared(p);
}
__device__ __forceinline__ void ldm_x4(uint32_t& r0, uint32_t& r1, uint32_t& r2, uint32_t& r3, uint32_t addr){
  asm volatile("ldmatrix.sync.aligned.m8n8.x4.shared.b16 {%0,%1,%2,%3},[%4];"
    : "=r"(r0),"=r"(r1),"=r"(r2),"=r"(r3) : "r"(addr));
}
__device__ __forceinline__ void ldm_x2(uint32_t& r0, uint32_t& r1, uint32_t addr){
  asm volatile("ldmatrix.sync.aligned.m8n8.x2.shared.b16 {%0,%1},[%2];"
    : "=r"(r0),"=r"(r1) : "r"(addr));
}
__device__ __forceinline__ void ldm_x2t(uint32_t& r0, uint32_t& r1, uint32_t addr){
  asm volatile("ldmatrix.sync.aligned.m8n8.x2.trans.shared.b16 {%0,%1},[%2];"
    : "=r"(r0),"=r"(r1) : "r"(addr));
}
__device__ __forceinline__ void mma_bf16(float& c0, float& c1, float& c2, float& c3,
    uint32_t a0, uint32_t a1, uint32_t a2, uint32_t a3, uint32_t b0, uint32_t b1){
  asm volatile("mma.sync.aligned.m16n8k16.row.col.f32.bf16.bf16.f32 "
    "{%0,%1,%2,%3},{%4,%5,%6,%7},{%8,%9},{%0,%1,%2,%3};"
    : "+f"(c0),"+f"(c1),"+f"(c2),"+f"(c3)
    : "r"(a0),"r"(a1),"r"(a2),"r"(a3),"r"(b0),"r"(b1));
}
__device__ __forceinline__ float wred(float v){
  #pragma unroll
  for(int o=16;o;o>>=1) v += __shfl_xor_sync(0xffffffffu, v, o);
  return v;
}
__device__ __forceinline__ float wmaxr(float v){
  #pragma unroll
  for(int o=16;o;o>>=1) v = fmaxf(v, __shfl_xor_sync(0xffffffffu, v, o));
  return v;
}
__device__ __forceinline__ float gelu_exact(float x){
  return 0.5f*x*(1.0f + erff(x*0.70710678118654752f));
}
__device__ __forceinline__ int tok2pos(int tok, int pt, int ph, int pw){
  int tt = tok>>6, hh = (tok>>3)&7, ww = tok&7;
  return (c_st_t[pt]+tt)*(HH*WW) + (c_st_h[ph]+hh)*WW + (c_st_h[pw]+ww);
}
__device__ __forceinline__ __nv_bfloat162 bf2(float a, float b){
  return __floats2bfloat162_rn(a, b);
}

// ---------------- K1: fused LN1 + QKV GEMM on the grid (M128 K64 N128) ------
// 324 blocks, 256 threads; grid tokens (position-dependent only).
#define LQKV_SMEM (34816 + 18432 + 18432)
__global__ void __launch_bounds__(256) k_ln1qkv(const float* __restrict__ x,
                      const float* __restrict__ g1, const float* __restrict__ b1,
                      const float* __restrict__ wq, const float* __restrict__ wk,
                      const float* __restrict__ wv){
  float* sX = dynsm;                         // 128*66 f32
  float* sM = dynsm + 8448;
  float* sR = sM + 128;
  __nv_bfloat16* sA = (__nv_bfloat16*)((char*)dynsm + 34816);  // 128*72
  __nv_bfloat16* sB = (__nv_bfloat16*)((char*)dynsm + 53248);  // 128*72
  int gbase = blockIdx.x*128;
  int bi = gbase/THW; int pos0 = gbase%THW;
  int tid = threadIdx.x;
  for(int i=tid;i<8192;i+=256){
    int ch=i>>7, t=i&127;
    sX[t*66+ch] = x[((size_t)(bi*64+ch))*THW + pos0 + t];
  }
  for(int i=tid;i<8192;i+=256){
    int n=i>>6, k=i&63;
    float wval;
    if(n<32)       wval = wq[k*32+n];
    else if(n<64)  wval = wk[k*32+(n-32)];
    else           wval = wv[k*64+(n-64)];
    sB[n*72+k] = __float2bfloat16(wval);
  }
  __syncthreads();
  for(int i=tid;i<8192;i+=256){
    int t=i>>6, ch=i&63;
    g_xt[((size_t)(gbase+t))*64+ch] = sX[t*66+ch];
  }
  {
    int row = tid>>1, hf = tid&1;
    float s=0.f, s2=0.f;
    #pragma unroll 8
    for(int j=hf*32;j<hf*32+32;j++){ float v=sX[row*66+j]; s+=v; s2+=v*v; }
    s  += __shfl_xor_sync(0xffffffffu, s, 1);
    s2 += __shfl_xor_sync(0xffffffffu, s2, 1);
    if(hf==0){
      float m=s*(1.0f/64.0f), var=s2*(1.0f/64.0f)-m*m;
      sM[row]=m; sR[row]=rsqrtf(var+1e-5f);
    }
  }
  __syncthreads();
  for(int i=tid;i<8192;i+=256){
    int t=i>>6, cc=i&63;
    float v = sX[t*66+cc];
    sA[t*72+cc] = __float2bfloat16((v-sM[t])*sR[t]*g1[cc]+b1[cc]);
  }
  __syncthreads();
  int w = tid>>5, lane = tid&31;
  int wr = w>>1, wc = w&1;
  float acc[2][8][4];
  #pragma unroll
  for(int mt=0;mt<2;mt++)
    #pragma unroll
    for(int nt=0;nt<8;nt++)
      #pragma unroll
      for(int q=0;q<4;q++) acc[mt][nt][q]=0.f;
  uint32_t sAb = sptr(sA), sBb = sptr(sB);
  #pragma unroll
  for(int ks=0;ks<4;ks++){
    uint32_t a[2][4];
    #pragma unroll
    for(int mt=0;mt<2;mt++){
      int row = wr*32 + mt*16 + (lane&7) + ((lane&8)?8:0);
      ldm_x4(a[mt][0],a[mt][1],a[mt][2],a[mt][3],
             sAb + row*144 + ks*32 + ((lane&16)?16:0));
    }
    #pragma unroll
    for(int nt=0;nt<8;nt++){
      int n0 = wc*64 + nt*8;
      uint32_t b0,b1;
      ldm_x2(b0,b1, sBb + (n0+(lane&7))*144 + ks*32 + ((lane&8)?16:0));
      #pragma unroll
      for(int mt=0;mt<2;mt++)
        mma_bf16(acc[mt][nt][0],acc[mt][nt][1],acc[mt][nt][2],acc[mt][nt][3],
                 a[mt][0],a[mt][1],a[mt][2],a[mt][3], b0,b1);
    }
  }
  #pragma unroll
  for(int mt=0;mt<2;mt++){
    #pragma unroll
    for(int nt=0;nt<8;nt++){
      int r = wr*32 + mt*16 + (lane>>2);
      int c = wc*64 + nt*8 + (lane&3)*2;
      #pragma unroll
      for(int hrow=0;hrow<2;hrow++){
        int rg = gbase + r + hrow*8;
        float v0 = acc[mt][nt][hrow*2], v1 = acc[mt][nt][hrow*2+1];
        if(c<32)       *(__nv_bfloat162*)&g_qh[(size_t)rg*32 + c]      = bf2(v0,v1);
        else if(c<64)  *(__nv_bfloat162*)&g_kh[(size_t)rg*32 + (c-32)] = bf2(v0,v1);
        else           *(__nv_bfloat162*)&g_vh[(size_t)rg*64 + (c-64)] = bf2(v0,v1);
      }
    }
  }
}

// ---------------- K2: attention via mma.sync bf16 (gathered grid q/k/v) -----
#define S_PITCH_W 524
#define S_PITCH_B 2096
#define SK_OFF 134144
#define SV_OFF 158720
#define SQ_OFF 199680
#define SINV_OFF 202752
#define AT_SMEM 203008
__global__ void __launch_bounds__(256,1) k_attn(){
  char* sm = (char*)dynsm;
  int p = blockIdx.x, hd = blockIdx.y;
  int q0 = blockIdx.z*64;
  int tid = threadIdx.x;
  float* sS = (float*)sm;
  float* sInv = (float*)(sm + SINV_OFF);
  int bi = p/NPB; int rp = p%NPB;
  int pt=rp/36, ph=(rp%36)/6, pw=rp%6;
  int gb = bi*THW;
  {
    const uint32_t* qg = (const uint32_t*)g_qh;
    uint32_t* dq = (uint32_t*)(sm + SQ_OFF);
    for(int i=tid;i<64*8;i+=256){
      int r=i>>3, dp=i&7;
      int pos = tok2pos(q0+r, pt, ph, pw);
      dq[r*12+dp] = qg[((size_t)(gb+pos))*16 + hd*8 + dp];
    }
    const uint32_t* kg = (const uint32_t*)g_kh;
    uint32_t* dk = (uint32_t*)(sm + SK_OFF);
    for(int i=tid;i<512*8;i+=256){
      int r=i>>3, dp=i&7;
      int pos = tok2pos(r, pt, ph, pw);
      dk[r*12+dp] = kg[((size_t)(gb+pos))*16 + hd*8 + dp];
    }
    const uint32_t* vg = (const uint32_t*)g_vh;
    uint32_t* dv = (uint32_t*)(sm + SV_OFF);
    for(int i=tid;i<512*16;i+=256){
      int r=i>>4, dp=i&15;
      int pos = tok2pos(r, pt, ph, pw);
      dv[r*20+dp] = vg[((size_t)(gb+pos))*32 + hd*16 + dp];
    }
  }
  __syncthreads();
  int w = tid>>5, lane = tid&31;
  {
    uint32_t sQb = sptr(sm + SQ_OFF);
    uint32_t aQ[4][4];
    #pragma unroll
    for(int qt=0;qt<4;qt++){
      int row = qt*16 + (lane&7) + ((lane&8)?8:0);
      ldm_x4(aQ[qt][0],aQ[qt][1],aQ[qt][2],aQ[qt][3],
             sQb + row*48 + ((lane&16)?16:0));
    }
    uint32_t sKb = sptr(sm + SK_OFF);
    for(int kt=0;kt<8;kt++){
      int j0 = w*64 + kt*8;
      uint32_t b0,b1;
      ldm_x2(b0,b1, sKb + (j0 + (lane&7))*48 + ((lane&8)?16:0));
      #pragma unroll
      for(int qt=0;qt<4;qt++){
        float c0=0.f,c1=0.f,c2=0.f,c3=0.f;
        mma_bf16(c0,c1,c2,c3, aQ[qt][0],aQ[qt][1],aQ[qt][2],aQ[qt][3], b0,b1);
        int r = qt*16 + (lane>>2);
        int c = j0 + (lane&3)*2;
        *(float2*)(sS + r*S_PITCH_W + c) = make_float2(c0,c1);
        *(float2*)(sS + (r+8)*S_PITCH_W + c) = make_float2(c2,c3);
      }
    }
  }
  __syncthreads();
  for(int rr=0;rr<8;rr++){
    int r = w*8 + rr;
    float* Srow = sS + r*S_PITCH_W;
    float m = -1e30f;
    #pragma unroll
    for(int jj=0;jj<16;jj++) m = fmaxf(m, Srow[lane + 32*jj]);
    m = wmaxr(m);
    float ev[16]; float sum = 0.f;
    #pragma unroll
    for(int jj=0;jj<16;jj++){
      ev[jj] = __expf(0.25f*(Srow[lane + 32*jj] - m));
      sum += ev[jj];
    }
    __syncwarp();
    __nv_bfloat16* Prow = (__nv_bfloat16*)(sm + r*S_PITCH_B);
    #pragma unroll
    for(int jj=0;jj<16;jj++) Prow[lane + 32*jj] = __float2bfloat16(ev[jj]);
    sum = wred(sum);
    if(lane==0) sInv[r] = 1.0f/sum;
  }
  __syncthreads();
  {
    uint32_t sVb = sptr(sm + SV_OFF);
    uint32_t sPb = sptr(sm);
    #pragma unroll
    for(int t2=0;t2<2;t2++){
      int tt = w + t2*8;
      int qt = tt>>2, nt = tt&3;
      float c0=0.f,c1=0.f,c2=0.f,c3=0.f;
      int arow = qt*16 + (lane&7) + ((lane&8)?8:0);
      uint32_t aBase = sPb + arow*S_PITCH_B + ((lane&16)?16:0);
      uint32_t bBase = sVb + ((lane&7) + ((lane&8)?8:0))*80 + nt*16;
      #pragma unroll 4
      for(int ks=0;ks<32;ks++){
        uint32_t a0,a1,a2,a3; ldm_x4(a0,a1,a2,a3, aBase + ks*32);
        uint32_t b0,b1; ldm_x2t(b0,b1, bBase + ks*16*80);
        mma_bf16(c0,c1,c2,c3, a0,a1,a2,a3, b0,b1);
      }
      int r = qt*16 + (lane>>2);
      int c = nt*8 + (lane&3)*2;
      float i0 = sInv[r], i1 = sInv[r+8];
      __nv_bfloat16* og = g_attnh + (size_t)(p*512 + q0 + r)*64 + hd*32 + c;
      *(__nv_bfloat162*)og = bf2(c0*i0, c1*i0);
      *(__nv_bfloat162*)(og + 8*64) = bf2(c2*i1, c3*i1);
    }
  }
}

// ---------------- K3: proj + residual via mma (M128 K64 N64) ----------------
__global__ void __launch_bounds__(256) k_proj(const float* __restrict__ wproj){
  __shared__ __nv_bfloat16 sA[128*72];
  __shared__ __nv_bfloat16 sB[64*72];
  int tid = threadIdx.x;
  int base = blockIdx.x*128;
  int p = base>>9, tok0 = base&511;
  int bi = p/NPB; int r0 = p%NPB;
  int pt=r0/36, ph=(r0%36)/6, pw=r0%6;
  const uint32_t* ag = (const uint32_t*)g_attnh;
  for(int i=tid;i<4096;i+=256){
    int t=i>>5, cp=i&31;
    ((uint32_t*)sA)[t*36+cp] = ag[((size_t)(base+t))*32 + cp];
  }
  for(int i=tid;i<4096;i+=256){
    int n=i>>6, k=i&63;
    sB[n*72+k] = __float2bfloat16(wproj[k*64+n]);
  }
  __syncthreads();
  int w = tid>>5, lane = tid&31;
  int wr = w>>1, wc = w&1;
  float acc[2][4][4];
  #pragma unroll
  for(int mt=0;mt<2;mt++)
    #pragma unroll
    for(int nt=0;nt<4;nt++)
      #pragma unroll
      for(int q=0;q<4;q++) acc[mt][nt][q]=0.f;
  uint32_t sAb = sptr(sA), sBb = sptr(sB);
  #pragma unroll
  for(int ks=0;ks<4;ks++){
    uint32_t a[2][4];
    #pragma unroll
    for(int mt=0;mt<2;mt++){
      int row = wr*32 + mt*16 + (lane&7) + ((lane&8)?8:0);
      ldm_x4(a[mt][0],a[mt][1],a[mt][2],a[mt][3],
             sAb + row*144 + ks*32 + ((lane&16)?16:0));
    }
    #pragma unroll
    for(int nt=0;nt<4;nt++){
      int n0 = wc*32 + nt*8;
      uint32_t b0,b1;
      ldm_x2(b0,b1, sBb + (n0+(lane&7))*144 + ks*32 + ((lane&8)?16:0));
      #pragma unroll
      for(int mt=0;mt<2;mt++)
        mma_bf16(acc[mt][nt][0],acc[mt][nt][1],acc[mt][nt][2],acc[mt][nt][3],
                 a[mt][0],a[mt][1],a[mt][2],a[mt][3], b0,b1);
    }
  }
  #pragma unroll
  for(int mt=0;mt<2;mt++){
    #pragma unroll
    for(int nt=0;nt<4;nt++){
      int r = wr*32 + mt*16 + (lane>>2);
      int c = wc*32 + nt*8 + (lane&3)*2;
      #pragma unroll
      for(int hrow=0;hrow<2;hrow++){
        int tok = r + hrow*8;
        int pos = tok2pos(tok0+tok, pt, ph, pw);
        float2 res = *(const float2*)&g_xt[((size_t)(bi*THW+pos))*64 + c];
        float v0 = acc[mt][nt][hrow*2]   + res.x;
        float v1 = acc[mt][nt][hrow*2+1] + res.y;
        *(float2*)&g_tok2[((size_t)(base+tok))*64 + c] = make_float2(v0,v1);
      }
    }
  }
}

// ---------------- K4: gather(tables) + LN2 + fc1(mma) + gelu + fused tr -----
#define MLP1_SMEM (34816 + 18432 + 18432)
__global__ void __launch_bounds__(256) k_mlp1(const float* __restrict__ g2, const float* __restrict__ b2,
                       const float* __restrict__ fc1w, const float* __restrict__ fc1b){
  float* sX = dynsm;                         // 128*66
  float* sM = dynsm + 8448;
  float* sR = sM + 128;
  __nv_bfloat16* sYn = (__nv_bfloat16*)((char*)dynsm + 34816);  // 128*72
  __nv_bfloat16* sB  = (__nv_bfloat16*)((char*)dynsm + 34816 + 18432);
  float* cmb = dynsm;                        // reused after GEMM: 128*132 f32
  int base = blockIdx.x*128;
  int bi = base/THW; int pos0 = base%THW;
  int tid = threadIdx.x;
  int ch = tid&63, tg = tid>>6;
  for(int k=0;k<32;k++){
    int t = tg + 4*k;
    int token = base + t;
    int pos = pos0 + t;
    int tt_ = pos/(HH*WW), hh_=(pos/WW)%HH, ww_=pos%WW;
    uint32_t et = c_cov_t[tt_], eh = c_cov_h[hh_], ew = c_cov_h[ww_];
    int na=1+(et&1), nb=1+(eh&1), nc=1+(ew&1);
    int tp0=(et>>1)&7, td0=(et>>4)&7, tp1=(et>>7)&7, td1=(et>>10)&7;
    int hp0=(eh>>1)&7, hd0=(eh>>4)&7, hp1=(eh>>7)&7, hd1=(eh>>10)&7;
    int wp0=(ew>>1)&7, wd0=(ew>>4)&7, wp1=(ew>>7)&7, wd1=(ew>>10)&7;
    float acc = 0.f;
    #pragma unroll
    for(int a=0;a<2;a++){
      if(a>=na) break;
      int pa = (a? tp1:tp0)*36, da = (a? td1:td0)*64;
      #pragma unroll
      for(int b=0;b<2;b++){
        if(b>=nb) break;
        int pb = pa + (b? hp1:hp0)*6, db = da + (b? hd1:hd0)*8;
        #pragma unroll
        for(int cI=0;cI<2;cI++){
          if(cI>=nc) break;
          int pp = bi*NPB + pb + (cI? wp1:wp0);
          int tk = db + (cI? wd1:wd0);
          acc += g_tok2[((size_t)(pp*512+tk))*64 + ch];
        }
      }
    }
    float xv = acc * c_idt[tt_]*c_idh[hh_]*c_idh[ww_];
    sX[t*66+ch] = xv;
    g_xtok[(size_t)token*64+ch] = xv;
  }
  for(int i=tid;i<8192;i+=256){
    int n=i>>6, k=i&63;
    sB[n*72+k] = __float2bfloat16(fc1w[k*128+n]);
  }
  __syncthreads();
  {
    int row = tid>>1, hf = tid&1;
    float s=0.f, s2=0.f;
    #pragma unroll 8
    for(int j=hf*32;j<hf*32+32;j++){ float v=sX[row*66+j]; s+=v; s2+=v*v; }
    s  += __shfl_xor_sync(0xffffffffu, s, 1);
    s2 += __shfl_xor_sync(0xffffffffu, s2, 1);
    if(hf==0){
      float m=s*(1.0f/64.0f), var=s2*(1.0f/64.0f)-m*m;
      sM[row]=m; sR[row]=rsqrtf(var+1e-5f);
    }
  }
  __syncthreads();
  for(int i=tid;i<8192;i+=256){
    int t=i>>6, cc=i&63;
    float v = sX[t*66+cc];
    sYn[t*72+cc] = __float2bfloat16((v-sM[t])*sR[t]*g2[cc]+b2[cc]);
  }
  __syncthreads();
  int w = tid>>5, lane = tid&31;
  int wr = w>>1, wc = w&1;
  float acc[2][8][4];
  #pragma unroll
  for(int mt=0;mt<2;mt++)
    #pragma unroll
    for(int nt=0;nt<8;nt++)
      #pragma unroll
      for(int q=0;q<4;q++) acc[mt][nt][q]=0.f;
  uint32_t sAb = sptr(sYn), sBb = sptr(sB);
  #pragma unroll
  for(int ks=0;ks<4;ks++){
    uint32_t a[2][4];
    #pragma unroll
    for(int mt=0;mt<2;mt++){
      int row = wr*32 + mt*16 + (lane&7) + ((lane&8)?8:0);
      ldm_x4(a[mt][0],a[mt][1],a[mt][2],a[mt][3],
             sAb + row*144 + ks*32 + ((lane&16)?16:0));
    }
    #pragma unroll
    for(int nt=0;nt<8;nt++){
      int n0 = wc*64 + nt*8;
      uint32_t b0,b1;
      ldm_x2(b0,b1, sBb + (n0+(lane&7))*144 + ks*32 + ((lane&8)?16:0));
      #pragma unroll
      for(int mt=0;mt<2;mt++)
        mma_bf16(acc[mt][nt][0],acc[mt][nt][1],acc[mt][nt][2],acc[mt][nt][3],
                 a[mt][0],a[mt][1],a[mt][2],a[mt][3], b0,b1);
    }
  }
  __syncthreads();   // all mma smem reads done; safe to reuse smem as cm buffer
  #pragma unroll
  for(int mt=0;mt<2;mt++){
    #pragma unroll
    for(int nt=0;nt<8;nt++){
      int r = wr*32 + mt*16 + (lane>>2);
      int c = wc*64 + nt*8 + (lane&3)*2;
      float bj0 = fc1b[c], bj1 = fc1b[c+1];
      #pragma unroll
      for(int hrow=0;hrow<2;hrow++){
        int tl = r + hrow*8;
        float v0 = gelu_exact(acc[mt][nt][hrow*2]   + bj0);
        float v1 = gelu_exact(acc[mt][nt][hrow*2+1] + bj1);
        *(float2*)&g_y2[(size_t)(base+tl)*128 + c] = make_float2(v0,v1);
        cmb[c*132 + tl] = v0;
        cmb[(c+1)*132 + tl] = v1;
      }
    }
  }
  __syncthreads();
  for(int i=tid;i<16384;i+=256){
    int c=i>>7, t=i&127;
    g_y2cm[((size_t)(bi*HID+c))*THW + pos0 + t] = cmb[c*132+t];
  }
}

// ---------------- K6: depthwise 5^3 conv + bias + gelu ----------------------
__global__ void __launch_bounds__(96) k_dwconv(const float* __restrict__ dww, const float* __restrict__ dwb){
  __shared__ float si[20*10*10];
  __shared__ float swt[125];
  int blk = blockIdx.x;
  int tile = blk%36; int cb = blk/36; int ch = cb%HID; int bi = cb/HID;
  int th = tile/6, tw = tile%6;
  int tid = threadIdx.x;
  const float* src = g_y2cm + ((size_t)(bi*HID+ch))*THW;

  for(int i=tid;i<125;i+=96) swt[i] = dww[ch*125+i];
  for(int i=tid;i<2000;i+=96){
    int it = i/100, rm = i%100, ih = rm/10, iw = rm%10;
    int gt = it-2, gh = th*6+ih-2, gw = tw*6+iw-2;
    float v = 0.f;
    if(gt>=0 && gt<TT && gh>=0 && gh<HH && gw>=0 && gw<WW)
      v = src[gt*(HH*WW) + gh*WW + gw];
    si[i] = v;
  }
  __syncthreads();
  int ot = tid/6, oh = tid%6;
  float acc[6] = {0.f,0.f,0.f,0.f,0.f,0.f};
  #pragma unroll
  for(int dt=0;dt<5;dt++){
    #pragma unroll
    for(int dh=0;dh<5;dh++){
      const float* row = si + (ot+dt)*100 + (oh+dh)*10;
      float rr[10];
      #pragma unroll
      for(int i=0;i<10;i++) rr[i]=row[i];
      const float* wp = swt + dt*25 + dh*5;
      float w0=wp[0],w1=wp[1],w2=wp[2],w3=wp[3],w4=wp[4];
      #pragma unroll
      for(int ow=0;ow<6;ow++)
        acc[ow] += rr[ow]*w0 + rr[ow+1]*w1 + rr[ow+2]*w2 + rr[ow+3]*w3 + rr[ow+4]*w4;
    }
  }
  float bsv = dwb[ch];
  float* dst = g_dwcm + ((size_t)(bi*HID+ch))*THW + ot*(HH*WW) + (th*6+oh)*WW + tw*6;
  #pragma unroll
  for(int ow=0;ow<6;ow++) dst[ow] = gelu_exact(acc[ow] + bsv);
}

// ---------------- K7: fc2(mma) + residual + transposed store ----------------
#define MLP2_SMEM (68608 + 16640)
__global__ void __launch_bounds__(256) k_mlp2(const float* __restrict__ fc2w, const float* __restrict__ fc2b,
                       float* __restrict__ out){
  float* sYf = dynsm;                                          // 64*132 f32
  __nv_bfloat16* sA = (__nv_bfloat16*)((char*)dynsm + 33792);  // 64*136
  __nv_bfloat16* sB = (__nv_bfloat16*)((char*)dynsm + 51200);  // 64*136
  float* sOut = (float*)((char*)dynsm + 68608);                // 64*65
  int base = blockIdx.x*64;
  int bi = base/THW; int pos0 = base%THW;
  int tid = threadIdx.x;
  for(int i=tid;i<8192;i+=256){ int t=i>>7, j=i&127; sYf[t*132+j] = g_y2[((size_t)(base+t))*128+j]; }
  for(int i=tid;i<8192;i+=256){
    int n=i>>7, k=i&127;
    sB[n*136+k] = __float2bfloat16(fc2w[k*64+n]);
  }
  __syncthreads();
  for(int i=tid;i<8192;i+=256){ int t=i&63, j=i>>6; sYf[t*132+j] += g_dwcm[((size_t)(bi*HID+j))*THW + pos0 + t]; }
  __syncthreads();
  for(int i=tid;i<4096;i+=256){
    int t=i>>6, jp=i&63;
    float2 v = *(const float2*)&sYf[t*132 + jp*2];
    *(__nv_bfloat162*)&sA[t*136+jp*2] = bf2(v.x, v.y);
  }
  __syncthreads();
  int w = tid>>5, lane = tid&31;
  int wr = w>>1, wc = w&1;
  float acc[4][4];
  #pragma unroll
  for(int nt=0;nt<4;nt++)
    #pragma unroll
    for(int q=0;q<4;q++) acc[nt][q]=0.f;
  uint32_t sAb = sptr(sA), sBb = sptr(sB);
  #pragma unroll
  for(int ks=0;ks<8;ks++){
    uint32_t a0,a1,a2,a3;
    {
      int row = wr*16 + (lane&7) + ((lane&8)?8:0);
      ldm_x4(a0,a1,a2,a3, sAb + row*272 + ks*32 + ((lane&16)?16:0));
    }
    #pragma unroll
    for(int nt=0;nt<4;nt++){
      int n0 = wc*32 + nt*8;
      uint32_t b0,b1;
      ldm_x2(b0,b1, sBb + (n0+(lane&7))*272 + ks*32 + ((lane&8)?16:0));
      mma_bf16(acc[nt][0],acc[nt][1],acc[nt][2],acc[nt][3], a0,a1,a2,a3, b0,b1);
    }
  }
  #pragma unroll
  for(int nt=0;nt<4;nt++){
    int r = wr*16 + (lane>>2);
    int c = wc*32 + nt*8 + (lane&3)*2;
    float b0 = fc2b[c], b1 = fc2b[c+1];
    #pragma unroll
    for(int hrow=0;hrow<2;hrow++){
      int t = r + hrow*8;
      float2 res = *(const float2*)&g_xtok[((size_t)(base+t))*64 + c];
      sOut[t*65+c]   = acc[nt][hrow*2]   + b0 + res.x;
      sOut[t*65+c+1] = acc[nt][hrow*2+1] + b1 + res.y;
    }
  }
  __syncthreads();
  for(int i=tid;i<4096;i+=256){
    int t=i&63, c=i>>6;
    out[((size_t)(bi*CC+c))*THW + pos0 + t] = sOut[t*65+c];
  }
}

// ---------------- launch ----------------------------------------------------
extern "C" void kernel_launch(void* const* d_in, const int* in_sizes, int n_in,
                              void* d_out, int out_size){
  const float* x    = (const float*)d_in[0];
  const float* ln1g = (const float*)d_in[1];
  const float* ln1b = (const float*)d_in[2];
  const float* wq   = (const float*)d_in[3];
  const float* wk   = (const float*)d_in[4];
  const float* wv   = (const float*)d_in[5];
  const float* wpr  = (const float*)d_in[6];
  const float* ln2g = (const float*)d_in[7];
  const float* ln2b = (const float*)d_in[8];
  const float* fc1w = (const float*)d_in[9];
  const float* fc1b = (const float*)d_in[10];
  const float* dww  = (const float*)d_in[11];
  const float* dwb  = (const float*)d_in[12];
  const float* fc2w = (const float*)d_in[13];
  const float* fc2b = (const float*)d_in[14];
  float* out = (float*)d_out;

  cudaFuncSetAttribute(k_ln1qkv, cudaFuncAttributeMaxDynamicSharedMemorySize, LQKV_SMEM);
  cudaFuncSetAttribute(k_attn, cudaFuncAttributeMaxDynamicSharedMemorySize, AT_SMEM);
  cudaFuncSetAttribute(k_mlp1, cudaFuncAttributeMaxDynamicSharedMemorySize, MLP1_SMEM);
  cudaFuncSetAttribute(k_mlp2, cudaFuncAttributeMaxDynamicSharedMemorySize, MLP2_SMEM);

  k_ln1qkv<<<NTOK2/128, 256, LQKV_SMEM>>>(x, ln1g, ln1b, wq, wk, wv);
  k_attn<<<dim3(NP, HEADS, 8), 256, AT_SMEM>>>();
  k_proj<<<NROW/128, 256>>>(wpr);
  k_mlp1<<<NTOK2/128, 256, MLP1_SMEM>>>(ln2g, ln2b, fc1w, fc1b);
  k_dwconv<<<BB*HID*36, 96>>>(dww, dwb);
  k_mlp2<<<NTOK2/64, 256, MLP2_SMEM>>>(fc2w, fc2b, out);
}

// round 15
// speedup vs baseline: 3.6812x; 1.0603x over previous
#include <cuda_runtime.h>
#include <cuda_bf16.h>
#include <math.h>
#include <stdint.h>

#define BB 2
#define CC 64
#define TT 16
#define HH 36
#define WW 36
#define THW (TT*HH*WW)
#define PS 8
#define NT 3
#define NH 6
#define NW 6
#define NPB (NT*NH*NW)
#define NP (BB*NPB)
#define TOKN 512
#define NROW (NP*TOKN)
#define HEADS 2
#define HID 128
#define NTOK2 (BB*THW)

__constant__ int   c_st_t[3] = {0,6,8};
__constant__ int   c_st_h[6] = {0,6,12,18,24,28};
__constant__ float c_idt[16] = {1,1,1,1,1,1,0.5f,0.5f,0.5f,0.5f,1,1,1,1,1,1};
__constant__ float c_idh[36] = {1,1,1,1,1,1, 0.5f,0.5f, 1,1,1,1, 0.5f,0.5f,
                                1,1,1,1, 0.5f,0.5f, 1,1,1,1, 0.5f,0.5f,
                                1,1, 0.5f,0.5f, 1,1,1,1,1,1};
// coverage tables: bit0=n-1, bits1-3=p0, bits4-6=d0, bits7-9=p1, bits10-12=d1
__constant__ uint32_t c_cov_t[16] = {0,16,32,48,64,80,225,1265,291,1331,2371,3411,4451,5491,100,116};
__constant__ uint32_t c_cov_h[36] = {0,16,32,48,64,80,225,1265,34,50,66,82,355,1395,36,52,68,84,
                                     485,1525,38,54,70,86,615,1655,40,56,713,1753,2793,3833,74,90,106,122};

__device__ float g_xt[NTOK2*64];               // x token-major grid
__device__ __nv_bfloat16 g_qh[NTOK2*32];       // grid q (both heads)
__device__ __nv_bfloat16 g_kh[NTOK2*32];       // grid k
__device__ __nv_bfloat16 g_vh[NTOK2*64];       // grid v
__device__ __nv_bfloat16 g_attnh[NROW*64];     // attention out (bf16)
__device__ float g_tok2[NROW*64];
__device__ float g_xtok[NTOK2*64];
__device__ float g_y2cm[BB*HID*THW];
__device__ float g_dwcm[BB*HID*THW];

extern __shared__ float dynsm[];

__device__ __forceinline__ uint32_t sptr(const void* p){
  return (uint32_t)__cvta_generic_to_shared(p);
}
__device__ __forceinline__ void ldm_x4(uint32_t& r0, uint32_t& r1, uint32_t& r2, uint32_t& r3, uint32_t addr){
  asm volatile("ldmatrix.sync.aligned.m8n8.x4.shared.b16 {%0,%1,%2,%3},[%4];"
    : "=r"(r0),"=r"(r1),"=r"(r2),"=r"(r3) : "r"(addr));
}
__device__ __forceinline__ void ldm_x2(uint32_t& r0, uint32_t& r1, uint32_t addr){
  asm volatile("ldmatrix.sync.aligned.m8n8.x2.shared.b16 {%0,%1},[%2];"
    : "=r"(r0),"=r"(r1) : "r"(addr));
}
__device__ __forceinline__ void ldm_x2t(uint32_t& r0, uint32_t& r1, uint32_t addr){
  asm volatile("ldmatrix.sync.aligned.m8n8.x2.trans.shared.b16 {%0,%1},[%2];"
    : "=r"(r0),"=r"(r1) : "r"(addr));
}
__device__ __forceinline__ void mma_bf16(float& c0, float& c1, float& c2, float& c3,
    uint32_t a0, uint32_t a1, uint32_t a2, uint32_t a3, uint32_t b0, uint32_t b1){
  asm volatile("mma.sync.aligned.m16n8k16.row.col.f32.bf16.bf16.f32 "
    "{%0,%1,%2,%3},{%4,%5,%6,%7},{%8,%9},{%0,%1,%2,%3};"
    : "+f"(c0),"+f"(c1),"+f"(c2),"+f"(c3)
    : "r"(a0),"r"(a1),"r"(a2),"r"(a3),"r"(b0),"r"(b1));
}
__device__ __forceinline__ float wred(float v){
  #pragma unroll
  for(int o=16;o;o>>=1) v += __shfl_xor_sync(0xffffffffu, v, o);
  return v;
}
__device__ __forceinline__ float wmaxr(float v){
  #pragma unroll
  for(int o=16;o;o>>=1) v = fmaxf(v, __shfl_xor_sync(0xffffffffu, v, o));
  return v;
}
__device__ __forceinline__ float gelu_exact(float x){
  return 0.5f*x*(1.0f + erff(x*0.70710678118654752f));
}
__device__ __forceinline__ int tok2pos(int tok, int pt, int ph, int pw){
  int tt = tok>>6, hh = (tok>>3)&7, ww = tok&7;
  return (c_st_t[pt]+tt)*(HH*WW) + (c_st_h[ph]+hh)*WW + (c_st_h[pw]+ww);
}
__device__ __forceinline__ __nv_bfloat162 bf2(float a, float b){
  return __floats2bfloat162_rn(a, b);
}

// ---------------- K1: fused LN1 + QKV GEMM on the grid (M128 K64 N128) ------
#define LQKV_SMEM (34816 + 18432 + 18432)
__global__ void __launch_bounds__(256) k_ln1qkv(const float* __restrict__ x,
                      const float* __restrict__ g1, const float* __restrict__ b1,
                      const float* __restrict__ wq, const float* __restrict__ wk,
                      const float* __restrict__ wv){
  float* sX = dynsm;                         // 128*66 f32
  float* sM = dynsm + 8448;
  float* sR = sM + 128;
  __nv_bfloat16* sA = (__nv_bfloat16*)((char*)dynsm + 34816);  // 128*72
  __nv_bfloat16* sB = (__nv_bfloat16*)((char*)dynsm + 53248);  // 128*72
  int gbase = blockIdx.x*128;
  int bi = gbase/THW; int pos0 = gbase%THW;
  int tid = threadIdx.x;
  for(int i=tid;i<8192;i+=256){
    int ch=i>>7, t=i&127;
    sX[t*66+ch] = x[((size_t)(bi*64+ch))*THW + pos0 + t];
  }
  for(int i=tid;i<8192;i+=256){
    int n=i>>6, k=i&63;
    float wval;
    if(n<32)       wval = wq[k*32+n];
    else if(n<64)  wval = wk[k*32+(n-32)];
    else           wval = wv[k*64+(n-64)];
    sB[n*72+k] = __float2bfloat16(wval);
  }
  __syncthreads();
  for(int i=tid;i<8192;i+=256){
    int t=i>>6, ch=i&63;
    g_xt[((size_t)(gbase+t))*64+ch] = sX[t*66+ch];
  }
  {
    int row = tid>>1, hf = tid&1;
    float s=0.f, s2=0.f;
    #pragma unroll 8
    for(int j=hf*32;j<hf*32+32;j++){ float v=sX[row*66+j]; s+=v; s2+=v*v; }
    s  += __shfl_xor_sync(0xffffffffu, s, 1);
    s2 += __shfl_xor_sync(0xffffffffu, s2, 1);
    if(hf==0){
      float m=s*(1.0f/64.0f), var=s2*(1.0f/64.0f)-m*m;
      sM[row]=m; sR[row]=rsqrtf(var+1e-5f);
    }
  }
  __syncthreads();
  for(int i=tid;i<8192;i+=256){
    int t=i>>6, cc=i&63;
    float v = sX[t*66+cc];
    sA[t*72+cc] = __float2bfloat16((v-sM[t])*sR[t]*g1[cc]+b1[cc]);
  }
  __syncthreads();
  int w = tid>>5, lane = tid&31;
  int wr = w>>1, wc = w&1;
  float acc[2][8][4];
  #pragma unroll
  for(int mt=0;mt<2;mt++)
    #pragma unroll
    for(int nt=0;nt<8;nt++)
      #pragma unroll
      for(int q=0;q<4;q++) acc[mt][nt][q]=0.f;
  uint32_t sAb = sptr(sA), sBb = sptr(sB);
  #pragma unroll
  for(int ks=0;ks<4;ks++){
    uint32_t a[2][4];
    #pragma unroll
    for(int mt=0;mt<2;mt++){
      int row = wr*32 + mt*16 + (lane&7) + ((lane&8)?8:0);
      ldm_x4(a[mt][0],a[mt][1],a[mt][2],a[mt][3],
             sAb + row*144 + ks*32 + ((lane&16)?16:0));
    }
    #pragma unroll
    for(int nt=0;nt<8;nt++){
      int n0 = wc*64 + nt*8;
      uint32_t b0,b1;
      ldm_x2(b0,b1, sBb + (n0+(lane&7))*144 + ks*32 + ((lane&8)?16:0));
      #pragma unroll
      for(int mt=0;mt<2;mt++)
        mma_bf16(acc[mt][nt][0],acc[mt][nt][1],acc[mt][nt][2],acc[mt][nt][3],
                 a[mt][0],a[mt][1],a[mt][2],a[mt][3], b0,b1);
    }
  }
  #pragma unroll
  for(int mt=0;mt<2;mt++){
    #pragma unroll
    for(int nt=0;nt<8;nt++){
      int r = wr*32 + mt*16 + (lane>>2);
      int c = wc*64 + nt*8 + (lane&3)*2;
      #pragma unroll
      for(int hrow=0;hrow<2;hrow++){
        int rg = gbase + r + hrow*8;
        float v0 = acc[mt][nt][hrow*2], v1 = acc[mt][nt][hrow*2+1];
        if(c<32)       *(__nv_bfloat162*)&g_qh[(size_t)rg*32 + c]      = bf2(v0,v1);
        else if(c<64)  *(__nv_bfloat162*)&g_kh[(size_t)rg*32 + (c-32)] = bf2(v0,v1);
        else           *(__nv_bfloat162*)&g_vh[(size_t)rg*64 + (c-64)] = bf2(v0,v1);
      }
    }
  }
}

// ---------------- K2: attention via mma.sync bf16 (gathered grid q/k/v) -----
#define S_PITCH_W 524
#define S_PITCH_B 2096
#define SK_OFF 134144
#define SV_OFF 158720
#define SQ_OFF 199680
#define SINV_OFF 202752
#define AT_SMEM 203008
__global__ void __launch_bounds__(256,1) k_attn(){
  char* sm = (char*)dynsm;
  int p = blockIdx.x, hd = blockIdx.y;
  int q0 = blockIdx.z*64;
  int tid = threadIdx.x;
  float* sS = (float*)sm;
  float* sInv = (float*)(sm + SINV_OFF);
  int bi = p/NPB; int rp = p%NPB;
  int pt=rp/36, ph=(rp%36)/6, pw=rp%6;
  int gb = bi*THW;
  {
    const uint32_t* qg = (const uint32_t*)g_qh;
    uint32_t* dq = (uint32_t*)(sm + SQ_OFF);
    for(int i=tid;i<64*8;i+=256){
      int r=i>>3, dp=i&7;
      int pos = tok2pos(q0+r, pt, ph, pw);
      dq[r*12+dp] = qg[((size_t)(gb+pos))*16 + hd*8 + dp];
    }
    const uint32_t* kg = (const uint32_t*)g_kh;
    uint32_t* dk = (uint32_t*)(sm + SK_OFF);
    for(int i=tid;i<512*8;i+=256){
      int r=i>>3, dp=i&7;
      int pos = tok2pos(r, pt, ph, pw);
      dk[r*12+dp] = kg[((size_t)(gb+pos))*16 + hd*8 + dp];
    }
    const uint32_t* vg = (const uint32_t*)g_vh;
    uint32_t* dv = (uint32_t*)(sm + SV_OFF);
    for(int i=tid;i<512*16;i+=256){
      int r=i>>4, dp=i&15;
      int pos = tok2pos(r, pt, ph, pw);
      dv[r*20+dp] = vg[((size_t)(gb+pos))*32 + hd*16 + dp];
    }
  }
  __syncthreads();
  int w = tid>>5, lane = tid&31;
  {
    uint32_t sQb = sptr(sm + SQ_OFF);
    uint32_t aQ[4][4];
    #pragma unroll
    for(int qt=0;qt<4;qt++){
      int row = qt*16 + (lane&7) + ((lane&8)?8:0);
      ldm_x4(aQ[qt][0],aQ[qt][1],aQ[qt][2],aQ[qt][3],
             sQb + row*48 + ((lane&16)?16:0));
    }
    uint32_t sKb = sptr(sm + SK_OFF);
    for(int kt=0;kt<8;kt++){
      int j0 = w*64 + kt*8;
      uint32_t b0,b1;
      ldm_x2(b0,b1, sKb + (j0 + (lane&7))*48 + ((lane&8)?16:0));
      #pragma unroll
      for(int qt=0;qt<4;qt++){
        float c0=0.f,c1=0.f,c2=0.f,c3=0.f;
        mma_bf16(c0,c1,c2,c3, aQ[qt][0],aQ[qt][1],aQ[qt][2],aQ[qt][3], b0,b1);
        int r = qt*16 + (lane>>2);
        int c = j0 + (lane&3)*2;
        *(float2*)(sS + r*S_PITCH_W + c) = make_float2(c0,c1);
        *(float2*)(sS + (r+8)*S_PITCH_W + c) = make_float2(c2,c3);
      }
    }
  }
  __syncthreads();
  for(int rr=0;rr<8;rr++){
    int r = w*8 + rr;
    float* Srow = sS + r*S_PITCH_W;
    float m = -1e30f;
    #pragma unroll
    for(int jj=0;jj<16;jj++) m = fmaxf(m, Srow[lane + 32*jj]);
    m = wmaxr(m);
    float ev[16]; float sum = 0.f;
    #pragma unroll
    for(int jj=0;jj<16;jj++){
      ev[jj] = __expf(0.25f*(Srow[lane + 32*jj] - m));
      sum += ev[jj];
    }
    __syncwarp();
    __nv_bfloat16* Prow = (__nv_bfloat16*)(sm + r*S_PITCH_B);
    #pragma unroll
    for(int jj=0;jj<16;jj++) Prow[lane + 32*jj] = __float2bfloat16(ev[jj]);
    sum = wred(sum);
    if(lane==0) sInv[r] = 1.0f/sum;
  }
  __syncthreads();
  {
    uint32_t sVb = sptr(sm + SV_OFF);
    uint32_t sPb = sptr(sm);
    #pragma unroll
    for(int t2=0;t2<2;t2++){
      int tt = w + t2*8;
      int qt = tt>>2, nt = tt&3;
      float c0=0.f,c1=0.f,c2=0.f,c3=0.f;
      int arow = qt*16 + (lane&7) + ((lane&8)?8:0);
      uint32_t aBase = sPb + arow*S_PITCH_B + ((lane&16)?16:0);
      uint32_t bBase = sVb + ((lane&7) + ((lane&8)?8:0))*80 + nt*16;
      #pragma unroll 4
      for(int ks=0;ks<32;ks++){
        uint32_t a0,a1,a2,a3; ldm_x4(a0,a1,a2,a3, aBase + ks*32);
        uint32_t b0,b1; ldm_x2t(b0,b1, bBase + ks*16*80);
        mma_bf16(c0,c1,c2,c3, a0,a1,a2,a3, b0,b1);
      }
      int r = qt*16 + (lane>>2);
      int c = nt*8 + (lane&3)*2;
      float i0 = sInv[r], i1 = sInv[r+8];
      __nv_bfloat16* og = g_attnh + (size_t)(p*512 + q0 + r)*64 + hd*32 + c;
      *(__nv_bfloat162*)og = bf2(c0*i0, c1*i0);
      *(__nv_bfloat162*)(og + 8*64) = bf2(c2*i1, c3*i1);
    }
  }
}

// ---------------- K3: proj + residual via mma (M128 K64 N64) ----------------
__global__ void __launch_bounds__(256) k_proj(const float* __restrict__ wproj){
  __shared__ __nv_bfloat16 sA[128*72];
  __shared__ __nv_bfloat16 sB[64*72];
  int tid = threadIdx.x;
  int base = blockIdx.x*128;
  int p = base>>9, tok0 = base&511;
  int bi = p/NPB; int r0 = p%NPB;
  int pt=r0/36, ph=(r0%36)/6, pw=r0%6;
  const uint32_t* ag = (const uint32_t*)g_attnh;
  for(int i=tid;i<4096;i+=256){
    int t=i>>5, cp=i&31;
    ((uint32_t*)sA)[t*36+cp] = ag[((size_t)(base+t))*32 + cp];
  }
  for(int i=tid;i<4096;i+=256){
    int n=i>>6, k=i&63;
    sB[n*72+k] = __float2bfloat16(wproj[k*64+n]);
  }
  __syncthreads();
  int w = tid>>5, lane = tid&31;
  int wr = w>>1, wc = w&1;
  float acc[2][4][4];
  #pragma unroll
  for(int mt=0;mt<2;mt++)
    #pragma unroll
    for(int nt=0;nt<4;nt++)
      #pragma unroll
      for(int q=0;q<4;q++) acc[mt][nt][q]=0.f;
  uint32_t sAb = sptr(sA), sBb = sptr(sB);
  #pragma unroll
  for(int ks=0;ks<4;ks++){
    uint32_t a[2][4];
    #pragma unroll
    for(int mt=0;mt<2;mt++){
      int row = wr*32 + mt*16 + (lane&7) + ((lane&8)?8:0);
      ldm_x4(a[mt][0],a[mt][1],a[mt][2],a[mt][3],
             sAb + row*144 + ks*32 + ((lane&16)?16:0));
    }
    #pragma unroll
    for(int nt=0;nt<4;nt++){
      int n0 = wc*32 + nt*8;
      uint32_t b0,b1;
      ldm_x2(b0,b1, sBb + (n0+(lane&7))*144 + ks*32 + ((lane&8)?16:0));
      #pragma unroll
      for(int mt=0;mt<2;mt++)
        mma_bf16(acc[mt][nt][0],acc[mt][nt][1],acc[mt][nt][2],acc[mt][nt][3],
                 a[mt][0],a[mt][1],a[mt][2],a[mt][3], b0,b1);
    }
  }
  #pragma unroll
  for(int mt=0;mt<2;mt++){
    #pragma unroll
    for(int nt=0;nt<4;nt++){
      int r = wr*32 + mt*16 + (lane>>2);
      int c = wc*32 + nt*8 + (lane&3)*2;
      #pragma unroll
      for(int hrow=0;hrow<2;hrow++){
        int tok = r + hrow*8;
        int pos = tok2pos(tok0+tok, pt, ph, pw);
        float2 res = *(const float2*)&g_xt[((size_t)(bi*THW+pos))*64 + c];
        float v0 = acc[mt][nt][hrow*2]   + res.x;
        float v1 = acc[mt][nt][hrow*2+1] + res.y;
        *(float2*)&g_tok2[((size_t)(base+tok))*64 + c] = make_float2(v0,v1);
      }
    }
  }
}

// ---------------- K3b: patch-reverse gather (high-parallelism) --------------
__global__ void __launch_bounds__(256) k_gather(){
  int idx = blockIdx.x*256 + threadIdx.x;       // over NTOK2*64
  int token = idx>>6, ch = idx&63;
  int bi = token/THW; int pos = token%THW;
  int tt_ = pos/(HH*WW), hh_=(pos/WW)%HH, ww_=pos%WW;
  uint32_t et = c_cov_t[tt_], eh = c_cov_h[hh_], ew = c_cov_h[ww_];
  int na=1+(et&1), nb=1+(eh&1), nc=1+(ew&1);
  int tp0=(et>>1)&7, td0=(et>>4)&7, tp1=(et>>7)&7, td1=(et>>10)&7;
  int hp0=(eh>>1)&7, hd0=(eh>>4)&7, hp1=(eh>>7)&7, hd1=(eh>>10)&7;
  int wp0=(ew>>1)&7, wd0=(ew>>4)&7, wp1=(ew>>7)&7, wd1=(ew>>10)&7;
  float acc = 0.f;
  #pragma unroll
  for(int a=0;a<2;a++){
    if(a>=na) break;
    int pa = (a? tp1:tp0)*36, da = (a? td1:td0)*64;
    #pragma unroll
    for(int b=0;b<2;b++){
      if(b>=nb) break;
      int pb = pa + (b? hp1:hp0)*6, db = da + (b? hd1:hd0)*8;
      #pragma unroll
      for(int cI=0;cI<2;cI++){
        if(cI>=nc) break;
        int pp = bi*NPB + pb + (cI? wp1:wp0);
        int tk = db + (cI? wd1:wd0);
        acc += g_tok2[((size_t)(pp*512+tk))*64 + ch];
      }
    }
  }
  g_xtok[(size_t)token*64+ch] = acc * c_idt[tt_]*c_idh[hh_]*c_idh[ww_];
}

// ---------------- K4: LN2 + fc1(mma) + gelu + fused transpose ---------------
#define MLP1_SMEM (34816 + 18432 + 18432)
__global__ void __launch_bounds__(256) k_mlp1(const float* __restrict__ g2, const float* __restrict__ b2,
                       const float* __restrict__ fc1w, const float* __restrict__ fc1b){
  float* sX = dynsm;                         // 128*66
  float* sM = dynsm + 8448;
  float* sR = sM + 128;
  __nv_bfloat16* sYn = (__nv_bfloat16*)((char*)dynsm + 34816);  // 128*72
  __nv_bfloat16* sB  = (__nv_bfloat16*)((char*)dynsm + 34816 + 18432);
  float* cmb = dynsm;                        // reused after GEMM: 128*132 f32
  int base = blockIdx.x*128;
  int bi = base/THW; int pos0 = base%THW;
  int tid = threadIdx.x;
  for(int i=tid;i<8192;i+=256){
    int t=i>>6, ch=i&63;
    sX[t*66+ch] = g_xtok[((size_t)(base+t))*64 + ch];
  }
  for(int i=tid;i<8192;i+=256){
    int n=i>>6, k=i&63;
    sB[n*72+k] = __float2bfloat16(fc1w[k*128+n]);
  }
  __syncthreads();
  {
    int row = tid>>1, hf = tid&1;
    float s=0.f, s2=0.f;
    #pragma unroll 8
    for(int j=hf*32;j<hf*32+32;j++){ float v=sX[row*66+j]; s+=v; s2+=v*v; }
    s  += __shfl_xor_sync(0xffffffffu, s, 1);
    s2 += __shfl_xor_sync(0xffffffffu, s2, 1);
    if(hf==0){
      float m=s*(1.0f/64.0f), var=s2*(1.0f/64.0f)-m*m;
      sM[row]=m; sR[row]=rsqrtf(var+1e-5f);
    }
  }
  __syncthreads();
  for(int i=tid;i<8192;i+=256){
    int t=i>>6, cc=i&63;
    float v = sX[t*66+cc];
    sYn[t*72+cc] = __float2bfloat16((v-sM[t])*sR[t]*g2[cc]+b2[cc]);
  }
  __syncthreads();
  int w = tid>>5, lane = tid&31;
  int wr = w>>1, wc = w&1;
  float acc[2][8][4];
  #pragma unroll
  for(int mt=0;mt<2;mt++)
    #pragma unroll
    for(int nt=0;nt<8;nt++)
      #pragma unroll
      for(int q=0;q<4;q++) acc[mt][nt][q]=0.f;
  uint32_t sAb = sptr(sYn), sBb = sptr(sB);
  #pragma unroll
  for(int ks=0;ks<4;ks++){
    uint32_t a[2][4];
    #pragma unroll
    for(int mt=0;mt<2;mt++){
      int row = wr*32 + mt*16 + (lane&7) + ((lane&8)?8:0);
      ldm_x4(a[mt][0],a[mt][1],a[mt][2],a[mt][3],
             sAb + row*144 + ks*32 + ((lane&16)?16:0));
    }
    #pragma unroll
    for(int nt=0;nt<8;nt++){
      int n0 = wc*64 + nt*8;
      uint32_t b0,b1;
      ldm_x2(b0,b1, sBb + (n0+(lane&7))*144 + ks*32 + ((lane&8)?16:0));
      #pragma unroll
      for(int mt=0;mt<2;mt++)
        mma_bf16(acc[mt][nt][0],acc[mt][nt][1],acc[mt][nt][2],acc[mt][nt][3],
                 a[mt][0],a[mt][1],a[mt][2],a[mt][3], b0,b1);
    }
  }
  __syncthreads();   // all mma smem reads done; safe to reuse smem as cm buffer
  #pragma unroll
  for(int mt=0;mt<2;mt++){
    #pragma unroll
    for(int nt=0;nt<8;nt++){
      int r = wr*32 + mt*16 + (lane>>2);
      int c = wc*64 + nt*8 + (lane&3)*2;
      float bj0 = fc1b[c], bj1 = fc1b[c+1];
      #pragma unroll
      for(int hrow=0;hrow<2;hrow++){
        int tl = r + hrow*8;
        cmb[c*132 + tl]     = gelu_exact(acc[mt][nt][hrow*2]   + bj0);
        cmb[(c+1)*132 + tl] = gelu_exact(acc[mt][nt][hrow*2+1] + bj1);
      }
    }
  }
  __syncthreads();
  for(int i=tid;i<16384;i+=256){
    int c=i>>7, t=i&127;
    g_y2cm[((size_t)(bi*HID+c))*THW + pos0 + t] = cmb[c*132+t];
  }
}

// ---------------- K6: depthwise 5^3 conv + bias + gelu ----------------------
__global__ void __launch_bounds__(96) k_dwconv(const float* __restrict__ dww, const float* __restrict__ dwb){
  __shared__ float si[20*10*10];
  __shared__ float swt[125];
  int blk = blockIdx.x;
  int tile = blk%36; int cb = blk/36; int ch = cb%HID; int bi = cb/HID;
  int th = tile/6, tw = tile%6;
  int tid = threadIdx.x;
  const float* src = g_y2cm + ((size_t)(bi*HID+ch))*THW;

  for(int i=tid;i<125;i+=96) swt[i] = dww[ch*125+i];
  for(int i=tid;i<2000;i+=96){
    int it = i/100, rm = i%100, ih = rm/10, iw = rm%10;
    int gt = it-2, gh = th*6+ih-2, gw = tw*6+iw-2;
    float v = 0.f;
    if(gt>=0 && gt<TT && gh>=0 && gh<HH && gw>=0 && gw<WW)
      v = src[gt*(HH*WW) + gh*WW + gw];
    si[i] = v;
  }
  __syncthreads();
  int ot = tid/6, oh = tid%6;
  float acc[6] = {0.f,0.f,0.f,0.f,0.f,0.f};
  #pragma unroll
  for(int dt=0;dt<5;dt++){
    #pragma unroll
    for(int dh=0;dh<5;dh++){
      const float* row = si + (ot+dt)*100 + (oh+dh)*10;
      float rr[10];
      #pragma unroll
      for(int i=0;i<10;i++) rr[i]=row[i];
      const float* wp = swt + dt*25 + dh*5;
      float w0=wp[0],w1=wp[1],w2=wp[2],w3=wp[3],w4=wp[4];
      #pragma unroll
      for(int ow=0;ow<6;ow++)
        acc[ow] += rr[ow]*w0 + rr[ow+1]*w1 + rr[ow+2]*w2 + rr[ow+3]*w3 + rr[ow+4]*w4;
    }
  }
  float bsv = dwb[ch];
  float* dst = g_dwcm + ((size_t)(bi*HID+ch))*THW + ot*(HH*WW) + (th*6+oh)*WW + tw*6;
  #pragma unroll
  for(int ow=0;ow<6;ow++) dst[ow] = gelu_exact(acc[ow] + bsv);
}

// ---------------- K7: fc2(mma) + residual + transposed store ----------------
#define MLP2_SMEM (68608 + 16640)
__global__ void __launch_bounds__(256) k_mlp2(const float* __restrict__ fc2w, const float* __restrict__ fc2b,
                       float* __restrict__ out){
  float* sYf = dynsm;                                          // 64*132 f32
  __nv_bfloat16* sA = (__nv_bfloat16*)((char*)dynsm + 33792);  // 64*136
  __nv_bfloat16* sB = (__nv_bfloat16*)((char*)dynsm + 51200);  // 64*136
  float* sOut = (float*)((char*)dynsm + 68608);                // 64*65
  int base = blockIdx.x*64;
  int bi = base/THW; int pos0 = base%THW;
  int tid = threadIdx.x;
  for(int i=tid;i<8192;i+=256){
    int t=i&63, j=i>>6;
    sYf[t*132+j] = g_y2cm[((size_t)(bi*HID+j))*THW + pos0 + t]
                 + g_dwcm[((size_t)(bi*HID+j))*THW + pos0 + t];
  }
  for(int i=tid;i<8192;i+=256){
    int n=i>>7, k=i&127;
    sB[n*136+k] = __float2bfloat16(fc2w[k*64+n]);
  }
  __syncthreads();
  for(int i=tid;i<4096;i+=256){
    int t=i>>6, jp=i&63;
    float2 v = *(const float2*)&sYf[t*132 + jp*2];
    *(__nv_bfloat162*)&sA[t*136+jp*2] = bf2(v.x, v.y);
  }
  __syncthreads();
  int w = tid>>5, lane = tid&31;
  int wr = w>>1, wc = w&1;
  float acc[4][4];
  #pragma unroll
  for(int nt=0;nt<4;nt++)
    #pragma unroll
    for(int q=0;q<4;q++) acc[nt][q]=0.f;
  uint32_t sAb = sptr(sA), sBb = sptr(sB);
  #pragma unroll
  for(int ks=0;ks<8;ks++){
    uint32_t a0,a1,a2,a3;
    {
      int row = wr*16 + (lane&7) + ((lane&8)?8:0);
      ldm_x4(a0,a1,a2,a3, sAb + row*272 + ks*32 + ((lane&16)?16:0));
    }
    #pragma unroll
    for(int nt=0;nt<4;nt++){
      int n0 = wc*32 + nt*8;
      uint32_t b0,b1;
      ldm_x2(b0,b1, sBb + (n0+(lane&7))*272 + ks*32 + ((lane&8)?16:0));
      mma_bf16(acc[nt][0],acc[nt][1],acc[nt][2],acc[nt][3], a0,a1,a2,a3, b0,b1);
    }
  }
  #pragma unroll
  for(int nt=0;nt<4;nt++){
    int r = wr*16 + (lane>>2);
    int c = wc*32 + nt*8 + (lane&3)*2;
    float b0 = fc2b[c], b1 = fc2b[c+1];
    #pragma unroll
    for(int hrow=0;hrow<2;hrow++){
      int t = r + hrow*8;
      float2 res = *(const float2*)&g_xtok[((size_t)(base+t))*64 + c];
      sOut[t*65+c]   = acc[nt][hrow*2]   + b0 + res.x;
      sOut[t*65+c+1] = acc[nt][hrow*2+1] + b1 + res.y;
    }
  }
  __syncthreads();
  for(int i=tid;i<4096;i+=256){
    int t=i&63, c=i>>6;
    out[((size_t)(bi*CC+c))*THW + pos0 + t] = sOut[t*65+c];
  }
}

// ---------------- launch ----------------------------------------------------
extern "C" void kernel_launch(void* const* d_in, const int* in_sizes, int n_in,
                              void* d_out, int out_size){
  const float* x    = (const float*)d_in[0];
  const float* ln1g = (const float*)d_in[1];
  const float* ln1b = (const float*)d_in[2];
  const float* wq   = (const float*)d_in[3];
  const float* wk   = (const float*)d_in[4];
  const float* wv   = (const float*)d_in[5];
  const float* wpr  = (const float*)d_in[6];
  const float* ln2g = (const float*)d_in[7];
  const float* ln2b = (const float*)d_in[8];
  const float* fc1w = (const float*)d_in[9];
  const float* fc1b = (const float*)d_in[10];
  const float* dww  = (const float*)d_in[11];
  const float* dwb  = (const float*)d_in[12];
  const float* fc2w = (const float*)d_in[13];
  const float* fc2b = (const float*)d_in[14];
  float* out = (float*)d_out;

  cudaFuncSetAttribute(k_ln1qkv, cudaFuncAttributeMaxDynamicSharedMemorySize, LQKV_SMEM);
  cudaFuncSetAttribute(k_attn, cudaFuncAttributeMaxDynamicSharedMemorySize, AT_SMEM);
  cudaFuncSetAttribute(k_mlp1, cudaFuncAttributeMaxDynamicSharedMemorySize, MLP1_SMEM);
  cudaFuncSetAttribute(k_mlp2, cudaFuncAttributeMaxDynamicSharedMemorySize, MLP2_SMEM);

  k_ln1qkv<<<NTOK2/128, 256, LQKV_SMEM>>>(x, ln1g, ln1b, wq, wk, wv);
  k_attn<<<dim3(NP, HEADS, 8), 256, AT_SMEM>>>();
  k_proj<<<NROW/128, 256>>>(wpr);
  k_gather<<<NTOK2*64/256, 256>>>();
  k_mlp1<<<NTOK2/128, 256, MLP1_SMEM>>>(ln2g, ln2b, fc1w, fc1b);
  k_dwconv<<<BB*HID*36, 96>>>(dww, dwb);
  k_mlp2<<<NTOK2/64, 256, MLP2_SMEM>>>(fc2w, fc2b, out);
}

// round 16
// speedup vs baseline: 4.6924x; 1.2747x over previous
#include <cuda_runtime.h>
#include <cuda_bf16.h>
#include <math.h>
#include <stdint.h>

#define BB 2
#define CC 64
#define TT 16
#define HH 36
#define WW 36
#define THW (TT*HH*WW)
#define PS 8
#define NT 3
#define NH 6
#define NW 6
#define NPB (NT*NH*NW)
#define NP (BB*NPB)
#define TOKN 512
#define NROW (NP*TOKN)
#define HEADS 2
#define HID 128
#define NTOK2 (BB*THW)

__constant__ int   c_st_t[3] = {0,6,8};
__constant__ int   c_st_h[6] = {0,6,12,18,24,28};
__constant__ float c_idt[16] = {1,1,1,1,1,1,0.5f,0.5f,0.5f,0.5f,1,1,1,1,1,1};
__constant__ float c_idh[36] = {1,1,1,1,1,1, 0.5f,0.5f, 1,1,1,1, 0.5f,0.5f,
                                1,1,1,1, 0.5f,0.5f, 1,1,1,1, 0.5f,0.5f,
                                1,1, 0.5f,0.5f, 1,1,1,1,1,1};
// coverage tables: bit0=n-1, bits1-3=p0, bits4-6=d0, bits7-9=p1, bits10-12=d1
__constant__ uint32_t c_cov_t[16] = {0,16,32,48,64,80,225,1265,291,1331,2371,3411,4451,5491,100,116};
__constant__ uint32_t c_cov_h[36] = {0,16,32,48,64,80,225,1265,34,50,66,82,355,1395,36,52,68,84,
                                     485,1525,38,54,70,86,615,1655,40,56,713,1753,2793,3833,74,90,106,122};

__device__ float g_xt[NTOK2*64];               // x token-major grid
__device__ __nv_bfloat16 g_qh[NTOK2*32];       // grid q (both heads)
__device__ __nv_bfloat16 g_kh[NTOK2*32];       // grid k
__device__ __nv_bfloat16 g_vh[NTOK2*64];       // grid v
__device__ __nv_bfloat16 g_attnh[NROW*64];     // attention out (bf16)
__device__ float g_tok2[NROW*64];
__device__ float g_xtok[NTOK2*64];
__device__ float g_y2cm[BB*HID*THW];
__device__ float g_dwcm[BB*HID*THW];

extern __shared__ float dynsm[];

__device__ __forceinline__ uint32_t sptr(const void* p){
  return (uint32_t)__cvta_generic_to_shared(p);
}
__device__ __forceinline__ void ldm_x4(uint32_t& r0, uint32_t& r1, uint32_t& r2, uint32_t& r3, uint32_t addr){
  asm volatile("ldmatrix.sync.aligned.m8n8.x4.shared.b16 {%0,%1,%2,%3},[%4];"
    : "=r"(r0),"=r"(r1),"=r"(r2),"=r"(r3) : "r"(addr));
}
__device__ __forceinline__ void ldm_x2(uint32_t& r0, uint32_t& r1, uint32_t addr){
  asm volatile("ldmatrix.sync.aligned.m8n8.x2.shared.b16 {%0,%1},[%2];"
    : "=r"(r0),"=r"(r1) : "r"(addr));
}
__device__ __forceinline__ void ldm_x2t(uint32_t& r0, uint32_t& r1, uint32_t addr){
  asm volatile("ldmatrix.sync.aligned.m8n8.x2.trans.shared.b16 {%0,%1},[%2];"
    : "=r"(r0),"=r"(r1) : "r"(addr));
}
__device__ __forceinline__ void mma_bf16(float& c0, float& c1, float& c2, float& c3,
    uint32_t a0, uint32_t a1, uint32_t a2, uint32_t a3, uint32_t b0, uint32_t b1){
  asm volatile("mma.sync.aligned.m16n8k16.row.col.f32.bf16.bf16.f32 "
    "{%0,%1,%2,%3},{%4,%5,%6,%7},{%8,%9},{%0,%1,%2,%3};"
    : "+f"(c0),"+f"(c1),"+f"(c2),"+f"(c3)
    : "r"(a0),"r"(a1),"r"(a2),"r"(a3),"r"(b0),"r"(b1));
}
__device__ __forceinline__ float wred(float v){
  #pragma unroll
  for(int o=16;o;o>>=1) v += __shfl_xor_sync(0xffffffffu, v, o);
  return v;
}
__device__ __forceinline__ float wmaxr(float v){
  #pragma unroll
  for(int o=16;o;o>>=1) v = fmaxf(v, __shfl_xor_sync(0xffffffffu, v, o));
  return v;
}
__device__ __forceinline__ float gelu_exact(float x){
  return 0.5f*x*(1.0f + erff(x*0.70710678118654752f));
}
__device__ __forceinline__ int tok2pos(int tok, int pt, int ph, int pw){
  int tt = tok>>6, hh = (tok>>3)&7, ww = tok&7;
  return (c_st_t[pt]+tt)*(HH*WW) + (c_st_h[ph]+hh)*WW + (c_st_h[pw]+ww);
}
__device__ __forceinline__ __nv_bfloat162 bf2(float a, float b){
  return __floats2bfloat162_rn(a, b);
}

// ---------------- K1: fused LN1 + QKV GEMM on the grid (M128 K64 N128) ------
#define LQKV_SMEM (34816 + 18432 + 18432)
__global__ void __launch_bounds__(256) k_ln1qkv(const float* __restrict__ x,
                      const float* __restrict__ g1, const float* __restrict__ b1,
                      const float* __restrict__ wq, const float* __restrict__ wk,
                      const float* __restrict__ wv){
  float* sX = dynsm;                         // 128*66 f32
  float* sM = dynsm + 8448;
  float* sR = sM + 128;
  __nv_bfloat16* sA = (__nv_bfloat16*)((char*)dynsm + 34816);  // 128*72
  __nv_bfloat16* sB = (__nv_bfloat16*)((char*)dynsm + 53248);  // 128*72
  int gbase = blockIdx.x*128;
  int bi = gbase/THW; int pos0 = gbase%THW;
  int tid = threadIdx.x;
  for(int i=tid;i<8192;i+=256){
    int ch=i>>7, t=i&127;
    sX[t*66+ch] = x[((size_t)(bi*64+ch))*THW + pos0 + t];
  }
  for(int i=tid;i<8192;i+=256){
    int n=i>>6, k=i&63;
    float wval;
    if(n<32)       wval = wq[k*32+n];
    else if(n<64)  wval = wk[k*32+(n-32)];
    else           wval = wv[k*64+(n-64)];
    sB[n*72+k] = __float2bfloat16(wval);
  }
  __syncthreads();
  for(int i=tid;i<8192;i+=256){
    int t=i>>6, ch=i&63;
    g_xt[((size_t)(gbase+t))*64+ch] = sX[t*66+ch];
  }
  {
    int row = tid>>1, hf = tid&1;
    float s=0.f, s2=0.f;
    #pragma unroll 8
    for(int j=hf*32;j<hf*32+32;j++){ float v=sX[row*66+j]; s+=v; s2+=v*v; }
    s  += __shfl_xor_sync(0xffffffffu, s, 1);
    s2 += __shfl_xor_sync(0xffffffffu, s2, 1);
    if(hf==0){
      float m=s*(1.0f/64.0f), var=s2*(1.0f/64.0f)-m*m;
      sM[row]=m; sR[row]=rsqrtf(var+1e-5f);
    }
  }
  __syncthreads();
  for(int i=tid;i<8192;i+=256){
    int t=i>>6, cc=i&63;
    float v = sX[t*66+cc];
    sA[t*72+cc] = __float2bfloat16((v-sM[t])*sR[t]*g1[cc]+b1[cc]);
  }
  __syncthreads();
  int w = tid>>5, lane = tid&31;
  int wr = w>>1, wc = w&1;
  float acc[2][8][4];
  #pragma unroll
  for(int mt=0;mt<2;mt++)
    #pragma unroll
    for(int nt=0;nt<8;nt++)
      #pragma unroll
      for(int q=0;q<4;q++) acc[mt][nt][q]=0.f;
  uint32_t sAb = sptr(sA), sBb = sptr(sB);
  #pragma unroll
  for(int ks=0;ks<4;ks++){
    uint32_t a[2][4];
    #pragma unroll
    for(int mt=0;mt<2;mt++){
      int row = wr*32 + mt*16 + (lane&7) + ((lane&8)?8:0);
      ldm_x4(a[mt][0],a[mt][1],a[mt][2],a[mt][3],
             sAb + row*144 + ks*32 + ((lane&16)?16:0));
    }
    #pragma unroll
    for(int nt=0;nt<8;nt++){
      int n0 = wc*64 + nt*8;
      uint32_t b0,b1;
      ldm_x2(b0,b1, sBb + (n0+(lane&7))*144 + ks*32 + ((lane&8)?16:0));
      #pragma unroll
      for(int mt=0;mt<2;mt++)
        mma_bf16(acc[mt][nt][0],acc[mt][nt][1],acc[mt][nt][2],acc[mt][nt][3],
                 a[mt][0],a[mt][1],a[mt][2],a[mt][3], b0,b1);
    }
  }
  #pragma unroll
  for(int mt=0;mt<2;mt++){
    #pragma unroll
    for(int nt=0;nt<8;nt++){
      int r = wr*32 + mt*16 + (lane>>2);
      int c = wc*64 + nt*8 + (lane&3)*2;
      #pragma unroll
      for(int hrow=0;hrow<2;hrow++){
        int rg = gbase + r + hrow*8;
        float v0 = acc[mt][nt][hrow*2], v1 = acc[mt][nt][hrow*2+1];
        if(c<32)       *(__nv_bfloat162*)&g_qh[(size_t)rg*32 + c]      = bf2(v0,v1);
        else if(c<64)  *(__nv_bfloat162*)&g_kh[(size_t)rg*32 + (c-32)] = bf2(v0,v1);
        else           *(__nv_bfloat162*)&g_vh[(size_t)rg*64 + (c-64)] = bf2(v0,v1);
      }
    }
  }
}

// ---------------- K2: attention, 128 q/block, bf16 S in-place ---------------
// smem: S/P bf16 [128][pitch 520e] | K [512][12]u32 | V [512][20]u32 | Q [128][12]u32 | inv[128]
#define SP_B 1040
#define SK_OFF 133120
#define SV_OFF 157696
#define SQ_OFF 198656
#define SINV_OFF 204800
#define AT_SMEM 205312
__global__ void __launch_bounds__(512,1) k_attn(){
  char* sm = (char*)dynsm;
  int p = blockIdx.x, hd = blockIdx.y;
  int q0 = blockIdx.z*128;
  int tid = threadIdx.x;
  float* sInv = (float*)(sm + SINV_OFF);
  int bi = p/NPB; int rp = p%NPB;
  int pt=rp/36, ph=(rp%36)/6, pw=rp%6;
  int gb = bi*THW;
  {
    const uint32_t* qg = (const uint32_t*)g_qh;
    uint32_t* dq = (uint32_t*)(sm + SQ_OFF);
    for(int i=tid;i<128*8;i+=512){
      int r=i>>3, dp=i&7;
      int pos = tok2pos(q0+r, pt, ph, pw);
      dq[r*12+dp] = qg[((size_t)(gb+pos))*16 + hd*8 + dp];
    }
    const uint32_t* kg = (const uint32_t*)g_kh;
    uint32_t* dk = (uint32_t*)(sm + SK_OFF);
    for(int i=tid;i<512*8;i+=512){
      int r=i>>3, dp=i&7;
      int pos = tok2pos(r, pt, ph, pw);
      dk[r*12+dp] = kg[((size_t)(gb+pos))*16 + hd*8 + dp];
    }
    const uint32_t* vg = (const uint32_t*)g_vh;
    uint32_t* dv = (uint32_t*)(sm + SV_OFF);
    for(int i=tid;i<512*16;i+=512){
      int r=i>>4, dp=i&15;
      int pos = tok2pos(r, pt, ph, pw);
      dv[r*20+dp] = vg[((size_t)(gb+pos))*32 + hd*16 + dp];
    }
  }
  __syncthreads();
  int w = tid>>5, lane = tid&31;

  // phase 1: S = Q @ K^T -> bf16 scores in place
  {
    int wq2 = w>>3, kh = w&7;     // wq2: 0..1 (64-query half), kh: 0..7 (64-key strip)
    uint32_t sQb = sptr(sm + SQ_OFF);
    uint32_t aQ[4][4];
    #pragma unroll
    for(int qt4=0;qt4<4;qt4++){
      int row = (wq2*4+qt4)*16 + (lane&7) + ((lane&8)?8:0);
      ldm_x4(aQ[qt4][0],aQ[qt4][1],aQ[qt4][2],aQ[qt4][3],
             sQb + row*48 + ((lane&16)?16:0));
    }
    uint32_t sKb = sptr(sm + SK_OFF);
    #pragma unroll
    for(int kt=0;kt<8;kt++){
      int j0 = kh*64 + kt*8;
      uint32_t b0,b1;
      ldm_x2(b0,b1, sKb + (j0 + (lane&7))*48 + ((lane&8)?16:0));
      #pragma unroll
      for(int qt4=0;qt4<4;qt4++){
        float c0=0.f,c1=0.f,c2=0.f,c3=0.f;
        mma_bf16(c0,c1,c2,c3, aQ[qt4][0],aQ[qt4][1],aQ[qt4][2],aQ[qt4][3], b0,b1);
        int r = (wq2*4+qt4)*16 + (lane>>2);
        int c = j0 + (lane&3)*2;
        *(__nv_bfloat162*)(sm + r*SP_B + c*2) = bf2(c0,c1);
        *(__nv_bfloat162*)(sm + (r+8)*SP_B + c*2) = bf2(c2,c3);
      }
    }
  }
  __syncthreads();

  // phase 2: per-row softmax in place (each lane owns its elements)
  #pragma unroll
  for(int rr=0;rr<8;rr++){
    int r = w*8 + rr;
    __nv_bfloat16* Srow = (__nv_bfloat16*)(sm + r*SP_B);
    float sv[16]; float m = -1e30f;
    #pragma unroll
    for(int jj=0;jj<16;jj++){ sv[jj] = __bfloat162float(Srow[lane + 32*jj]); m = fmaxf(m, sv[jj]); }
    m = wmaxr(m);
    float sum = 0.f;
    #pragma unroll
    for(int jj=0;jj<16;jj++){
      float e = __expf(0.25f*(sv[jj]-m));
      Srow[lane + 32*jj] = __float2bfloat16(e);
      sum += e;
    }
    sum = wred(sum);
    if(lane==0) sInv[r] = 1.0f/sum;
  }
  __syncthreads();

  // phase 3: O = P @ V (16 warps x 2 n-tiles cover 8 q-tiles x 4 n-tiles)
  {
    uint32_t sVb = sptr(sm + SV_OFF);
    int qt = w>>1, ntb = (w&1)*2;
    int arow = qt*16 + (lane&7) + ((lane&8)?8:0);
    uint32_t aBase = sptr(sm) + arow*SP_B + ((lane&16)?16:0);
    uint32_t bBase0 = sVb + ((lane&7) + ((lane&8)?8:0))*80;
    float c[2][4];
    #pragma unroll
    for(int n2=0;n2<2;n2++){ c[n2][0]=0.f;c[n2][1]=0.f;c[n2][2]=0.f;c[n2][3]=0.f; }
    #pragma unroll 4
    for(int ks=0;ks<32;ks++){
      uint32_t a0,a1,a2,a3; ldm_x4(a0,a1,a2,a3, aBase + ks*32);
      #pragma unroll
      for(int n2=0;n2<2;n2++){
        uint32_t b0,b1; ldm_x2t(b0,b1, bBase0 + (ntb+n2)*16 + ks*16*80);
        mma_bf16(c[n2][0],c[n2][1],c[n2][2],c[n2][3], a0,a1,a2,a3, b0,b1);
      }
    }
    int r = qt*16 + (lane>>2);
    float i0 = sInv[r], i1 = sInv[r+8];
    #pragma unroll
    for(int n2=0;n2<2;n2++){
      int cc = (ntb+n2)*8 + (lane&3)*2;
      __nv_bfloat16* og = g_attnh + (size_t)(p*512 + q0 + r)*64 + hd*32 + cc;
      *(__nv_bfloat162*)og = bf2(c[n2][0]*i0, c[n2][1]*i0);
      *(__nv_bfloat162*)(og + 8*64) = bf2(c[n2][2]*i1, c[n2][3]*i1);
    }
  }
}

// ---------------- K3: proj + residual via mma (M128 K64 N64) ----------------
__global__ void __launch_bounds__(256) k_proj(const float* __restrict__ wproj){
  __shared__ __nv_bfloat16 sA[128*72];
  __shared__ __nv_bfloat16 sB[64*72];
  int tid = threadIdx.x;
  int base = blockIdx.x*128;
  int p = base>>9, tok0 = base&511;
  int bi = p/NPB; int r0 = p%NPB;
  int pt=r0/36, ph=(r0%36)/6, pw=r0%6;
  const uint32_t* ag = (const uint32_t*)g_attnh;
  for(int i=tid;i<4096;i+=256){
    int t=i>>5, cp=i&31;
    ((uint32_t*)sA)[t*36+cp] = ag[((size_t)(base+t))*32 + cp];
  }
  for(int i=tid;i<4096;i+=256){
    int n=i>>6, k=i&63;
    sB[n*72+k] = __float2bfloat16(wproj[k*64+n]);
  }
  __syncthreads();
  int w = tid>>5, lane = tid&31;
  int wr = w>>1, wc = w&1;
  float acc[2][4][4];
  #pragma unroll
  for(int mt=0;mt<2;mt++)
    #pragma unroll
    for(int nt=0;nt<4;nt++)
      #pragma unroll
      for(int q=0;q<4;q++) acc[mt][nt][q]=0.f;
  uint32_t sAb = sptr(sA), sBb = sptr(sB);
  #pragma unroll
  for(int ks=0;ks<4;ks++){
    uint32_t a[2][4];
    #pragma unroll
    for(int mt=0;mt<2;mt++){
      int row = wr*32 + mt*16 + (lane&7) + ((lane&8)?8:0);
      ldm_x4(a[mt][0],a[mt][1],a[mt][2],a[mt][3],
             sAb + row*144 + ks*32 + ((lane&16)?16:0));
    }
    #pragma unroll
    for(int nt=0;nt<4;nt++){
      int n0 = wc*32 + nt*8;
      uint32_t b0,b1;
      ldm_x2(b0,b1, sBb + (n0+(lane&7))*144 + ks*32 + ((lane&8)?16:0));
      #pragma unroll
      for(int mt=0;mt<2;mt++)
        mma_bf16(acc[mt][nt][0],acc[mt][nt][1],acc[mt][nt][2],acc[mt][nt][3],
                 a[mt][0],a[mt][1],a[mt][2],a[mt][3], b0,b1);
    }
  }
  #pragma unroll
  for(int mt=0;mt<2;mt++){
    #pragma unroll
    for(int nt=0;nt<4;nt++){
      int r = wr*32 + mt*16 + (lane>>2);
      int c = wc*32 + nt*8 + (lane&3)*2;
      #pragma unroll
      for(int hrow=0;hrow<2;hrow++){
        int tok = r + hrow*8;
        int pos = tok2pos(tok0+tok, pt, ph, pw);
        float2 res = *(const float2*)&g_xt[((size_t)(bi*THW+pos))*64 + c];
        float v0 = acc[mt][nt][hrow*2]   + res.x;
        float v1 = acc[mt][nt][hrow*2+1] + res.y;
        *(float2*)&g_tok2[((size_t)(base+tok))*64 + c] = make_float2(v0,v1);
      }
    }
  }
}

// ---------------- K3b: patch-reverse gather (high-parallelism) --------------
__global__ void __launch_bounds__(256) k_gather(){
  int idx = blockIdx.x*256 + threadIdx.x;       // over NTOK2*64
  int token = idx>>6, ch = idx&63;
  int bi = token/THW; int pos = token%THW;
  int tt_ = pos/(HH*WW), hh_=(pos/WW)%HH, ww_=pos%WW;
  uint32_t et = c_cov_t[tt_], eh = c_cov_h[hh_], ew = c_cov_h[ww_];
  int na=1+(et&1), nb=1+(eh&1), nc=1+(ew&1);
  int tp0=(et>>1)&7, td0=(et>>4)&7, tp1=(et>>7)&7, td1=(et>>10)&7;
  int hp0=(eh>>1)&7, hd0=(eh>>4)&7, hp1=(eh>>7)&7, hd1=(eh>>10)&7;
  int wp0=(ew>>1)&7, wd0=(ew>>4)&7, wp1=(ew>>7)&7, wd1=(ew>>10)&7;
  float acc = 0.f;
  #pragma unroll
  for(int a=0;a<2;a++){
    if(a>=na) break;
    int pa = (a? tp1:tp0)*36, da = (a? td1:td0)*64;
    #pragma unroll
    for(int b=0;b<2;b++){
      if(b>=nb) break;
      int pb = pa + (b? hp1:hp0)*6, db = da + (b? hd1:hd0)*8;
      #pragma unroll
      for(int cI=0;cI<2;cI++){
        if(cI>=nc) break;
        int pp = bi*NPB + pb + (cI? wp1:wp0);
        int tk = db + (cI? wd1:wd0);
        acc += g_tok2[((size_t)(pp*512+tk))*64 + ch];
      }
    }
  }
  g_xtok[(size_t)token*64+ch] = acc * c_idt[tt_]*c_idh[hh_]*c_idh[ww_];
}

// ---------------- K4: LN2 + fc1(mma) + gelu + fused transpose ---------------
#define MLP1_SMEM (34816 + 18432 + 18432)
__global__ void __launch_bounds__(256) k_mlp1(const float* __restrict__ g2, const float* __restrict__ b2,
                       const float* __restrict__ fc1w, const float* __restrict__ fc1b){
  float* sX = dynsm;                         // 128*66
  float* sM = dynsm + 8448;
  float* sR = sM + 128;
  __nv_bfloat16* sYn = (__nv_bfloat16*)((char*)dynsm + 34816);  // 128*72
  __nv_bfloat16* sB  = (__nv_bfloat16*)((char*)dynsm + 34816 + 18432);
  float* cmb = dynsm;                        // reused after GEMM: 128*132 f32
  int base = blockIdx.x*128;
  int bi = base/THW; int pos0 = base%THW;
  int tid = threadIdx.x;
  for(int i=tid;i<8192;i+=256){
    int t=i>>6, ch=i&63;
    sX[t*66+ch] = g_xtok[((size_t)(base+t))*64 + ch];
  }
  for(int i=tid;i<8192;i+=256){
    int n=i>>6, k=i&63;
    sB[n*72+k] = __float2bfloat16(fc1w[k*128+n]);
  }
  __syncthreads();
  {
    int row = tid>>1, hf = tid&1;
    float s=0.f, s2=0.f;
    #pragma unroll 8
    for(int j=hf*32;j<hf*32+32;j++){ float v=sX[row*66+j]; s+=v; s2+=v*v; }
    s  += __shfl_xor_sync(0xffffffffu, s, 1);
    s2 += __shfl_xor_sync(0xffffffffu, s2, 1);
    if(hf==0){
      float m=s*(1.0f/64.0f), var=s2*(1.0f/64.0f)-m*m;
      sM[row]=m; sR[row]=rsqrtf(var+1e-5f);
    }
  }
  __syncthreads();
  for(int i=tid;i<8192;i+=256){
    int t=i>>6, cc=i&63;
    float v = sX[t*66+cc];
    sYn[t*72+cc] = __float2bfloat16((v-sM[t])*sR[t]*g2[cc]+b2[cc]);
  }
  __syncthreads();
  int w = tid>>5, lane = tid&31;
  int wr = w>>1, wc = w&1;
  float acc[2][8][4];
  #pragma unroll
  for(int mt=0;mt<2;mt++)
    #pragma unroll
    for(int nt=0;nt<8;nt++)
      #pragma unroll
      for(int q=0;q<4;q++) acc[mt][nt][q]=0.f;
  uint32_t sAb = sptr(sYn), sBb = sptr(sB);
  #pragma unroll
  for(int ks=0;ks<4;ks++){
    uint32_t a[2][4];
    #pragma unroll
    for(int mt=0;mt<2;mt++){
      int row = wr*32 + mt*16 + (lane&7) + ((lane&8)?8:0);
      ldm_x4(a[mt][0],a[mt][1],a[mt][2],a[mt][3],
             sAb + row*144 + ks*32 + ((lane&16)?16:0));
    }
    #pragma unroll
    for(int nt=0;nt<8;nt++){
      int n0 = wc*64 + nt*8;
      uint32_t b0,b1;
      ldm_x2(b0,b1, sBb + (n0+(lane&7))*144 + ks*32 + ((lane&8)?16:0));
      #pragma unroll
      for(int mt=0;mt<2;mt++)
        mma_bf16(acc[mt][nt][0],acc[mt][nt][1],acc[mt][nt][2],acc[mt][nt][3],
                 a[mt][0],a[mt][1],a[mt][2],a[mt][3], b0,b1);
    }
  }
  __syncthreads();   // all mma smem reads done; safe to reuse smem as cm buffer
  #pragma unroll
  for(int mt=0;mt<2;mt++){
    #pragma unroll
    for(int nt=0;nt<8;nt++){
      int r = wr*32 + mt*16 + (lane>>2);
      int c = wc*64 + nt*8 + (lane&3)*2;
      float bj0 = fc1b[c], bj1 = fc1b[c+1];
      #pragma unroll
      for(int hrow=0;hrow<2;hrow++){
        int tl = r + hrow*8;
        cmb[c*132 + tl]     = gelu_exact(acc[mt][nt][hrow*2]   + bj0);
        cmb[(c+1)*132 + tl] = gelu_exact(acc[mt][nt][hrow*2+1] + bj1);
      }
    }
  }
  __syncthreads();
  for(int i=tid;i<16384;i+=256){
    int c=i>>7, t=i&127;
    g_y2cm[((size_t)(bi*HID+c))*THW + pos0 + t] = cmb[c*132+t];
  }
}

// ---------------- K6: depthwise 5^3 conv + bias + gelu ----------------------
__global__ void __launch_bounds__(96) k_dwconv(const float* __restrict__ dww, const float* __restrict__ dwb){
  __shared__ float si[20*10*10];
  __shared__ float swt[125];
  int blk = blockIdx.x;
  int tile = blk%36; int cb = blk/36; int ch = cb%HID; int bi = cb/HID;
  int th = tile/6, tw = tile%6;
  int tid = threadIdx.x;
  const float* src = g_y2cm + ((size_t)(bi*HID+ch))*THW;

  for(int i=tid;i<125;i+=96) swt[i] = dww[ch*125+i];
  for(int i=tid;i<2000;i+=96){
    int it = i/100, rm = i%100, ih = rm/10, iw = rm%10;
    int gt = it-2, gh = th*6+ih-2, gw = tw*6+iw-2;
    float v = 0.f;
    if(gt>=0 && gt<TT && gh>=0 && gh<HH && gw>=0 && gw<WW)
      v = src[gt*(HH*WW) + gh*WW + gw];
    si[i] = v;
  }
  __syncthreads();
  int ot = tid/6, oh = tid%6;
  float acc[6] = {0.f,0.f,0.f,0.f,0.f,0.f};
  #pragma unroll
  for(int dt=0;dt<5;dt++){
    #pragma unroll
    for(int dh=0;dh<5;dh++){
      const float* row = si + (ot+dt)*100 + (oh+dh)*10;
      float rr[10];
      #pragma unroll
      for(int i=0;i<10;i++) rr[i]=row[i];
      const float* wp = swt + dt*25 + dh*5;
      float w0=wp[0],w1=wp[1],w2=wp[2],w3=wp[3],w4=wp[4];
      #pragma unroll
      for(int ow=0;ow<6;ow++)
        acc[ow] += rr[ow]*w0 + rr[ow+1]*w1 + rr[ow+2]*w2 + rr[ow+3]*w3 + rr[ow+4]*w4;
    }
  }
  float bsv = dwb[ch];
  float* dst = g_dwcm + ((size_t)(bi*HID+ch))*THW + ot*(HH*WW) + (th*6+oh)*WW + tw*6;
  #pragma unroll
  for(int ow=0;ow<6;ow++) dst[ow] = gelu_exact(acc[ow] + bsv);
}

// ---------------- K7: fc2(mma) + residual + transposed store ----------------
#define MLP2_SMEM (68608 + 16640)
__global__ void __launch_bounds__(256) k_mlp2(const float* __restrict__ fc2w, const float* __restrict__ fc2b,
                       float* __restrict__ out){
  float* sYf = dynsm;                                          // 64*132 f32
  __nv_bfloat16* sA = (__nv_bfloat16*)((char*)dynsm + 33792);  // 64*136
  __nv_bfloat16* sB = (__nv_bfloat16*)((char*)dynsm + 51200);  // 64*136
  float* sOut = (float*)((char*)dynsm + 68608);                // 64*65
  int base = blockIdx.x*64;
  int bi = base/THW; int pos0 = base%THW;
  int tid = threadIdx.x;
  for(int i=tid;i<8192;i+=256){
    int t=i&63, j=i>>6;
    sYf[t*132+j] = g_y2cm[((size_t)(bi*HID+j))*THW + pos0 + t]
                 + g_dwcm[((size_t)(bi*HID+j))*THW + pos0 + t];
  }
  for(int i=tid;i<8192;i+=256){
    int n=i>>7, k=i&127;
    sB[n*136+k] = __float2bfloat16(fc2w[k*64+n]);
  }
  __syncthreads();
  for(int i=tid;i<4096;i+=256){
    int t=i>>6, jp=i&63;
    float2 v = *(const float2*)&sYf[t*132 + jp*2];
    *(__nv_bfloat162*)&sA[t*136+jp*2] = bf2(v.x, v.y);
  }
  __syncthreads();
  int w = tid>>5, lane = tid&31;
  int wr = w>>1, wc = w&1;
  float acc[4][4];
  #pragma unroll
  for(int nt=0;nt<4;nt++)
    #pragma unroll
    for(int q=0;q<4;q++) acc[nt][q]=0.f;
  uint32_t sAb = sptr(sA), sBb = sptr(sB);
  #pragma unroll
  for(int ks=0;ks<8;ks++){
    uint32_t a0,a1,a2,a3;
    {
      int row = wr*16 + (lane&7) + ((lane&8)?8:0);
      ldm_x4(a0,a1,a2,a3, sAb + row*272 + ks*32 + ((lane&16)?16:0));
    }
    #pragma unroll
    for(int nt=0;nt<4;nt++){
      int n0 = wc*32 + nt*8;
      uint32_t b0,b1;
      ldm_x2(b0,b1, sBb + (n0+(lane&7))*272 + ks*32 + ((lane&8)?16:0));
      mma_bf16(acc[nt][0],acc[nt][1],acc[nt][2],acc[nt][3], a0,a1,a2,a3, b0,b1);
    }
  }
  #pragma unroll
  for(int nt=0;nt<4;nt++){
    int r = wr*16 + (lane>>2);
    int c = wc*32 + nt*8 + (lane&3)*2;
    float b0 = fc2b[c], b1 = fc2b[c+1];
    #pragma unroll
    for(int hrow=0;hrow<2;hrow++){
      int t = r + hrow*8;
      float2 res = *(const float2*)&g_xtok[((size_t)(base+t))*64 + c];
      sOut[t*65+c]   = acc[nt][hrow*2]   + b0 + res.x;
      sOut[t*65+c+1] = acc[nt][hrow*2+1] + b1 + res.y;
    }
  }
  __syncthreads();
  for(int i=tid;i<4096;i+=256){
    int t=i&63, c=i>>6;
    out[((size_t)(bi*CC+c))*THW + pos0 + t] = sOut[t*65+c];
  }
}

// ---------------- launch ----------------------------------------------------
extern "C" void kernel_launch(void* const* d_in, const int* in_sizes, int n_in,
                              void* d_out, int out_size){
  const float* x    = (const float*)d_in[0];
  const float* ln1g = (const float*)d_in[1];
  const float* ln1b = (const float*)d_in[2];
  const float* wq   = (const float*)d_in[3];
  const float* wk   = (const float*)d_in[4];
  const float* wv   = (const float*)d_in[5];
  const float* wpr  = (const float*)d_in[6];
  const float* ln2g = (const float*)d_in[7];
  const float* ln2b = (const float*)d_in[8];
  const float* fc1w = (const float*)d_in[9];
  const float* fc1b = (const float*)d_in[10];
  const float* dww  = (const float*)d_in[11];
  const float* dwb  = (const float*)d_in[12];
  const float* fc2w = (const float*)d_in[13];
  const float* fc2b = (const float*)d_in[14];
  float* out = (float*)d_out;

  cudaFuncSetAttribute(k_ln1qkv, cudaFuncAttributeMaxDynamicSharedMemorySize, LQKV_SMEM);
  cudaFuncSetAttribute(k_attn, cudaFuncAttributeMaxDynamicSharedMemorySize, AT_SMEM);
  cudaFuncSetAttribute(k_mlp1, cudaFuncAttributeMaxDynamicSharedMemorySize, MLP1_SMEM);
  cudaFuncSetAttribute(k_mlp2, cudaFuncAttributeMaxDynamicSharedMemorySize, MLP2_SMEM);

  k_ln1qkv<<<NTOK2/128, 256, LQKV_SMEM>>>(x, ln1g, ln1b, wq, wk, wv);
  k_attn<<<dim3(NP, HEADS, 4), 512, AT_SMEM>>>();
  k_proj<<<NROW/128, 256>>>(wpr);
  k_gather<<<NTOK2*64/256, 256>>>();
  k_mlp1<<<NTOK2/128, 256, MLP1_SMEM>>>(ln2g, ln2b, fc1w, fc1b);
  k_dwconv<<<BB*HID*36, 96>>>(dww, dwb);
  k_mlp2<<<NTOK2/64, 256, MLP2_SMEM>>>(fc2w, fc2b, out);
}